// round 1
// baseline (speedup 1.0000x reference)
#include <cuda_runtime.h>
#include <cuda_bf16.h>

// Problem: B=4, S=1024, HID=1024, H=16, DH=64
// inputs: 0 hidden [4096,1024] f32, 1 mask [4,1024] f32, 2 freqs [1024,64] f32,
//         3 Wq [1024,1024], 4 bq[1024], 5 Wk, 6 bk, 7 Wv, 8 bv
// output: ctx [4,1024,1024] f32

#define BATCH 4
#define SEQ   1024
#define HID   1024
#define NH    16
#define DH    64

// scratch: q,k,v in [B,H,S,DH] layout
__device__ float g_q[BATCH*NH*SEQ*DH];
__device__ float g_k[BATCH*NH*SEQ*DH];
__device__ float g_v[BATCH*NH*SEQ*DH];

// ---------------------------------------------------------------------------
// QKV projection: X[4096,1024] @ W[1024,1024] + b, output permuted to [B,H,S,DH]
// 128x128 tile, BK=8, 256 threads, 8x8 microtile.
// ---------------------------------------------------------------------------
__global__ __launch_bounds__(256) void qkv_gemm(
    const float* __restrict__ X,
    const float* __restrict__ Wq, const float* __restrict__ Wk, const float* __restrict__ Wv,
    const float* __restrict__ bq, const float* __restrict__ bk, const float* __restrict__ bv)
{
    const int which = blockIdx.z;
    const float* __restrict__ W    = (which == 0) ? Wq : (which == 1) ? Wk : Wv;
    const float* __restrict__ bias = (which == 0) ? bq : (which == 1) ? bk : bv;
    float* __restrict__ Out        = (which == 0) ? g_q : (which == 1) ? g_k : g_v;

    __shared__ float As[8][128];   // As[k][m]
    __shared__ float Bs[8][128];   // Bs[k][n]

    const int m0 = blockIdx.y * 128;
    const int n0 = blockIdx.x * 128;
    const int tid = threadIdx.x;
    const int ty = tid >> 4;        // 0..15
    const int tx = tid & 15;        // 0..15

    const int arow  = tid >> 1;          // 0..127
    const int acol4 = (tid & 1) * 4;     // 0 or 4
    const int brow  = tid >> 5;          // 0..7
    const int bcol4 = (tid & 31) * 4;    // 0..124

    float acc[8][8];
    #pragma unroll
    for (int i = 0; i < 8; i++)
        #pragma unroll
        for (int j = 0; j < 8; j++) acc[i][j] = 0.0f;

    for (int k0 = 0; k0 < HID; k0 += 8) {
        float4 av = *(const float4*)&X[(size_t)(m0 + arow) * HID + k0 + acol4];
        As[acol4 + 0][arow] = av.x;
        As[acol4 + 1][arow] = av.y;
        As[acol4 + 2][arow] = av.z;
        As[acol4 + 3][arow] = av.w;
        *(float4*)&Bs[brow][bcol4] =
            *(const float4*)&W[(size_t)(k0 + brow) * HID + n0 + bcol4];
        __syncthreads();

        #pragma unroll
        for (int kk = 0; kk < 8; kk++) {
            float a[8], b[8];
            *(float4*)&a[0] = *(const float4*)&As[kk][8 * ty];
            *(float4*)&a[4] = *(const float4*)&As[kk][8 * ty + 4];
            *(float4*)&b[0] = *(const float4*)&Bs[kk][8 * tx];
            *(float4*)&b[4] = *(const float4*)&Bs[kk][8 * tx + 4];
            #pragma unroll
            for (int i = 0; i < 8; i++)
                #pragma unroll
                for (int j = 0; j < 8; j++)
                    acc[i][j] = fmaf(a[i], b[j], acc[i][j]);
        }
        __syncthreads();
    }

    // epilogue: add bias, permute write to [B,H,S,DH]
    #pragma unroll
    for (int i = 0; i < 8; i++) {
        const int m = m0 + 8 * ty + i;
        const int b_ = m >> 10;          // /1024
        const int s  = m & 1023;
        #pragma unroll
        for (int j = 0; j < 8; j += 4) {
            const int n = n0 + 8 * tx + j;    // 4-aligned, stays in one head block
            const int h = n >> 6;
            const int d = n & 63;
            float4 r;
            r.x = acc[i][j + 0] + bias[n + 0];
            r.y = acc[i][j + 1] + bias[n + 1];
            r.z = acc[i][j + 2] + bias[n + 2];
            r.w = acc[i][j + 3] + bias[n + 3];
            *(float4*)&Out[(((size_t)(b_ * NH + h) * SEQ + s) << 6) + d] = r;
        }
    }
}

// ---------------------------------------------------------------------------
// RoPE (in place on g_q / g_k). freqs[s][d], d<32 == d>=32 half.
// One thread per rotation pair.
// ---------------------------------------------------------------------------
__global__ __launch_bounds__(256) void rope_kernel(const float* __restrict__ freqs)
{
    float* __restrict__ T = blockIdx.y ? g_k : g_q;
    const int p  = blockIdx.x * 256 + threadIdx.x;   // 0 .. B*H*S*32-1
    const int d  = p & 31;
    const int s  = (p >> 5) & 1023;
    const int bh = p >> 15;
    const float f = freqs[s * 64 + d];
    float c, sn;
    __sincosf(f, &sn, &c);
    // use accurate sincos: replace approx with precise
    sn = sinf(f); c = cosf(f);
    const size_t base = (((size_t)bh << 10) + s) * 64 + d;
    const float x1 = T[base];
    const float x2 = T[base + 32];
    T[base]      = x1 * c - x2 * sn;
    T[base + 32] = x2 * c + x1 * sn;
}

// ---------------------------------------------------------------------------
// Flash attention: one CTA per (q-tile 64, h, b). 256 threads, 4x4 microtiles.
// smem: Qt[d][r], KVt (K transposed / V row-major), Pt[c][r]  -> 48 KB exact.
// ---------------------------------------------------------------------------
__global__ __launch_bounds__(256) void attn_kernel(
    const float* __restrict__ mask, float* __restrict__ out)
{
    __shared__ float Qt[64][64];   // Qt[kdim][qrow]
    __shared__ float KVt[64][64];  // phase1: K^T [kdim][kcol]; phase2: V [kcol][d]
    __shared__ float Pt[64][64];   // probs transposed [kcol][qrow]

    const int q0 = blockIdx.x * 64;
    const int h  = blockIdx.y;
    const int b  = blockIdx.z;
    const int tid = threadIdx.x;
    const int ty = tid >> 4;   // 0..15 -> q rows 4*ty..
    const int tx = tid & 15;   // 0..15 -> cols 4*tx..

    const size_t base = ((size_t)(b * NH + h)) * SEQ * DH;

    // load Q tile transposed
    for (int f = tid; f < 1024; f += 256) {
        const int r  = f >> 4;
        const int d0 = (f & 15) << 2;
        float4 v = *(const float4*)&g_q[base + (size_t)(q0 + r) * 64 + d0];
        Qt[d0 + 0][r] = v.x; Qt[d0 + 1][r] = v.y;
        Qt[d0 + 2][r] = v.z; Qt[d0 + 3][r] = v.w;
    }

    float m_i[4], l_i[4], acc[4][4];
    #pragma unroll
    for (int i = 0; i < 4; i++) {
        m_i[i] = -1e30f; l_i[i] = 0.0f;
        #pragma unroll
        for (int j = 0; j < 4; j++) acc[i][j] = 0.0f;
    }

    const float* __restrict__ mrow = mask + b * SEQ;
    const float scale = 0.125f;  // 1/sqrt(64)

    for (int kt = 0; kt < 16; kt++) {
        const int kc0 = kt * 64;
        __syncthreads();  // prev PV done with KVt/Pt (and covers Q load, iter 0)

        // load K tile transposed
        for (int f = tid; f < 1024; f += 256) {
            const int r  = f >> 4;
            const int d0 = (f & 15) << 2;
            float4 v = *(const float4*)&g_k[base + (size_t)(kc0 + r) * 64 + d0];
            KVt[d0 + 0][r] = v.x; KVt[d0 + 1][r] = v.y;
            KVt[d0 + 2][r] = v.z; KVt[d0 + 3][r] = v.w;
        }
        __syncthreads();

        // S = Q K^T (register 4x4)
        float s[4][4];
        #pragma unroll
        for (int i = 0; i < 4; i++)
            #pragma unroll
            for (int j = 0; j < 4; j++) s[i][j] = 0.0f;

        #pragma unroll 8
        for (int kk = 0; kk < 64; kk++) {
            const float4 qv = *(const float4*)&Qt[kk][4 * ty];
            const float4 kv = *(const float4*)&KVt[kk][4 * tx];
            const float qa[4] = {qv.x, qv.y, qv.z, qv.w};
            const float kb[4] = {kv.x, kv.y, kv.z, kv.w};
            #pragma unroll
            for (int i = 0; i < 4; i++)
                #pragma unroll
                for (int j = 0; j < 4; j++)
                    s[i][j] = fmaf(qa[i], kb[j], s[i][j]);
        }

        float mk[4];
        #pragma unroll
        for (int j = 0; j < 4; j++) mk[j] = mrow[kc0 + 4 * tx + j];

        // online softmax per row (rows owned by 16 lanes sharing ty)
        #pragma unroll
        for (int i = 0; i < 4; i++) {
            float rowmax = -1e30f;
            #pragma unroll
            for (int j = 0; j < 4; j++) {
                s[i][j] = fmaf(s[i][j], scale, mk[j]);
                rowmax = fmaxf(rowmax, s[i][j]);
            }
            #pragma unroll
            for (int o = 1; o < 16; o <<= 1)
                rowmax = fmaxf(rowmax, __shfl_xor_sync(0xffffffffu, rowmax, o));
            const float mnew = fmaxf(m_i[i], rowmax);
            const float corr = __expf(m_i[i] - mnew);
            l_i[i] *= corr;
            #pragma unroll
            for (int j = 0; j < 4; j++) acc[i][j] *= corr;
            float psum = 0.0f;
            #pragma unroll
            for (int j = 0; j < 4; j++) {
                const float pj = __expf(s[i][j] - mnew);
                s[i][j] = pj;
                psum += pj;
            }
            #pragma unroll
            for (int o = 1; o < 16; o <<= 1)
                psum += __shfl_xor_sync(0xffffffffu, psum, o);
            l_i[i] += psum;
            m_i[i] = mnew;
        }

        // write P transposed
        #pragma unroll
        for (int j = 0; j < 4; j++)
            #pragma unroll
            for (int i = 0; i < 4; i++)
                Pt[4 * tx + j][4 * ty + i] = s[i][j];
        __syncthreads();  // K reads + P writes complete

        // load V tile (row-major)
        for (int f = tid; f < 1024; f += 256) {
            const int r  = f >> 4;
            const int d0 = (f & 15) << 2;
            *(float4*)&KVt[r][d0] =
                *(const float4*)&g_v[base + (size_t)(kc0 + r) * 64 + d0];
        }
        __syncthreads();

        // acc += P V
        #pragma unroll 8
        for (int kc = 0; kc < 64; kc++) {
            const float4 pv = *(const float4*)&Pt[kc][4 * ty];
            const float4 vv = *(const float4*)&KVt[kc][4 * tx];
            const float pa[4] = {pv.x, pv.y, pv.z, pv.w};
            const float vb[4] = {vv.x, vv.y, vv.z, vv.w};
            #pragma unroll
            for (int i = 0; i < 4; i++)
                #pragma unroll
                for (int j = 0; j < 4; j++)
                    acc[i][j] = fmaf(pa[i], vb[j], acc[i][j]);
        }
    }

    // epilogue: out[(b*S + s)*1024 + h*64 + d]
    #pragma unroll
    for (int i = 0; i < 4; i++) {
        const float inv = 1.0f / l_i[i];
        const int srow = q0 + 4 * ty + i;
        float4 o;
        o.x = acc[i][0] * inv;
        o.y = acc[i][1] * inv;
        o.z = acc[i][2] * inv;
        o.w = acc[i][3] * inv;
        *(float4*)&out[((size_t)(b * SEQ + srow) * (NH * DH)) + h * 64 + 4 * tx] = o;
    }
}

// ---------------------------------------------------------------------------
extern "C" void kernel_launch(void* const* d_in, const int* in_sizes, int n_in,
                              void* d_out, int out_size)
{
    const float* X     = (const float*)d_in[0];
    const float* mask  = (const float*)d_in[1];
    const float* freqs = (const float*)d_in[2];
    const float* Wq    = (const float*)d_in[3];
    const float* bq    = (const float*)d_in[4];
    const float* Wk    = (const float*)d_in[5];
    const float* bk    = (const float*)d_in[6];
    const float* Wv    = (const float*)d_in[7];
    const float* bv    = (const float*)d_in[8];
    float* out = (float*)d_out;

    dim3 gGemm(HID / 128, (BATCH * SEQ) / 128, 3);   // 8 x 32 x 3
    qkv_gemm<<<gGemm, 256>>>(X, Wq, Wk, Wv, bq, bk, bv);

    dim3 gRope((BATCH * NH * SEQ * 32) / 256, 2);    // 8192 x 2
    rope_kernel<<<gRope, 256>>>(freqs);

    dim3 gAttn(SEQ / 64, NH, BATCH);                 // 16 x 16 x 4
    attn_kernel<<<gAttn, 256>>>(mask, out);
}

// round 3
// speedup vs baseline: 1.5647x; 1.5647x over previous
#include <cuda_runtime.h>
#include <cuda_bf16.h>
#include <cstdint>

// Problem: B=4, S=1024, HID=1024, H=16, DH=64
// inputs: 0 hidden [4096,1024] f32, 1 mask [4,1024] f32, 2 freqs [1024,64] f32,
//         3 Wq, 4 bq, 5 Wk, 6 bk, 7 Wv, 8 bv
// output: ctx [4,1024,1024] f32

#define BATCH 4
#define SEQ   1024
#define HID   1024
#define NH    16
#define DH    64

// scratch: q,k,v in [B,H,S,DH] layout
__device__ float g_q[BATCH*NH*SEQ*DH];
__device__ float g_k[BATCH*NH*SEQ*DH];
__device__ float g_v[BATCH*NH*SEQ*DH];

__device__ __forceinline__ uint32_t f32_to_tf32(float x) {
    uint32_t u;
    asm("cvt.rna.tf32.f32 %0, %1;" : "=r"(u) : "f"(x));
    return u;
}

__device__ __forceinline__ void mma_tf32_16x8x8(
    float& c0, float& c1, float& c2, float& c3,
    uint32_t a0, uint32_t a1, uint32_t a2, uint32_t a3,
    uint32_t b0, uint32_t b1)
{
    asm volatile(
        "mma.sync.aligned.m16n8k8.row.col.f32.tf32.tf32.f32 "
        "{%0,%1,%2,%3}, {%4,%5,%6,%7}, {%8,%9}, {%0,%1,%2,%3};"
        : "+f"(c0), "+f"(c1), "+f"(c2), "+f"(c3)
        : "r"(a0), "r"(a1), "r"(a2), "r"(a3), "r"(b0), "r"(b1));
}

// ---------------------------------------------------------------------------
// QKV projection via tf32 mma.sync.
// BM=128, BN=64, BK=16, 256 threads (8 warps, 4x2 grid, 32x32 warp tile).
// A = X tile (row-major), B = W tile (W[k][n] native k-major = mma "col" operand).
// Double-buffered smem, conflict-free padded layouts (stride 20 / 136 words).
// ---------------------------------------------------------------------------
#define BKC 16
#define NCH (HID / BKC)   // 64

__global__ __launch_bounds__(256) void qkv_mma(
    const float* __restrict__ X,
    const float* __restrict__ Wq, const float* __restrict__ Wk, const float* __restrict__ Wv,
    const float* __restrict__ bq, const float* __restrict__ bk, const float* __restrict__ bv)
{
    __shared__ uint32_t As[2][128][20];
    __shared__ uint32_t Bs[2][16][136];

    const int which = blockIdx.z;
    const float* __restrict__ W    = (which == 0) ? Wq : (which == 1) ? Wk : Wv;
    const float* __restrict__ bias = (which == 0) ? bq : (which == 1) ? bk : bv;
    float* __restrict__ Out        = (which == 0) ? g_q : (which == 1) ? g_k : g_v;

    const int m0 = blockIdx.y * 128;
    const int n0 = blockIdx.x * 64;
    const int h  = blockIdx.x & (NH - 1);

    const int tid  = threadIdx.x;
    const int wid  = tid >> 5;
    const int lane = tid & 31;
    const int wm = (wid & 3) * 32;
    const int wn = (wid >> 2) * 32;
    const int lr = lane >> 2;
    const int lc = lane & 3;

    float acc[2][4][4];
    #pragma unroll
    for (int mt = 0; mt < 2; mt++)
        #pragma unroll
        for (int nt = 0; nt < 4; nt++)
            #pragma unroll
            for (int r = 0; r < 4; r++) acc[mt][nt][r] = 0.0f;

    auto load_chunk = [&](int buf, int k0) {
        #pragma unroll
        for (int i = 0; i < 2; i++) {
            const int g   = tid + i * 256;
            const int row = g >> 2;
            const int kc  = (g & 3) * 4;
            const float4 v = *(const float4*)&X[(size_t)(m0 + row) * HID + k0 + kc];
            uint4 t;
            t.x = f32_to_tf32(v.x); t.y = f32_to_tf32(v.y);
            t.z = f32_to_tf32(v.z); t.w = f32_to_tf32(v.w);
            *(uint4*)&As[buf][row][kc] = t;
        }
        {
            const int krow = tid >> 4;
            const int nc   = (tid & 15) * 4;
            const float4 v = *(const float4*)&W[(size_t)(k0 + krow) * HID + n0 + nc];
            uint4 t;
            t.x = f32_to_tf32(v.x); t.y = f32_to_tf32(v.y);
            t.z = f32_to_tf32(v.z); t.w = f32_to_tf32(v.w);
            *(uint4*)&Bs[buf][krow][nc] = t;
        }
    };

    load_chunk(0, 0);
    __syncthreads();

    for (int c = 0; c < NCH; c++) {
        const int cur = c & 1;

        if (c + 1 < NCH)
            load_chunk(cur ^ 1, (c + 1) * BKC);

        #pragma unroll
        for (int kk = 0; kk < 16; kk += 8) {
            uint32_t bf[4][2];
            #pragma unroll
            for (int nt = 0; nt < 4; nt++) {
                bf[nt][0] = Bs[cur][kk + lc    ][wn + nt * 8 + lr];
                bf[nt][1] = Bs[cur][kk + lc + 4][wn + nt * 8 + lr];
            }
            #pragma unroll
            for (int mt = 0; mt < 2; mt++) {
                uint32_t a0 = As[cur][wm + mt * 16 + lr    ][kk + lc    ];
                uint32_t a1 = As[cur][wm + mt * 16 + 8 + lr][kk + lc    ];
                uint32_t a2 = As[cur][wm + mt * 16 + lr    ][kk + lc + 4];
                uint32_t a3 = As[cur][wm + mt * 16 + 8 + lr][kk + lc + 4];
                #pragma unroll
                for (int nt = 0; nt < 4; nt++)
                    mma_tf32_16x8x8(acc[mt][nt][0], acc[mt][nt][1],
                                    acc[mt][nt][2], acc[mt][nt][3],
                                    a0, a1, a2, a3, bf[nt][0], bf[nt][1]);
            }
        }
        __syncthreads();
    }

    // epilogue: add bias, write permuted to [B,H,S,DH]
    #pragma unroll
    for (int mt = 0; mt < 2; mt++) {
        #pragma unroll
        for (int nt = 0; nt < 4; nt++) {
            const int d = wn + nt * 8 + 2 * lc;
            const float bx = bias[n0 + d];
            const float by = bias[n0 + d + 1];
            #pragma unroll
            for (int half = 0; half < 2; half++) {
                const int m  = m0 + wm + mt * 16 + half * 8 + lr;
                const int b_ = m >> 10;
                const int s  = m & 1023;
                float2 o;
                o.x = acc[mt][nt][2 * half + 0] + bx;
                o.y = acc[mt][nt][2 * half + 1] + by;
                *(float2*)&Out[(((size_t)(b_ * NH + h) * SEQ + s) << 6) + d] = o;
            }
        }
    }
}

// ---------------------------------------------------------------------------
// RoPE (in place on g_q / g_k).
// ---------------------------------------------------------------------------
__global__ __launch_bounds__(256) void rope_kernel(const float* __restrict__ freqs)
{
    float* __restrict__ T = blockIdx.y ? g_k : g_q;
    const int p  = blockIdx.x * 256 + threadIdx.x;
    const int d  = p & 31;
    const int s  = (p >> 5) & 1023;
    const int bh = p >> 15;
    const float f = freqs[s * 64 + d];
    const float sn = sinf(f), c = cosf(f);
    const size_t base = (((size_t)bh << 10) + s) * 64 + d;
    const float x1 = T[base];
    const float x2 = T[base + 32];
    T[base]      = x1 * c - x2 * sn;
    T[base + 32] = x2 * c + x1 * sn;
}

// ---------------------------------------------------------------------------
// Flash attention (fp32) with fully-masked K-tile early exit.
// ---------------------------------------------------------------------------
__global__ __launch_bounds__(256) void attn_kernel(
    const float* __restrict__ mask, float* __restrict__ out)
{
    __shared__ float Qt[64][64];
    __shared__ float KVt[64][64];
    __shared__ float Pt[64][64];

    const int q0 = blockIdx.x * 64;
    const int h  = blockIdx.y;
    const int b  = blockIdx.z;
    const int tid = threadIdx.x;
    const int ty = tid >> 4;
    const int tx = tid & 15;

    const size_t base = ((size_t)(b * NH + h)) * SEQ * DH;

    for (int f = tid; f < 1024; f += 256) {
        const int r  = f >> 4;
        const int d0 = (f & 15) << 2;
        float4 v = *(const float4*)&g_q[base + (size_t)(q0 + r) * 64 + d0];
        Qt[d0 + 0][r] = v.x; Qt[d0 + 1][r] = v.y;
        Qt[d0 + 2][r] = v.z; Qt[d0 + 3][r] = v.w;
    }

    float m_i[4], l_i[4], acc[4][4];
    #pragma unroll
    for (int i = 0; i < 4; i++) {
        m_i[i] = -1e30f; l_i[i] = 0.0f;
        #pragma unroll
        for (int j = 0; j < 4; j++) acc[i][j] = 0.0f;
    }

    const float* __restrict__ mrow = mask + b * SEQ;
    const float scale = 0.125f;

    for (int kt = 0; kt < 16; kt++) {
        const int kc0 = kt * 64;
        if (mrow[kc0] < -1e5f) break;   // mask monotone: rest fully masked
        __syncthreads();

        for (int f = tid; f < 1024; f += 256) {
            const int r  = f >> 4;
            const int d0 = (f & 15) << 2;
            float4 v = *(const float4*)&g_k[base + (size_t)(kc0 + r) * 64 + d0];
            KVt[d0 + 0][r] = v.x; KVt[d0 + 1][r] = v.y;
            KVt[d0 + 2][r] = v.z; KVt[d0 + 3][r] = v.w;
        }
        __syncthreads();

        float s[4][4];
        #pragma unroll
        for (int i = 0; i < 4; i++)
            #pragma unroll
            for (int j = 0; j < 4; j++) s[i][j] = 0.0f;

        #pragma unroll 8
        for (int kk = 0; kk < 64; kk++) {
            const float4 qv = *(const float4*)&Qt[kk][4 * ty];
            const float4 kv = *(const float4*)&KVt[kk][4 * tx];
            const float qa[4] = {qv.x, qv.y, qv.z, qv.w};
            const float kb[4] = {kv.x, kv.y, kv.z, kv.w};
            #pragma unroll
            for (int i = 0; i < 4; i++)
                #pragma unroll
                for (int j = 0; j < 4; j++)
                    s[i][j] = fmaf(qa[i], kb[j], s[i][j]);
        }

        float mk[4];
        #pragma unroll
        for (int j = 0; j < 4; j++) mk[j] = mrow[kc0 + 4 * tx + j];

        #pragma unroll
        for (int i = 0; i < 4; i++) {
            float rowmax = -1e30f;
            #pragma unroll
            for (int j = 0; j < 4; j++) {
                s[i][j] = fmaf(s[i][j], scale, mk[j]);
                rowmax = fmaxf(rowmax, s[i][j]);
            }
            #pragma unroll
            for (int o = 1; o < 16; o <<= 1)
                rowmax = fmaxf(rowmax, __shfl_xor_sync(0xffffffffu, rowmax, o));
            const float mnew = fmaxf(m_i[i], rowmax);
            const float corr = __expf(m_i[i] - mnew);
            l_i[i] *= corr;
            #pragma unroll
            for (int j = 0; j < 4; j++) acc[i][j] *= corr;
            float psum = 0.0f;
            #pragma unroll
            for (int j = 0; j < 4; j++) {
                const float pj = __expf(s[i][j] - mnew);
                s[i][j] = pj;
                psum += pj;
            }
            #pragma unroll
            for (int o = 1; o < 16; o <<= 1)
                psum += __shfl_xor_sync(0xffffffffu, psum, o);
            l_i[i] += psum;
            m_i[i] = mnew;
        }

        #pragma unroll
        for (int j = 0; j < 4; j++)
            #pragma unroll
            for (int i = 0; i < 4; i++)
                Pt[4 * tx + j][4 * ty + i] = s[i][j];
        __syncthreads();

        for (int f = tid; f < 1024; f += 256) {
            const int r  = f >> 4;
            const int d0 = (f & 15) << 2;
            *(float4*)&KVt[r][d0] =
                *(const float4*)&g_v[base + (size_t)(kc0 + r) * 64 + d0];
        }
        __syncthreads();

        #pragma unroll 8
        for (int kc = 0; kc < 64; kc++) {
            const float4 pv = *(const float4*)&Pt[kc][4 * ty];
            const float4 vv = *(const float4*)&KVt[kc][4 * tx];
            const float pa[4] = {pv.x, pv.y, pv.z, pv.w};
            const float vb[4] = {vv.x, vv.y, vv.z, vv.w};
            #pragma unroll
            for (int i = 0; i < 4; i++)
                #pragma unroll
                for (int j = 0; j < 4; j++)
                    acc[i][j] = fmaf(pa[i], vb[j], acc[i][j]);
        }
    }

    #pragma unroll
    for (int i = 0; i < 4; i++) {
        const float inv = 1.0f / l_i[i];
        const int srow = q0 + 4 * ty + i;
        float4 o;
        o.x = acc[i][0] * inv;
        o.y = acc[i][1] * inv;
        o.z = acc[i][2] * inv;
        o.w = acc[i][3] * inv;
        *(float4*)&out[((size_t)(b * SEQ + srow) * (NH * DH)) + h * 64 + 4 * tx] = o;
    }
}

// ---------------------------------------------------------------------------
extern "C" void kernel_launch(void* const* d_in, const int* in_sizes, int n_in,
                              void* d_out, int out_size)
{
    const float* X     = (const float*)d_in[0];
    const float* mask  = (const float*)d_in[1];
    const float* freqs = (const float*)d_in[2];
    const float* Wq    = (const float*)d_in[3];
    const float* bq    = (const float*)d_in[4];
    const float* Wk    = (const float*)d_in[5];
    const float* bk    = (const float*)d_in[6];
    const float* Wv    = (const float*)d_in[7];
    const float* bv    = (const float*)d_in[8];
    float* out = (float*)d_out;

    dim3 gG(HID / 64, (BATCH * SEQ) / 128, 3);   // 16 x 32 x 3
    qkv_mma<<<gG, 256>>>(X, Wq, Wk, Wv, bq, bk, bv);

    dim3 gR((BATCH * NH * SEQ * 32) / 256, 2);
    rope_kernel<<<gR, 256>>>(freqs);

    dim3 gA(SEQ / 64, NH, BATCH);
    attn_kernel<<<gA, 256>>>(mask, out);
}

// round 4
// speedup vs baseline: 2.5659x; 1.6399x over previous
#include <cuda_runtime.h>
#include <cuda_bf16.h>
#include <cstdint>

// Problem: B=4, S=1024, HID=1024, H=16, DH=64
// inputs: 0 hidden [4096,1024] f32, 1 mask [4,1024] f32, 2 freqs [1024,64] f32,
//         3 Wq, 4 bq, 5 Wk, 6 bk, 7 Wv, 8 bv
// output: ctx [4,1024,1024] f32

#define BATCH 4
#define SEQ   1024
#define HID   1024
#define NH    16
#define DH    64

// scratch: q,k,v in [B,H,S,DH] layout
__device__ float g_q[BATCH*NH*SEQ*DH];
__device__ float g_k[BATCH*NH*SEQ*DH];
__device__ float g_v[BATCH*NH*SEQ*DH];

__device__ __forceinline__ uint32_t f32_to_tf32(float x) {
    uint32_t u;
    asm("cvt.rna.tf32.f32 %0, %1;" : "=r"(u) : "f"(x));
    return u;
}

__device__ __forceinline__ void mma_tf32_16x8x8(
    float& c0, float& c1, float& c2, float& c3,
    uint32_t a0, uint32_t a1, uint32_t a2, uint32_t a3,
    uint32_t b0, uint32_t b1)
{
    asm volatile(
        "mma.sync.aligned.m16n8k8.row.col.f32.tf32.tf32.f32 "
        "{%0,%1,%2,%3}, {%4,%5,%6,%7}, {%8,%9}, {%0,%1,%2,%3};"
        : "+f"(c0), "+f"(c1), "+f"(c2), "+f"(c3)
        : "r"(a0), "r"(a1), "r"(a2), "r"(a3), "r"(b0), "r"(b1));
}

// ---------------------------------------------------------------------------
// QKV projection via tf32 mma.sync (unchanged from R3).
// ---------------------------------------------------------------------------
#define BKC 16
#define NCH (HID / BKC)   // 64

__global__ __launch_bounds__(256) void qkv_mma(
    const float* __restrict__ X,
    const float* __restrict__ Wq, const float* __restrict__ Wk, const float* __restrict__ Wv,
    const float* __restrict__ bq, const float* __restrict__ bk, const float* __restrict__ bv)
{
    __shared__ uint32_t As[2][128][20];
    __shared__ uint32_t Bs[2][16][136];

    const int which = blockIdx.z;
    const float* __restrict__ W    = (which == 0) ? Wq : (which == 1) ? Wk : Wv;
    const float* __restrict__ bias = (which == 0) ? bq : (which == 1) ? bk : bv;
    float* __restrict__ Out        = (which == 0) ? g_q : (which == 1) ? g_k : g_v;

    const int m0 = blockIdx.y * 128;
    const int n0 = blockIdx.x * 64;
    const int h  = blockIdx.x & (NH - 1);

    const int tid  = threadIdx.x;
    const int wid  = tid >> 5;
    const int lane = tid & 31;
    const int wm = (wid & 3) * 32;
    const int wn = (wid >> 2) * 32;
    const int lr = lane >> 2;
    const int lc = lane & 3;

    float acc[2][4][4];
    #pragma unroll
    for (int mt = 0; mt < 2; mt++)
        #pragma unroll
        for (int nt = 0; nt < 4; nt++)
            #pragma unroll
            for (int r = 0; r < 4; r++) acc[mt][nt][r] = 0.0f;

    auto load_chunk = [&](int buf, int k0) {
        #pragma unroll
        for (int i = 0; i < 2; i++) {
            const int g   = tid + i * 256;
            const int row = g >> 2;
            const int kc  = (g & 3) * 4;
            const float4 v = *(const float4*)&X[(size_t)(m0 + row) * HID + k0 + kc];
            uint4 t;
            t.x = f32_to_tf32(v.x); t.y = f32_to_tf32(v.y);
            t.z = f32_to_tf32(v.z); t.w = f32_to_tf32(v.w);
            *(uint4*)&As[buf][row][kc] = t;
        }
        {
            const int krow = tid >> 4;
            const int nc   = (tid & 15) * 4;
            const float4 v = *(const float4*)&W[(size_t)(k0 + krow) * HID + n0 + nc];
            uint4 t;
            t.x = f32_to_tf32(v.x); t.y = f32_to_tf32(v.y);
            t.z = f32_to_tf32(v.z); t.w = f32_to_tf32(v.w);
            *(uint4*)&Bs[buf][krow][nc] = t;
        }
    };

    load_chunk(0, 0);
    __syncthreads();

    for (int c = 0; c < NCH; c++) {
        const int cur = c & 1;

        if (c + 1 < NCH)
            load_chunk(cur ^ 1, (c + 1) * BKC);

        #pragma unroll
        for (int kk = 0; kk < 16; kk += 8) {
            uint32_t bf[4][2];
            #pragma unroll
            for (int nt = 0; nt < 4; nt++) {
                bf[nt][0] = Bs[cur][kk + lc    ][wn + nt * 8 + lr];
                bf[nt][1] = Bs[cur][kk + lc + 4][wn + nt * 8 + lr];
            }
            #pragma unroll
            for (int mt = 0; mt < 2; mt++) {
                uint32_t a0 = As[cur][wm + mt * 16 + lr    ][kk + lc    ];
                uint32_t a1 = As[cur][wm + mt * 16 + 8 + lr][kk + lc    ];
                uint32_t a2 = As[cur][wm + mt * 16 + lr    ][kk + lc + 4];
                uint32_t a3 = As[cur][wm + mt * 16 + 8 + lr][kk + lc + 4];
                #pragma unroll
                for (int nt = 0; nt < 4; nt++)
                    mma_tf32_16x8x8(acc[mt][nt][0], acc[mt][nt][1],
                                    acc[mt][nt][2], acc[mt][nt][3],
                                    a0, a1, a2, a3, bf[nt][0], bf[nt][1]);
            }
        }
        __syncthreads();
    }

    #pragma unroll
    for (int mt = 0; mt < 2; mt++) {
        #pragma unroll
        for (int nt = 0; nt < 4; nt++) {
            const int d = wn + nt * 8 + 2 * lc;
            const float bx = bias[n0 + d];
            const float by = bias[n0 + d + 1];
            #pragma unroll
            for (int half = 0; half < 2; half++) {
                const int m  = m0 + wm + mt * 16 + half * 8 + lr;
                const int b_ = m >> 10;
                const int s  = m & 1023;
                float2 o;
                o.x = acc[mt][nt][2 * half + 0] + bx;
                o.y = acc[mt][nt][2 * half + 1] + by;
                *(float2*)&Out[(((size_t)(b_ * NH + h) * SEQ + s) << 6) + d] = o;
            }
        }
    }
}

// ---------------------------------------------------------------------------
// RoPE (in place on g_q / g_k).
// ---------------------------------------------------------------------------
__global__ __launch_bounds__(256) void rope_kernel(const float* __restrict__ freqs)
{
    float* __restrict__ T = blockIdx.y ? g_k : g_q;
    const int p  = blockIdx.x * 256 + threadIdx.x;
    const int d  = p & 31;
    const int s  = (p >> 5) & 1023;
    const int bh = p >> 15;
    const float f = freqs[s * 64 + d];
    const float sn = sinf(f), c = cosf(f);
    const size_t base = (((size_t)bh << 10) + s) * 64 + d;
    const float x1 = T[base];
    const float x2 = T[base + 32];
    T[base]      = x1 * c - x2 * sn;
    T[base + 32] = x2 * c + x1 * sn;
}

// ---------------------------------------------------------------------------
// Flash attention on tensor cores (2-term compensated tf32).
// 4 warps, q-tile 64 (warp = m16 x n64). K/P smem stride 68, V stride 72
// (conflict-free fragment loads). P round-trips smem per-warp (syncwarp only).
// ---------------------------------------------------------------------------
#define KSTR 68
#define VSTR 72

__global__ __launch_bounds__(128) void attn_mma(
    const float* __restrict__ mask, float* __restrict__ out)
{
    __shared__ float Ks[64 * KSTR];
    __shared__ float Vs[64 * VSTR];
    __shared__ float Ps[64 * KSTR];
    __shared__ float Msk[SEQ];

    const int q0 = blockIdx.x * 64;
    const int h  = blockIdx.y;
    const int b  = blockIdx.z;
    const int tid  = threadIdx.x;
    const int w    = tid >> 5;
    const int lane = tid & 31;
    const int lr = lane >> 2;
    const int lc = lane & 3;
    const size_t base = ((size_t)(b * NH + h)) * SEQ * DH;

    for (int i = tid; i < SEQ; i += 128) Msk[i] = mask[b * SEQ + i];

    // stage Q tile into Ps (reused for P afterwards)
    #pragma unroll
    for (int j = 0; j < 8; j++) {
        const int i   = tid + j * 128;
        const int row = i >> 4;
        const int c4  = (i & 15) * 4;
        *(float4*)&Ps[row * KSTR + c4] =
            *(const float4*)&g_q[base + (size_t)(q0 + row) * 64 + c4];
    }
    __syncthreads();

    // persistent Q fragments (f32; split per use)
    float qf[8][4];
    #pragma unroll
    for (int ds = 0; ds < 8; ds++) {
        qf[ds][0] = Ps[(16 * w + lr    ) * KSTR + ds * 8 + lc    ];
        qf[ds][1] = Ps[(16 * w + lr + 8) * KSTR + ds * 8 + lc    ];
        qf[ds][2] = Ps[(16 * w + lr    ) * KSTR + ds * 8 + lc + 4];
        qf[ds][3] = Ps[(16 * w + lr + 8) * KSTR + ds * 8 + lc + 4];
    }
    __syncthreads();

    float m0 = -1e30f, m1 = -1e30f, l0 = 0.0f, l1 = 0.0f;
    float ctx[8][4];
    #pragma unroll
    for (int nt = 0; nt < 8; nt++)
        #pragma unroll
        for (int r = 0; r < 4; r++) ctx[nt][r] = 0.0f;

    for (int kt = 0; kt < 16; kt++) {
        const int kc0 = kt * 64;
        if (Msk[kc0] < -1e5f) break;     // monotone mask: rest fully masked
        __syncthreads();                 // prev PV done with Ks/Vs

        // stage K, V tiles
        #pragma unroll
        for (int j = 0; j < 8; j++) {
            const int i   = tid + j * 128;
            const int row = i >> 4;
            const int c4  = (i & 15) * 4;
            *(float4*)&Ks[row * KSTR + c4] =
                *(const float4*)&g_k[base + (size_t)(kc0 + row) * 64 + c4];
            *(float4*)&Vs[row * VSTR + c4] =
                *(const float4*)&g_v[base + (size_t)(kc0 + row) * 64 + c4];
        }
        __syncthreads();

        // ---- S = Q K^T (2-term tf32) ----
        float sa[8][4];
        #pragma unroll
        for (int nt = 0; nt < 8; nt++)
            #pragma unroll
            for (int r = 0; r < 4; r++) sa[nt][r] = 0.0f;

        #pragma unroll
        for (int ds = 0; ds < 8; ds++) {
            uint32_t ah[4], al[4];
            #pragma unroll
            for (int r = 0; r < 4; r++) {
                ah[r] = f32_to_tf32(qf[ds][r]);
                al[r] = f32_to_tf32(qf[ds][r] - __uint_as_float(ah[r]));
            }
            #pragma unroll
            for (int nt = 0; nt < 8; nt++) {
                const float b0 = Ks[(nt * 8 + lr) * KSTR + ds * 8 + lc    ];
                const float b1 = Ks[(nt * 8 + lr) * KSTR + ds * 8 + lc + 4];
                const uint32_t bh0 = f32_to_tf32(b0);
                const uint32_t bh1 = f32_to_tf32(b1);
                mma_tf32_16x8x8(sa[nt][0], sa[nt][1], sa[nt][2], sa[nt][3],
                                ah[0], ah[1], ah[2], ah[3], bh0, bh1);
                mma_tf32_16x8x8(sa[nt][0], sa[nt][1], sa[nt][2], sa[nt][3],
                                al[0], al[1], al[2], al[3], bh0, bh1);
            }
        }

        // ---- scale + mask + online softmax ----
        float mx0 = -1e30f, mx1 = -1e30f;
        #pragma unroll
        for (int nt = 0; nt < 8; nt++) {
            const float mk0 = Msk[kc0 + nt * 8 + 2 * lc    ];
            const float mk1 = Msk[kc0 + nt * 8 + 2 * lc + 1];
            sa[nt][0] = fmaf(sa[nt][0], 0.125f, mk0);
            sa[nt][1] = fmaf(sa[nt][1], 0.125f, mk1);
            sa[nt][2] = fmaf(sa[nt][2], 0.125f, mk0);
            sa[nt][3] = fmaf(sa[nt][3], 0.125f, mk1);
            mx0 = fmaxf(mx0, fmaxf(sa[nt][0], sa[nt][1]));
            mx1 = fmaxf(mx1, fmaxf(sa[nt][2], sa[nt][3]));
        }
        mx0 = fmaxf(mx0, __shfl_xor_sync(0xffffffffu, mx0, 1));
        mx0 = fmaxf(mx0, __shfl_xor_sync(0xffffffffu, mx0, 2));
        mx1 = fmaxf(mx1, __shfl_xor_sync(0xffffffffu, mx1, 1));
        mx1 = fmaxf(mx1, __shfl_xor_sync(0xffffffffu, mx1, 2));

        const float mn0 = fmaxf(m0, mx0);
        const float mn1 = fmaxf(m1, mx1);
        const float cr0 = __expf(m0 - mn0);
        const float cr1 = __expf(m1 - mn1);
        l0 *= cr0; l1 *= cr1;
        m0 = mn0; m1 = mn1;

        float ps0 = 0.0f, ps1 = 0.0f;
        #pragma unroll
        for (int nt = 0; nt < 8; nt++) {
            ctx[nt][0] *= cr0; ctx[nt][1] *= cr0;
            ctx[nt][2] *= cr1; ctx[nt][3] *= cr1;
            sa[nt][0] = __expf(sa[nt][0] - mn0);
            sa[nt][1] = __expf(sa[nt][1] - mn0);
            sa[nt][2] = __expf(sa[nt][2] - mn1);
            sa[nt][3] = __expf(sa[nt][3] - mn1);
            ps0 += sa[nt][0] + sa[nt][1];
            ps1 += sa[nt][2] + sa[nt][3];
        }
        ps0 += __shfl_xor_sync(0xffffffffu, ps0, 1);
        ps0 += __shfl_xor_sync(0xffffffffu, ps0, 2);
        ps1 += __shfl_xor_sync(0xffffffffu, ps1, 1);
        ps1 += __shfl_xor_sync(0xffffffffu, ps1, 2);
        l0 += ps0; l1 += ps1;

        // ---- store P (warp-private rows) ----
        #pragma unroll
        for (int nt = 0; nt < 8; nt++) {
            *(float2*)&Ps[(16 * w + lr    ) * KSTR + nt * 8 + 2 * lc] =
                make_float2(sa[nt][0], sa[nt][1]);
            *(float2*)&Ps[(16 * w + lr + 8) * KSTR + nt * 8 + 2 * lc] =
                make_float2(sa[nt][2], sa[nt][3]);
        }
        __syncwarp();

        // ---- ctx += P V (2-term tf32) ----
        #pragma unroll
        for (int kk = 0; kk < 8; kk++) {
            float af[4];
            af[0] = Ps[(16 * w + lr    ) * KSTR + kk * 8 + lc    ];
            af[1] = Ps[(16 * w + lr + 8) * KSTR + kk * 8 + lc    ];
            af[2] = Ps[(16 * w + lr    ) * KSTR + kk * 8 + lc + 4];
            af[3] = Ps[(16 * w + lr + 8) * KSTR + kk * 8 + lc + 4];
            uint32_t ah[4], al[4];
            #pragma unroll
            for (int r = 0; r < 4; r++) {
                ah[r] = f32_to_tf32(af[r]);
                al[r] = f32_to_tf32(af[r] - __uint_as_float(ah[r]));
            }
            #pragma unroll
            for (int nt = 0; nt < 8; nt++) {
                const float b0 = Vs[(kk * 8 + lc    ) * VSTR + nt * 8 + lr];
                const float b1 = Vs[(kk * 8 + lc + 4) * VSTR + nt * 8 + lr];
                const uint32_t bh0 = f32_to_tf32(b0);
                const uint32_t bh1 = f32_to_tf32(b1);
                mma_tf32_16x8x8(ctx[nt][0], ctx[nt][1], ctx[nt][2], ctx[nt][3],
                                ah[0], ah[1], ah[2], ah[3], bh0, bh1);
                mma_tf32_16x8x8(ctx[nt][0], ctx[nt][1], ctx[nt][2], ctx[nt][3],
                                al[0], al[1], al[2], al[3], bh0, bh1);
            }
        }
        __syncwarp();   // P reads done before next iter's P store
    }

    // ---- epilogue ----
    const float inv0 = 1.0f / l0;
    const float inv1 = 1.0f / l1;
    const int row0 = q0 + 16 * w + lr;
    const int row1 = row0 + 8;
    #pragma unroll
    for (int nt = 0; nt < 8; nt++) {
        const int d = nt * 8 + 2 * lc;
        *(float2*)&out[(size_t)(b * SEQ + row0) * (NH * DH) + h * 64 + d] =
            make_float2(ctx[nt][0] * inv0, ctx[nt][1] * inv0);
        *(float2*)&out[(size_t)(b * SEQ + row1) * (NH * DH) + h * 64 + d] =
            make_float2(ctx[nt][2] * inv1, ctx[nt][3] * inv1);
    }
}

// ---------------------------------------------------------------------------
extern "C" void kernel_launch(void* const* d_in, const int* in_sizes, int n_in,
                              void* d_out, int out_size)
{
    const float* X     = (const float*)d_in[0];
    const float* mask  = (const float*)d_in[1];
    const float* freqs = (const float*)d_in[2];
    const float* Wq    = (const float*)d_in[3];
    const float* bq    = (const float*)d_in[4];
    const float* Wk    = (const float*)d_in[5];
    const float* bk    = (const float*)d_in[6];
    const float* Wv    = (const float*)d_in[7];
    const float* bv    = (const float*)d_in[8];
    float* out = (float*)d_out;

    dim3 gG(HID / 64, (BATCH * SEQ) / 128, 3);   // 16 x 32 x 3
    qkv_mma<<<gG, 256>>>(X, Wq, Wk, Wv, bq, bk, bv);

    dim3 gR((BATCH * NH * SEQ * 32) / 256, 2);
    rope_kernel<<<gR, 256>>>(freqs);

    dim3 gA(SEQ / 64, NH, BATCH);                // 16 x 16 x 4
    attn_mma<<<gA, 128>>>(mask, out);
}

// round 5
// speedup vs baseline: 2.8055x; 1.0934x over previous
#include <cuda_runtime.h>
#include <cuda_bf16.h>
#include <cstdint>

// Problem: B=4, S=1024, HID=1024, H=16, DH=64
// inputs: 0 hidden [4096,1024] f32, 1 mask [4,1024] f32, 2 freqs [1024,64] f32,
//         3 Wq, 4 bq, 5 Wk, 6 bk, 7 Wv, 8 bv
// output: ctx [4,1024,1024] f32

#define BATCH 4
#define SEQ   1024
#define HID   1024
#define NH    16
#define DH    64

// scratch: q,k,v in [B,H,S,DH] layout
__device__ float g_q[BATCH*NH*SEQ*DH];
__device__ float g_k[BATCH*NH*SEQ*DH];
__device__ float g_v[BATCH*NH*SEQ*DH];

__device__ __forceinline__ uint32_t f32_to_tf32(float x) {
    uint32_t u;
    asm("cvt.rna.tf32.f32 %0, %1;" : "=r"(u) : "f"(x));
    return u;
}

__device__ __forceinline__ void mma_tf32_16x8x8(
    float& c0, float& c1, float& c2, float& c3,
    uint32_t a0, uint32_t a1, uint32_t a2, uint32_t a3,
    uint32_t b0, uint32_t b1)
{
    asm volatile(
        "mma.sync.aligned.m16n8k8.row.col.f32.tf32.tf32.f32 "
        "{%0,%1,%2,%3}, {%4,%5,%6,%7}, {%8,%9}, {%0,%1,%2,%3};"
        : "+f"(c0), "+f"(c1), "+f"(c2), "+f"(c3)
        : "r"(a0), "r"(a1), "r"(a2), "r"(a3), "r"(b0), "r"(b1));
}

// ---------------------------------------------------------------------------
// QKV projection via tf32 mma.sync.
// CTA tile 128x128, BK=16, 256 threads (8 warps, 2(m) x 4(n) warp grid,
// warp tile 64x32 => mt=4, nt=4). Double-buffered smem.
// Crossbar model: 24 wavefronts per 16 MMAs (32 tensor cyc) -> tensor-bound.
// ---------------------------------------------------------------------------
#define BKC 16
#define NCH (HID / BKC)   // 64

__global__ __launch_bounds__(256, 2) void qkv_mma(
    const float* __restrict__ X,
    const float* __restrict__ Wq, const float* __restrict__ Wk, const float* __restrict__ Wv,
    const float* __restrict__ bq, const float* __restrict__ bk, const float* __restrict__ bv)
{
    __shared__ uint32_t As[2][128][20];    // [m][k], stride 20 -> conflict-free frags
    __shared__ uint32_t Bs[2][16][136];    // [k][n], stride 136 -> conflict-free frags

    const int which = blockIdx.z;
    const float* __restrict__ W    = (which == 0) ? Wq : (which == 1) ? Wk : Wv;
    const float* __restrict__ bias = (which == 0) ? bq : (which == 1) ? bk : bv;
    float* __restrict__ Out        = (which == 0) ? g_q : (which == 1) ? g_k : g_v;

    const int m0 = blockIdx.y * 128;
    const int n0 = blockIdx.x * 128;       // covers 2 heads

    const int tid  = threadIdx.x;
    const int wid  = tid >> 5;
    const int lane = tid & 31;
    const int wm = (wid & 1) * 64;         // warp m offset
    const int wn = (wid >> 1) * 32;        // warp n offset
    const int lr = lane >> 2;              // 0..7
    const int lc = lane & 3;               // 0..3

    float acc[4][4][4];
    #pragma unroll
    for (int mt = 0; mt < 4; mt++)
        #pragma unroll
        for (int nt = 0; nt < 4; nt++)
            #pragma unroll
            for (int r = 0; r < 4; r++) acc[mt][nt][r] = 0.0f;

    // global -> smem (fp32 -> tf32 RN on the way in)
    auto load_chunk = [&](int buf, int k0) {
        #pragma unroll
        for (int i = 0; i < 2; i++) {       // A: 128x16 = 512 float4
            const int g   = tid + i * 256;
            const int row = g >> 2;
            const int kc  = (g & 3) * 4;
            const float4 v = *(const float4*)&X[(size_t)(m0 + row) * HID + k0 + kc];
            uint4 t;
            t.x = f32_to_tf32(v.x); t.y = f32_to_tf32(v.y);
            t.z = f32_to_tf32(v.z); t.w = f32_to_tf32(v.w);
            *(uint4*)&As[buf][row][kc] = t;
        }
        #pragma unroll
        for (int i = 0; i < 2; i++) {       // B: 16x128 = 512 float4
            const int g    = tid + i * 256;
            const int krow = g >> 5;
            const int nc   = (g & 31) * 4;
            const float4 v = *(const float4*)&W[(size_t)(k0 + krow) * HID + n0 + nc];
            uint4 t;
            t.x = f32_to_tf32(v.x); t.y = f32_to_tf32(v.y);
            t.z = f32_to_tf32(v.z); t.w = f32_to_tf32(v.w);
            *(uint4*)&Bs[buf][krow][nc] = t;
        }
    };

    load_chunk(0, 0);
    __syncthreads();

    for (int c = 0; c < NCH; c++) {
        const int cur = c & 1;

        if (c + 1 < NCH)
            load_chunk(cur ^ 1, (c + 1) * BKC);

        #pragma unroll
        for (int kk = 0; kk < 16; kk += 8) {
            uint32_t bf[4][2];
            #pragma unroll
            for (int nt = 0; nt < 4; nt++) {
                bf[nt][0] = Bs[cur][kk + lc    ][wn + nt * 8 + lr];
                bf[nt][1] = Bs[cur][kk + lc + 4][wn + nt * 8 + lr];
            }
            #pragma unroll
            for (int mt = 0; mt < 4; mt++) {
                uint32_t a0 = As[cur][wm + mt * 16 + lr    ][kk + lc    ];
                uint32_t a1 = As[cur][wm + mt * 16 + 8 + lr][kk + lc    ];
                uint32_t a2 = As[cur][wm + mt * 16 + lr    ][kk + lc + 4];
                uint32_t a3 = As[cur][wm + mt * 16 + 8 + lr][kk + lc + 4];
                #pragma unroll
                for (int nt = 0; nt < 4; nt++)
                    mma_tf32_16x8x8(acc[mt][nt][0], acc[mt][nt][1],
                                    acc[mt][nt][2], acc[mt][nt][3],
                                    a0, a1, a2, a3, bf[nt][0], bf[nt][1]);
            }
        }
        __syncthreads();
    }

    // epilogue: add bias, write permuted to [B,H,S,DH]
    #pragma unroll
    for (int mt = 0; mt < 4; mt++) {
        #pragma unroll
        for (int nt = 0; nt < 4; nt++) {
            const int dd = wn + nt * 8 + 2 * lc;     // 0..127 within CTA n-tile
            const int h  = (n0 + dd) >> 6;
            const int d  = dd & 63;
            const float bx = bias[n0 + dd];
            const float by = bias[n0 + dd + 1];
            #pragma unroll
            for (int half = 0; half < 2; half++) {
                const int m  = m0 + wm + mt * 16 + half * 8 + lr;
                const int b_ = m >> 10;
                const int s  = m & 1023;
                float2 o;
                o.x = acc[mt][nt][2 * half + 0] + bx;
                o.y = acc[mt][nt][2 * half + 1] + by;
                *(float2*)&Out[(((size_t)(b_ * NH + h) * SEQ + s) << 6) + d] = o;
            }
        }
    }
}

// ---------------------------------------------------------------------------
// RoPE (in place on g_q / g_k).
// ---------------------------------------------------------------------------
__global__ __launch_bounds__(256) void rope_kernel(const float* __restrict__ freqs)
{
    float* __restrict__ T = blockIdx.y ? g_k : g_q;
    const int p  = blockIdx.x * 256 + threadIdx.x;
    const int d  = p & 31;
    const int s  = (p >> 5) & 1023;
    const int bh = p >> 15;
    const float f = freqs[s * 64 + d];
    const float sn = sinf(f), c = cosf(f);
    const size_t base = (((size_t)bh << 10) + s) * 64 + d;
    const float x1 = T[base];
    const float x2 = T[base + 32];
    T[base]      = x1 * c - x2 * sn;
    T[base + 32] = x2 * c + x1 * sn;
}

// ---------------------------------------------------------------------------
// Flash attention on tensor cores (2-term compensated tf32). Unchanged (R4).
// ---------------------------------------------------------------------------
#define KSTR 68
#define VSTR 72

__global__ __launch_bounds__(128) void attn_mma(
    const float* __restrict__ mask, float* __restrict__ out)
{
    __shared__ float Ks[64 * KSTR];
    __shared__ float Vs[64 * VSTR];
    __shared__ float Ps[64 * KSTR];
    __shared__ float Msk[SEQ];

    const int q0 = blockIdx.x * 64;
    const int h  = blockIdx.y;
    const int b  = blockIdx.z;
    const int tid  = threadIdx.x;
    const int w    = tid >> 5;
    const int lane = tid & 31;
    const int lr = lane >> 2;
    const int lc = lane & 3;
    const size_t base = ((size_t)(b * NH + h)) * SEQ * DH;

    for (int i = tid; i < SEQ; i += 128) Msk[i] = mask[b * SEQ + i];

    #pragma unroll
    for (int j = 0; j < 8; j++) {
        const int i   = tid + j * 128;
        const int row = i >> 4;
        const int c4  = (i & 15) * 4;
        *(float4*)&Ps[row * KSTR + c4] =
            *(const float4*)&g_q[base + (size_t)(q0 + row) * 64 + c4];
    }
    __syncthreads();

    float qf[8][4];
    #pragma unroll
    for (int ds = 0; ds < 8; ds++) {
        qf[ds][0] = Ps[(16 * w + lr    ) * KSTR + ds * 8 + lc    ];
        qf[ds][1] = Ps[(16 * w + lr + 8) * KSTR + ds * 8 + lc    ];
        qf[ds][2] = Ps[(16 * w + lr    ) * KSTR + ds * 8 + lc + 4];
        qf[ds][3] = Ps[(16 * w + lr + 8) * KSTR + ds * 8 + lc + 4];
    }
    __syncthreads();

    float m0 = -1e30f, m1 = -1e30f, l0 = 0.0f, l1 = 0.0f;
    float ctx[8][4];
    #pragma unroll
    for (int nt = 0; nt < 8; nt++)
        #pragma unroll
        for (int r = 0; r < 4; r++) ctx[nt][r] = 0.0f;

    for (int kt = 0; kt < 16; kt++) {
        const int kc0 = kt * 64;
        if (Msk[kc0] < -1e5f) break;
        __syncthreads();

        #pragma unroll
        for (int j = 0; j < 8; j++) {
            const int i   = tid + j * 128;
            const int row = i >> 4;
            const int c4  = (i & 15) * 4;
            *(float4*)&Ks[row * KSTR + c4] =
                *(const float4*)&g_k[base + (size_t)(kc0 + row) * 64 + c4];
            *(float4*)&Vs[row * VSTR + c4] =
                *(const float4*)&g_v[base + (size_t)(kc0 + row) * 64 + c4];
        }
        __syncthreads();

        float sa[8][4];
        #pragma unroll
        for (int nt = 0; nt < 8; nt++)
            #pragma unroll
            for (int r = 0; r < 4; r++) sa[nt][r] = 0.0f;

        #pragma unroll
        for (int ds = 0; ds < 8; ds++) {
            uint32_t ah[4], al[4];
            #pragma unroll
            for (int r = 0; r < 4; r++) {
                ah[r] = f32_to_tf32(qf[ds][r]);
                al[r] = f32_to_tf32(qf[ds][r] - __uint_as_float(ah[r]));
            }
            #pragma unroll
            for (int nt = 0; nt < 8; nt++) {
                const float b0 = Ks[(nt * 8 + lr) * KSTR + ds * 8 + lc    ];
                const float b1 = Ks[(nt * 8 + lr) * KSTR + ds * 8 + lc + 4];
                const uint32_t bh0 = f32_to_tf32(b0);
                const uint32_t bh1 = f32_to_tf32(b1);
                mma_tf32_16x8x8(sa[nt][0], sa[nt][1], sa[nt][2], sa[nt][3],
                                ah[0], ah[1], ah[2], ah[3], bh0, bh1);
                mma_tf32_16x8x8(sa[nt][0], sa[nt][1], sa[nt][2], sa[nt][3],
                                al[0], al[1], al[2], al[3], bh0, bh1);
            }
        }

        float mx0 = -1e30f, mx1 = -1e30f;
        #pragma unroll
        for (int nt = 0; nt < 8; nt++) {
            const float mk0 = Msk[kc0 + nt * 8 + 2 * lc    ];
            const float mk1 = Msk[kc0 + nt * 8 + 2 * lc + 1];
            sa[nt][0] = fmaf(sa[nt][0], 0.125f, mk0);
            sa[nt][1] = fmaf(sa[nt][1], 0.125f, mk1);
            sa[nt][2] = fmaf(sa[nt][2], 0.125f, mk0);
            sa[nt][3] = fmaf(sa[nt][3], 0.125f, mk1);
            mx0 = fmaxf(mx0, fmaxf(sa[nt][0], sa[nt][1]));
            mx1 = fmaxf(mx1, fmaxf(sa[nt][2], sa[nt][3]));
        }
        mx0 = fmaxf(mx0, __shfl_xor_sync(0xffffffffu, mx0, 1));
        mx0 = fmaxf(mx0, __shfl_xor_sync(0xffffffffu, mx0, 2));
        mx1 = fmaxf(mx1, __shfl_xor_sync(0xffffffffu, mx1, 1));
        mx1 = fmaxf(mx1, __shfl_xor_sync(0xffffffffu, mx1, 2));

        const float mn0 = fmaxf(m0, mx0);
        const float mn1 = fmaxf(m1, mx1);
        const float cr0 = __expf(m0 - mn0);
        const float cr1 = __expf(m1 - mn1);
        l0 *= cr0; l1 *= cr1;
        m0 = mn0; m1 = mn1;

        float ps0 = 0.0f, ps1 = 0.0f;
        #pragma unroll
        for (int nt = 0; nt < 8; nt++) {
            ctx[nt][0] *= cr0; ctx[nt][1] *= cr0;
            ctx[nt][2] *= cr1; ctx[nt][3] *= cr1;
            sa[nt][0] = __expf(sa[nt][0] - mn0);
            sa[nt][1] = __expf(sa[nt][1] - mn0);
            sa[nt][2] = __expf(sa[nt][2] - mn1);
            sa[nt][3] = __expf(sa[nt][3] - mn1);
            ps0 += sa[nt][0] + sa[nt][1];
            ps1 += sa[nt][2] + sa[nt][3];
        }
        ps0 += __shfl_xor_sync(0xffffffffu, ps0, 1);
        ps0 += __shfl_xor_sync(0xffffffffu, ps0, 2);
        ps1 += __shfl_xor_sync(0xffffffffu, ps1, 1);
        ps1 += __shfl_xor_sync(0xffffffffu, ps1, 2);
        l0 += ps0; l1 += ps1;

        #pragma unroll
        for (int nt = 0; nt < 8; nt++) {
            *(float2*)&Ps[(16 * w + lr    ) * KSTR + nt * 8 + 2 * lc] =
                make_float2(sa[nt][0], sa[nt][1]);
            *(float2*)&Ps[(16 * w + lr + 8) * KSTR + nt * 8 + 2 * lc] =
                make_float2(sa[nt][2], sa[nt][3]);
        }
        __syncwarp();

        #pragma unroll
        for (int kk = 0; kk < 8; kk++) {
            float af[4];
            af[0] = Ps[(16 * w + lr    ) * KSTR + kk * 8 + lc    ];
            af[1] = Ps[(16 * w + lr + 8) * KSTR + kk * 8 + lc    ];
            af[2] = Ps[(16 * w + lr    ) * KSTR + kk * 8 + lc + 4];
            af[3] = Ps[(16 * w + lr + 8) * KSTR + kk * 8 + lc + 4];
            uint32_t ah[4], al[4];
            #pragma unroll
            for (int r = 0; r < 4; r++) {
                ah[r] = f32_to_tf32(af[r]);
                al[r] = f32_to_tf32(af[r] - __uint_as_float(ah[r]));
            }
            #pragma unroll
            for (int nt = 0; nt < 8; nt++) {
                const float b0 = Vs[(kk * 8 + lc    ) * VSTR + nt * 8 + lr];
                const float b1 = Vs[(kk * 8 + lc + 4) * VSTR + nt * 8 + lr];
                const uint32_t bh0 = f32_to_tf32(b0);
                const uint32_t bh1 = f32_to_tf32(b1);
                mma_tf32_16x8x8(ctx[nt][0], ctx[nt][1], ctx[nt][2], ctx[nt][3],
                                ah[0], ah[1], ah[2], ah[3], bh0, bh1);
                mma_tf32_16x8x8(ctx[nt][0], ctx[nt][1], ctx[nt][2], ctx[nt][3],
                                al[0], al[1], al[2], al[3], bh0, bh1);
            }
        }
        __syncwarp();
    }

    const float inv0 = 1.0f / l0;
    const float inv1 = 1.0f / l1;
    const int row0 = q0 + 16 * w + lr;
    const int row1 = row0 + 8;
    #pragma unroll
    for (int nt = 0; nt < 8; nt++) {
        const int d = nt * 8 + 2 * lc;
        *(float2*)&out[(size_t)(b * SEQ + row0) * (NH * DH) + h * 64 + d] =
            make_float2(ctx[nt][0] * inv0, ctx[nt][1] * inv0);
        *(float2*)&out[(size_t)(b * SEQ + row1) * (NH * DH) + h * 64 + d] =
            make_float2(ctx[nt][2] * inv1, ctx[nt][3] * inv1);
    }
}

// ---------------------------------------------------------------------------
extern "C" void kernel_launch(void* const* d_in, const int* in_sizes, int n_in,
                              void* d_out, int out_size)
{
    const float* X     = (const float*)d_in[0];
    const float* mask  = (const float*)d_in[1];
    const float* freqs = (const float*)d_in[2];
    const float* Wq    = (const float*)d_in[3];
    const float* bq    = (const float*)d_in[4];
    const float* Wk    = (const float*)d_in[5];
    const float* bk    = (const float*)d_in[6];
    const float* Wv    = (const float*)d_in[7];
    const float* bv    = (const float*)d_in[8];
    float* out = (float*)d_out;

    dim3 gG(HID / 128, (BATCH * SEQ) / 128, 3);   // 8 x 32 x 3
    qkv_mma<<<gG, 256>>>(X, Wq, Wk, Wv, bq, bk, bv);

    dim3 gR((BATCH * NH * SEQ * 32) / 256, 2);
    rope_kernel<<<gR, 256>>>(freqs);

    dim3 gA(SEQ / 64, NH, BATCH);                 // 16 x 16 x 4
    attn_mma<<<gA, 128>>>(mask, out);
}

// round 7
// speedup vs baseline: 3.1410x; 1.1196x over previous
#include <cuda_runtime.h>
#include <cuda_bf16.h>
#include <cstdint>

// Problem: B=4, S=1024, HID=1024, H=16, DH=64
// inputs: 0 hidden [4096,1024] f32, 1 mask [4,1024] f32, 2 freqs [1024,64] f32,
//         3 Wq, 4 bq, 5 Wk, 6 bk, 7 Wv, 8 bv
// output: ctx [4,1024,1024] f32

#define BATCH 4
#define SEQ   1024
#define HID   1024
#define NH    16
#define DH    64

// scratch
__device__ float    g_q[BATCH*NH*SEQ*DH];
__device__ float    g_k[BATCH*NH*SEQ*DH];
__device__ float    g_v[BATCH*NH*SEQ*DH];
__device__ uint32_t g_xt[BATCH*SEQ*HID];     // X as tf32 bits
__device__ uint32_t g_wc[3*HID*HID];         // Wq|Wk|Wv as tf32 bits

__device__ __forceinline__ uint32_t f32_to_tf32(float x) {
    uint32_t u;
    asm("cvt.rna.tf32.f32 %0, %1;" : "=r"(u) : "f"(x));
    return u;
}

__device__ __forceinline__ void mma_tf32_16x8x8(
    float& c0, float& c1, float& c2, float& c3,
    uint32_t a0, uint32_t a1, uint32_t a2, uint32_t a3,
    uint32_t b0, uint32_t b1)
{
    asm volatile(
        "mma.sync.aligned.m16n8k8.row.col.f32.tf32.tf32.f32 "
        "{%0,%1,%2,%3}, {%4,%5,%6,%7}, {%8,%9}, {%0,%1,%2,%3};"
        : "+f"(c0), "+f"(c1), "+f"(c2), "+f"(c3)
        : "r"(a0), "r"(a1), "r"(a2), "r"(a3), "r"(b0), "r"(b1));
}

__device__ __forceinline__ uint32_t smem_u32(const void* p) {
    uint32_t a;
    asm("{ .reg .u64 t; cvta.to.shared.u64 t, %1; cvt.u32.u64 %0, t; }" : "=r"(a) : "l"(p));
    return a;
}

#define CP_ASYNC16(dst, src) \
    asm volatile("cp.async.cg.shared.global [%0], [%1], 16;" :: "r"(dst), "l"(src) : "memory")
#define CP_COMMIT() asm volatile("cp.async.commit_group;" ::: "memory")
#define CP_WAIT1()  asm volatile("cp.async.wait_group 1;" ::: "memory")

// ---------------------------------------------------------------------------
// Pre-convert X and W to tf32 bit patterns (one pass, vectorized).
// ---------------------------------------------------------------------------
__global__ __launch_bounds__(256) void precvt(
    const float* __restrict__ X,
    const float* __restrict__ Wq, const float* __restrict__ Wk, const float* __restrict__ Wv)
{
    size_t g = (size_t)blockIdx.x * 256 + threadIdx.x;   // float4 index
    const size_t NX = (size_t)BATCH * SEQ * HID / 4;     // 1M
    const size_t NW = (size_t)HID * HID / 4;             // 256K
    const float* src;
    uint32_t* dst;
    if (g < NX)               { src = X;  dst = g_xt; }
    else if (g < NX + NW)     { src = Wq; dst = g_wc;               g -= NX; }
    else if (g < NX + 2 * NW) { src = Wk; dst = g_wc + HID * HID;   g -= NX + NW; }
    else                      { src = Wv; dst = g_wc + 2*HID*HID;   g -= NX + 2*NW; }
    const float4 v = ((const float4*)src)[g];
    uint4 t;
    t.x = f32_to_tf32(v.x); t.y = f32_to_tf32(v.y);
    t.z = f32_to_tf32(v.z); t.w = f32_to_tf32(v.w);
    ((uint4*)dst)[g] = t;
}

// ---------------------------------------------------------------------------
// QKV projection via tf32 mma.sync + cp.async 3-stage pipeline.
// CTA tile 128x128, BK=16, 256 threads (8 warps, 2(m) x 4(n), warp 64x32).
// ---------------------------------------------------------------------------
#define BKC 16
#define NCH (HID / BKC)   // 64
#define NSTAGE 3
#define ASTR 20           // words; conflict-free frags, 16B-aligned rows
#define BSTR 136          // words; conflict-free frags, 16B-aligned rows
#define A_WORDS (128 * ASTR)
#define B_WORDS (16 * BSTR)
#define STG_WORDS (A_WORDS + B_WORDS)
#define QKV_SMEM (NSTAGE * STG_WORDS * 4)   // 56832 bytes

__global__ __launch_bounds__(256, 2) void qkv_mma(
    const float* __restrict__ bq, const float* __restrict__ bk, const float* __restrict__ bv)
{
    extern __shared__ uint32_t smw[];
    const uint32_t sb = smem_u32(smw);

    const int which = blockIdx.z;
    const uint32_t* __restrict__ W = g_wc + (size_t)which * HID * HID;
    const float* __restrict__ bias = (which == 0) ? bq : (which == 1) ? bk : bv;
    float* __restrict__ Out        = (which == 0) ? g_q : (which == 1) ? g_k : g_v;

    const int m0 = blockIdx.y * 128;
    const int n0 = blockIdx.x * 128;

    const int tid  = threadIdx.x;
    const int wid  = tid >> 5;
    const int lane = tid & 31;
    const int wm = (wid & 1) * 64;
    const int wn = (wid >> 1) * 32;
    const int lr = lane >> 2;
    const int lc = lane & 3;

    // per-thread cp.async coordinates (constant across stages)
    const int arow  = tid >> 2;              // 0..63 (+64 for second half)
    const int akc   = (tid & 3) * 4;
    const int bkrow = tid >> 5;              // 0..7 (+8 for second half)
    const int bnc   = (tid & 31) * 4;

    auto issue_stage = [&](int stg, int k0) {
        const uint32_t ab = sb + (uint32_t)(stg * STG_WORDS) * 4;
        const uint32_t bb = ab + A_WORDS * 4;
        #pragma unroll
        for (int i = 0; i < 2; i++) {
            const int row = arow + i * 64;
            CP_ASYNC16(ab + (uint32_t)(row * ASTR + akc) * 4,
                       &g_xt[(size_t)(m0 + row) * HID + k0 + akc]);
        }
        #pragma unroll
        for (int i = 0; i < 2; i++) {
            const int kr = bkrow + i * 8;
            CP_ASYNC16(bb + (uint32_t)(kr * BSTR + bnc) * 4,
                       &W[(size_t)(k0 + kr) * HID + n0 + bnc]);
        }
    };

    float acc[4][4][4];
    #pragma unroll
    for (int mt = 0; mt < 4; mt++)
        #pragma unroll
        for (int nt = 0; nt < 4; nt++)
            #pragma unroll
            for (int r = 0; r < 4; r++) acc[mt][nt][r] = 0.0f;

    issue_stage(0, 0);        CP_COMMIT();
    issue_stage(1, BKC);      CP_COMMIT();

    int stg = 0;
    for (int c = 0; c < NCH; c++) {
        CP_WAIT1();
        __syncthreads();   // stage `stg` data visible to all; prior compute on
                           // the stage we are about to overwrite is done

        if (c + 2 < NCH)
            issue_stage((stg + 2) % NSTAGE, (c + 2) * BKC);
        CP_COMMIT();       // unconditional: keeps group accounting uniform

        const uint32_t* As = smw + stg * STG_WORDS;
        const uint32_t* Bs = As + A_WORDS;

        #pragma unroll
        for (int kk = 0; kk < 16; kk += 8) {
            uint32_t bf[4][2];
            #pragma unroll
            for (int nt = 0; nt < 4; nt++) {
                bf[nt][0] = Bs[(kk + lc    ) * BSTR + wn + nt * 8 + lr];
                bf[nt][1] = Bs[(kk + lc + 4) * BSTR + wn + nt * 8 + lr];
            }
            #pragma unroll
            for (int mt = 0; mt < 4; mt++) {
                uint32_t a0 = As[(wm + mt * 16 + lr    ) * ASTR + kk + lc    ];
                uint32_t a1 = As[(wm + mt * 16 + 8 + lr) * ASTR + kk + lc    ];
                uint32_t a2 = As[(wm + mt * 16 + lr    ) * ASTR + kk + lc + 4];
                uint32_t a3 = As[(wm + mt * 16 + 8 + lr) * ASTR + kk + lc + 4];
                #pragma unroll
                for (int nt = 0; nt < 4; nt++)
                    mma_tf32_16x8x8(acc[mt][nt][0], acc[mt][nt][1],
                                    acc[mt][nt][2], acc[mt][nt][3],
                                    a0, a1, a2, a3, bf[nt][0], bf[nt][1]);
            }
        }
        stg = (stg + 1) % NSTAGE;
    }

    // epilogue: add bias, write permuted to [B,H,S,DH]
    #pragma unroll
    for (int mt = 0; mt < 4; mt++) {
        #pragma unroll
        for (int nt = 0; nt < 4; nt++) {
            const int dd = wn + nt * 8 + 2 * lc;
            const int h  = (n0 + dd) >> 6;
            const int d  = dd & 63;
            const float bx = bias[n0 + dd];
            const float by = bias[n0 + dd + 1];
            #pragma unroll
            for (int half = 0; half < 2; half++) {
                const int m  = m0 + wm + mt * 16 + half * 8 + lr;
                const int b_ = m >> 10;
                const int s  = m & 1023;
                float2 o;
                o.x = acc[mt][nt][2 * half + 0] + bx;
                o.y = acc[mt][nt][2 * half + 1] + by;
                *(float2*)&Out[(((size_t)(b_ * NH + h) * SEQ + s) << 6) + d] = o;
            }
        }
    }
}

// ---------------------------------------------------------------------------
// RoPE (in place on g_q / g_k).
// ---------------------------------------------------------------------------
__global__ __launch_bounds__(256) void rope_kernel(const float* __restrict__ freqs)
{
    float* __restrict__ T = blockIdx.y ? g_k : g_q;
    const int p  = blockIdx.x * 256 + threadIdx.x;
    const int d  = p & 31;
    const int s  = (p >> 5) & 1023;
    const int bh = p >> 15;
    const float f = freqs[s * 64 + d];
    const float sn = sinf(f), c = cosf(f);
    const size_t base = (((size_t)bh << 10) + s) * 64 + d;
    const float x1 = T[base];
    const float x2 = T[base + 32];
    T[base]      = x1 * c - x2 * sn;
    T[base + 32] = x2 * c + x1 * sn;
}

// ---------------------------------------------------------------------------
// Flash attention on tensor cores.
// QK^T: 2-term compensated tf32 (scores feed exp — keep precision).
// PV:   1-term tf32 (P in [0,1]; truncation error ~1e-4, random-sign).
// ---------------------------------------------------------------------------
#define KSTR 68
#define VSTR 72

__global__ __launch_bounds__(128) void attn_mma(
    const float* __restrict__ mask, float* __restrict__ out)
{
    __shared__ float Ks[64 * KSTR];
    __shared__ float Vs[64 * VSTR];
    __shared__ float Ps[64 * KSTR];
    __shared__ float Msk[SEQ];

    const int q0 = blockIdx.x * 64;
    const int h  = blockIdx.y;
    const int b  = blockIdx.z;
    const int tid  = threadIdx.x;
    const int w    = tid >> 5;
    const int lane = tid & 31;
    const int lr = lane >> 2;
    const int lc = lane & 3;
    const size_t base = ((size_t)(b * NH + h)) * SEQ * DH;

    for (int i = tid; i < SEQ; i += 128) Msk[i] = mask[b * SEQ + i];

    #pragma unroll
    for (int j = 0; j < 8; j++) {
        const int i   = tid + j * 128;
        const int row = i >> 4;
        const int c4  = (i & 15) * 4;
        *(float4*)&Ps[row * KSTR + c4] =
            *(const float4*)&g_q[base + (size_t)(q0 + row) * 64 + c4];
    }
    __syncthreads();

    // persistent pre-split Q fragments
    uint32_t qh[8][4], ql[8][4];
    #pragma unroll
    for (int ds = 0; ds < 8; ds++) {
        float v[4];
        v[0] = Ps[(16 * w + lr    ) * KSTR + ds * 8 + lc    ];
        v[1] = Ps[(16 * w + lr + 8) * KSTR + ds * 8 + lc    ];
        v[2] = Ps[(16 * w + lr    ) * KSTR + ds * 8 + lc + 4];
        v[3] = Ps[(16 * w + lr + 8) * KSTR + ds * 8 + lc + 4];
        #pragma unroll
        for (int r = 0; r < 4; r++) {
            qh[ds][r] = f32_to_tf32(v[r]);
            ql[ds][r] = f32_to_tf32(v[r] - __uint_as_float(qh[ds][r]));
        }
    }
    __syncthreads();

    float m0 = -1e30f, m1 = -1e30f, l0 = 0.0f, l1 = 0.0f;
    float ctx[8][4];
    #pragma unroll
    for (int nt = 0; nt < 8; nt++)
        #pragma unroll
        for (int r = 0; r < 4; r++) ctx[nt][r] = 0.0f;

    for (int kt = 0; kt < 16; kt++) {
        const int kc0 = kt * 64;
        if (Msk[kc0] < -1e5f) break;
        __syncthreads();

        #pragma unroll
        for (int j = 0; j < 8; j++) {
            const int i   = tid + j * 128;
            const int row = i >> 4;
            const int c4  = (i & 15) * 4;
            *(float4*)&Ks[row * KSTR + c4] =
                *(const float4*)&g_k[base + (size_t)(kc0 + row) * 64 + c4];
            *(float4*)&Vs[row * VSTR + c4] =
                *(const float4*)&g_v[base + (size_t)(kc0 + row) * 64 + c4];
        }
        __syncthreads();

        float sa[8][4];
        #pragma unroll
        for (int nt = 0; nt < 8; nt++)
            #pragma unroll
            for (int r = 0; r < 4; r++) sa[nt][r] = 0.0f;

        #pragma unroll
        for (int ds = 0; ds < 8; ds++) {
            #pragma unroll
            for (int nt = 0; nt < 8; nt++) {
                const float b0 = Ks[(nt * 8 + lr) * KSTR + ds * 8 + lc    ];
                const float b1 = Ks[(nt * 8 + lr) * KSTR + ds * 8 + lc + 4];
                const uint32_t bh0 = f32_to_tf32(b0);
                const uint32_t bh1 = f32_to_tf32(b1);
                mma_tf32_16x8x8(sa[nt][0], sa[nt][1], sa[nt][2], sa[nt][3],
                                qh[ds][0], qh[ds][1], qh[ds][2], qh[ds][3], bh0, bh1);
                mma_tf32_16x8x8(sa[nt][0], sa[nt][1], sa[nt][2], sa[nt][3],
                                ql[ds][0], ql[ds][1], ql[ds][2], ql[ds][3], bh0, bh1);
            }
        }

        float mx0 = -1e30f, mx1 = -1e30f;
        #pragma unroll
        for (int nt = 0; nt < 8; nt++) {
            const float mk0 = Msk[kc0 + nt * 8 + 2 * lc    ];
            const float mk1 = Msk[kc0 + nt * 8 + 2 * lc + 1];
            sa[nt][0] = fmaf(sa[nt][0], 0.125f, mk0);
            sa[nt][1] = fmaf(sa[nt][1], 0.125f, mk1);
            sa[nt][2] = fmaf(sa[nt][2], 0.125f, mk0);
            sa[nt][3] = fmaf(sa[nt][3], 0.125f, mk1);
            mx0 = fmaxf(mx0, fmaxf(sa[nt][0], sa[nt][1]));
            mx1 = fmaxf(mx1, fmaxf(sa[nt][2], sa[nt][3]));
        }
        mx0 = fmaxf(mx0, __shfl_xor_sync(0xffffffffu, mx0, 1));
        mx0 = fmaxf(mx0, __shfl_xor_sync(0xffffffffu, mx0, 2));
        mx1 = fmaxf(mx1, __shfl_xor_sync(0xffffffffu, mx1, 1));
        mx1 = fmaxf(mx1, __shfl_xor_sync(0xffffffffu, mx1, 2));

        const float mn0 = fmaxf(m0, mx0);
        const float mn1 = fmaxf(m1, mx1);
        const float cr0 = __expf(m0 - mn0);
        const float cr1 = __expf(m1 - mn1);
        l0 *= cr0; l1 *= cr1;
        m0 = mn0; m1 = mn1;

        float ps0 = 0.0f, ps1 = 0.0f;
        #pragma unroll
        for (int nt = 0; nt < 8; nt++) {
            ctx[nt][0] *= cr0; ctx[nt][1] *= cr0;
            ctx[nt][2] *= cr1; ctx[nt][3] *= cr1;
            sa[nt][0] = __expf(sa[nt][0] - mn0);
            sa[nt][1] = __expf(sa[nt][1] - mn0);
            sa[nt][2] = __expf(sa[nt][2] - mn1);
            sa[nt][3] = __expf(sa[nt][3] - mn1);
            ps0 += sa[nt][0] + sa[nt][1];
            ps1 += sa[nt][2] + sa[nt][3];
        }
        ps0 += __shfl_xor_sync(0xffffffffu, ps0, 1);
        ps0 += __shfl_xor_sync(0xffffffffu, ps0, 2);
        ps1 += __shfl_xor_sync(0xffffffffu, ps1, 1);
        ps1 += __shfl_xor_sync(0xffffffffu, ps1, 2);
        l0 += ps0; l1 += ps1;

        // store P (warp-private rows)
        #pragma unroll
        for (int nt = 0; nt < 8; nt++) {
            *(float2*)&Ps[(16 * w + lr    ) * KSTR + nt * 8 + 2 * lc] =
                make_float2(sa[nt][0], sa[nt][1]);
            *(float2*)&Ps[(16 * w + lr + 8) * KSTR + nt * 8 + 2 * lc] =
                make_float2(sa[nt][2], sa[nt][3]);
        }
        __syncwarp();

        // ctx += P V (1-term tf32)
        #pragma unroll
        for (int kk = 0; kk < 8; kk++) {
            uint32_t ah[4];
            ah[0] = f32_to_tf32(Ps[(16 * w + lr    ) * KSTR + kk * 8 + lc    ]);
            ah[1] = f32_to_tf32(Ps[(16 * w + lr + 8) * KSTR + kk * 8 + lc    ]);
            ah[2] = f32_to_tf32(Ps[(16 * w + lr    ) * KSTR + kk * 8 + lc + 4]);
            ah[3] = f32_to_tf32(Ps[(16 * w + lr + 8) * KSTR + kk * 8 + lc + 4]);
            #pragma unroll
            for (int nt = 0; nt < 8; nt++) {
                const uint32_t bh0 = f32_to_tf32(Vs[(kk * 8 + lc    ) * VSTR + nt * 8 + lr]);
                const uint32_t bh1 = f32_to_tf32(Vs[(kk * 8 + lc + 4) * VSTR + nt * 8 + lr]);
                mma_tf32_16x8x8(ctx[nt][0], ctx[nt][1], ctx[nt][2], ctx[nt][3],
                                ah[0], ah[1], ah[2], ah[3], bh0, bh1);
            }
        }
        __syncwarp();
    }

    const float inv0 = 1.0f / l0;
    const float inv1 = 1.0f / l1;
    const int row0 = q0 + 16 * w + lr;
    const int row1 = row0 + 8;
    #pragma unroll
    for (int nt = 0; nt < 8; nt++) {
        const int d = nt * 8 + 2 * lc;
        *(float2*)&out[(size_t)(b * SEQ + row0) * (NH * DH) + h * 64 + d] =
            make_float2(ctx[nt][0] * inv0, ctx[nt][1] * inv0);
        *(float2*)&out[(size_t)(b * SEQ + row1) * (NH * DH) + h * 64 + d] =
            make_float2(ctx[nt][2] * inv1, ctx[nt][3] * inv1);
    }
}

// ---------------------------------------------------------------------------
extern "C" void kernel_launch(void* const* d_in, const int* in_sizes, int n_in,
                              void* d_out, int out_size)
{
    const float* X     = (const float*)d_in[0];
    const float* mask  = (const float*)d_in[1];
    const float* freqs = (const float*)d_in[2];
    const float* Wq    = (const float*)d_in[3];
    const float* bq    = (const float*)d_in[4];
    const float* Wk    = (const float*)d_in[5];
    const float* bk    = (const float*)d_in[6];
    const float* Wv    = (const float*)d_in[7];
    const float* bv    = (const float*)d_in[8];
    float* out = (float*)d_out;

    cudaFuncSetAttribute(qkv_mma, cudaFuncAttributeMaxDynamicSharedMemorySize, QKV_SMEM);

    const int NX = BATCH * SEQ * HID / 4;
    const int NW = HID * HID / 4;
    precvt<<<(NX + 3 * NW) / 256, 256>>>(X, Wq, Wk, Wv);

    dim3 gG(HID / 128, (BATCH * SEQ) / 128, 3);   // 8 x 32 x 3
    qkv_mma<<<gG, 256, QKV_SMEM>>>(bq, bk, bv);

    dim3 gR((BATCH * NH * SEQ * 32) / 256, 2);
    rope_kernel<<<gR, 256>>>(freqs);

    dim3 gA(SEQ / 64, NH, BATCH);                 // 16 x 16 x 4
    attn_mma<<<gA, 128>>>(mask, out);
}

// round 8
// speedup vs baseline: 3.3961x; 1.0812x over previous
#include <cuda_runtime.h>
#include <cuda_bf16.h>
#include <cstdint>

// Problem: B=4, S=1024, HID=1024, H=16, DH=64
// inputs: 0 hidden [4096,1024] f32, 1 mask [4,1024] f32, 2 freqs [1024,64] f32,
//         3 Wq, 4 bq, 5 Wk, 6 bk, 7 Wv, 8 bv
// output: ctx [4,1024,1024] f32

#define BATCH 4
#define SEQ   1024
#define HID   1024
#define NH    16
#define DH    64

// scratch. g_q stays f32 (needs hi/lo split in attn).
// g_k: f32 after qkv, OVERWRITTEN with tf32 bits by rope.
// g_v: written as tf32 bits directly by qkv epilogue.
__device__ float    g_q[BATCH*NH*SEQ*DH];
__device__ uint32_t g_k[BATCH*NH*SEQ*DH];
__device__ uint32_t g_v[BATCH*NH*SEQ*DH];
__device__ uint32_t g_xt[BATCH*SEQ*HID];     // X as tf32 bits
__device__ uint32_t g_wc[3*HID*HID];         // Wq|Wk|Wv as tf32 bits

__device__ __forceinline__ uint32_t f32_to_tf32(float x) {
    uint32_t u;
    asm("cvt.rna.tf32.f32 %0, %1;" : "=r"(u) : "f"(x));
    return u;
}

__device__ __forceinline__ void mma_tf32_16x8x8(
    float& c0, float& c1, float& c2, float& c3,
    uint32_t a0, uint32_t a1, uint32_t a2, uint32_t a3,
    uint32_t b0, uint32_t b1)
{
    asm volatile(
        "mma.sync.aligned.m16n8k8.row.col.f32.tf32.tf32.f32 "
        "{%0,%1,%2,%3}, {%4,%5,%6,%7}, {%8,%9}, {%0,%1,%2,%3};"
        : "+f"(c0), "+f"(c1), "+f"(c2), "+f"(c3)
        : "r"(a0), "r"(a1), "r"(a2), "r"(a3), "r"(b0), "r"(b1));
}

__device__ __forceinline__ uint32_t smem_u32(const void* p) {
    uint32_t a;
    asm("{ .reg .u64 t; cvta.to.shared.u64 t, %1; cvt.u32.u64 %0, t; }" : "=r"(a) : "l"(p));
    return a;
}

#define CP_ASYNC16(dst, src) \
    asm volatile("cp.async.cg.shared.global [%0], [%1], 16;" :: "r"(dst), "l"(src) : "memory")
#define CP_COMMIT() asm volatile("cp.async.commit_group;" ::: "memory")
#define CP_WAIT1()  asm volatile("cp.async.wait_group 1;" ::: "memory")

// ---------------------------------------------------------------------------
// Pre-convert X and W to tf32 bit patterns.
// ---------------------------------------------------------------------------
__global__ __launch_bounds__(256) void precvt(
    const float* __restrict__ X,
    const float* __restrict__ Wq, const float* __restrict__ Wk, const float* __restrict__ Wv)
{
    size_t g = (size_t)blockIdx.x * 256 + threadIdx.x;
    const size_t NX = (size_t)BATCH * SEQ * HID / 4;
    const size_t NW = (size_t)HID * HID / 4;
    const float* src;
    uint32_t* dst;
    if (g < NX)               { src = X;  dst = g_xt; }
    else if (g < NX + NW)     { src = Wq; dst = g_wc;               g -= NX; }
    else if (g < NX + 2 * NW) { src = Wk; dst = g_wc + HID * HID;   g -= NX + NW; }
    else                      { src = Wv; dst = g_wc + 2*HID*HID;   g -= NX + 2*NW; }
    const float4 v = ((const float4*)src)[g];
    uint4 t;
    t.x = f32_to_tf32(v.x); t.y = f32_to_tf32(v.y);
    t.z = f32_to_tf32(v.z); t.w = f32_to_tf32(v.w);
    ((uint4*)dst)[g] = t;
}

// ---------------------------------------------------------------------------
// QKV projection via tf32 mma.sync + cp.async 3-stage pipeline.
// V output written as tf32 bits (attention consumes V 1-term).
// ---------------------------------------------------------------------------
#define BKC 16
#define NCH (HID / BKC)
#define NSTAGE 3
#define ASTR 20
#define BSTR 136
#define A_WORDS (128 * ASTR)
#define B_WORDS (16 * BSTR)
#define STG_WORDS (A_WORDS + B_WORDS)
#define QKV_SMEM (NSTAGE * STG_WORDS * 4)

__global__ __launch_bounds__(256, 2) void qkv_mma(
    const float* __restrict__ bq, const float* __restrict__ bk, const float* __restrict__ bv)
{
    extern __shared__ uint32_t smw[];
    const uint32_t sb = smem_u32(smw);

    const int which = blockIdx.z;
    const uint32_t* __restrict__ W = g_wc + (size_t)which * HID * HID;
    const float* __restrict__ bias = (which == 0) ? bq : (which == 1) ? bk : bv;

    const int m0 = blockIdx.y * 128;
    const int n0 = blockIdx.x * 128;

    const int tid  = threadIdx.x;
    const int wid  = tid >> 5;
    const int lane = tid & 31;
    const int wm = (wid & 1) * 64;
    const int wn = (wid >> 1) * 32;
    const int lr = lane >> 2;
    const int lc = lane & 3;

    const int arow  = tid >> 2;
    const int akc   = (tid & 3) * 4;
    const int bkrow = tid >> 5;
    const int bnc   = (tid & 31) * 4;

    auto issue_stage = [&](int stg, int k0) {
        const uint32_t ab = sb + (uint32_t)(stg * STG_WORDS) * 4;
        const uint32_t bb = ab + A_WORDS * 4;
        #pragma unroll
        for (int i = 0; i < 2; i++) {
            const int row = arow + i * 64;
            CP_ASYNC16(ab + (uint32_t)(row * ASTR + akc) * 4,
                       &g_xt[(size_t)(m0 + row) * HID + k0 + akc]);
        }
        #pragma unroll
        for (int i = 0; i < 2; i++) {
            const int kr = bkrow + i * 8;
            CP_ASYNC16(bb + (uint32_t)(kr * BSTR + bnc) * 4,
                       &W[(size_t)(k0 + kr) * HID + n0 + bnc]);
        }
    };

    float acc[4][4][4];
    #pragma unroll
    for (int mt = 0; mt < 4; mt++)
        #pragma unroll
        for (int nt = 0; nt < 4; nt++)
            #pragma unroll
            for (int r = 0; r < 4; r++) acc[mt][nt][r] = 0.0f;

    issue_stage(0, 0);        CP_COMMIT();
    issue_stage(1, BKC);      CP_COMMIT();

    int stg = 0;
    for (int c = 0; c < NCH; c++) {
        CP_WAIT1();
        __syncthreads();

        if (c + 2 < NCH)
            issue_stage((stg + 2) % NSTAGE, (c + 2) * BKC);
        CP_COMMIT();

        const uint32_t* As = smw + stg * STG_WORDS;
        const uint32_t* Bs = As + A_WORDS;

        #pragma unroll
        for (int kk = 0; kk < 16; kk += 8) {
            uint32_t bf[4][2];
            #pragma unroll
            for (int nt = 0; nt < 4; nt++) {
                bf[nt][0] = Bs[(kk + lc    ) * BSTR + wn + nt * 8 + lr];
                bf[nt][1] = Bs[(kk + lc + 4) * BSTR + wn + nt * 8 + lr];
            }
            #pragma unroll
            for (int mt = 0; mt < 4; mt++) {
                uint32_t a0 = As[(wm + mt * 16 + lr    ) * ASTR + kk + lc    ];
                uint32_t a1 = As[(wm + mt * 16 + 8 + lr) * ASTR + kk + lc    ];
                uint32_t a2 = As[(wm + mt * 16 + lr    ) * ASTR + kk + lc + 4];
                uint32_t a3 = As[(wm + mt * 16 + 8 + lr) * ASTR + kk + lc + 4];
                #pragma unroll
                for (int nt = 0; nt < 4; nt++)
                    mma_tf32_16x8x8(acc[mt][nt][0], acc[mt][nt][1],
                                    acc[mt][nt][2], acc[mt][nt][3],
                                    a0, a1, a2, a3, bf[nt][0], bf[nt][1]);
            }
        }
        stg = (stg + 1) % NSTAGE;
    }

    // epilogue: add bias, permute to [B,H,S,DH].
    // Q -> f32 (g_q), K -> f32 bits-as-float (g_k, rope converts later),
    // V -> tf32 bits (g_v).
    #pragma unroll
    for (int mt = 0; mt < 4; mt++) {
        #pragma unroll
        for (int nt = 0; nt < 4; nt++) {
            const int dd = wn + nt * 8 + 2 * lc;
            const int h  = (n0 + dd) >> 6;
            const int d  = dd & 63;
            const float bx = bias[n0 + dd];
            const float by = bias[n0 + dd + 1];
            #pragma unroll
            for (int half = 0; half < 2; half++) {
                const int m  = m0 + wm + mt * 16 + half * 8 + lr;
                const int b_ = m >> 10;
                const int s  = m & 1023;
                const float ox = acc[mt][nt][2 * half + 0] + bx;
                const float oy = acc[mt][nt][2 * half + 1] + by;
                const size_t idx = (((size_t)(b_ * NH + h) * SEQ + s) << 6) + d;
                if (which == 0) {
                    *(float2*)&g_q[idx] = make_float2(ox, oy);
                } else if (which == 1) {
                    *(float2*)&g_k[idx] = make_float2(ox, oy);   // still f32; rope converts
                } else {
                    uint2 u;
                    u.x = f32_to_tf32(ox);
                    u.y = f32_to_tf32(oy);
                    *(uint2*)&g_v[idx] = u;
                }
            }
        }
    }
}

// ---------------------------------------------------------------------------
// RoPE. Q: f32 in/out. K: f32 in, tf32 bits out (in place).
// ---------------------------------------------------------------------------
__global__ __launch_bounds__(256) void rope_kernel(const float* __restrict__ freqs)
{
    const int p  = blockIdx.x * 256 + threadIdx.x;
    const int d  = p & 31;
    const int s  = (p >> 5) & 1023;
    const int bh = p >> 15;
    const float f = freqs[s * 64 + d];
    const float sn = sinf(f), c = cosf(f);
    const size_t base = (((size_t)bh << 10) + s) * 64 + d;
    if (blockIdx.y == 0) {
        const float x1 = g_q[base];
        const float x2 = g_q[base + 32];
        g_q[base]      = x1 * c - x2 * sn;
        g_q[base + 32] = x2 * c + x1 * sn;
    } else {
        float* kf = (float*)g_k;
        const float x1 = kf[base];
        const float x2 = kf[base + 32];
        g_k[base]      = f32_to_tf32(x1 * c - x2 * sn);
        g_k[base + 32] = f32_to_tf32(x2 * c + x1 * sn);
    }
}

// ---------------------------------------------------------------------------
// Flash attention on tensor cores.
// K/V pre-converted tf32 bits, staged via cp.async double buffer.
// QK^T: 2-term compensated (Q split hi/lo). PV: 1-term. P stored as bits.
// Inner loops: LDS + MMA only — zero cvt.
// ---------------------------------------------------------------------------
#define KSTR 68
#define VSTR 72
#define KS_W (64 * KSTR)              // 4352 words
#define VS_W (64 * VSTR)              // 4608 words
#define KV_STG_W (KS_W + VS_W)        // 8960 words per stage
#define PS_OFF (2 * KV_STG_W)         // 17920
#define MSK_OFF (PS_OFF + KS_W)       // 22272
#define ATTN_SMEM ((MSK_OFF + SEQ) * 4)   // 93184 bytes

__global__ __launch_bounds__(128) void attn_mma(
    const float* __restrict__ mask, float* __restrict__ out)
{
    extern __shared__ uint32_t sm[];
    const uint32_t sb = smem_u32(sm);
    float*    Msk = (float*)(sm + MSK_OFF);
    uint32_t* Psb = sm + PS_OFF;

    const int q0 = blockIdx.x * 64;
    const int h  = blockIdx.y;
    const int b  = blockIdx.z;
    const int tid  = threadIdx.x;
    const int w    = tid >> 5;
    const int lane = tid & 31;
    const int lr = lane >> 2;
    const int lc = lane & 3;
    const size_t base = ((size_t)(b * NH + h)) * SEQ * DH;

    for (int i = tid; i < SEQ; i += 128) Msk[i] = mask[b * SEQ + i];

    // stage Q (f32) into Ps region
    {
        float* Pf = (float*)Psb;
        #pragma unroll
        for (int j = 0; j < 8; j++) {
            const int i   = tid + j * 128;
            const int row = i >> 4;
            const int c4  = (i & 15) * 4;
            *(float4*)&Pf[row * KSTR + c4] =
                *(const float4*)&g_q[base + (size_t)(q0 + row) * 64 + c4];
        }
    }
    __syncthreads();

    // live tile count (mask monotone per batch row)
    int nlive = 0;
    while (nlive < 16 && Msk[nlive * 64] >= -1e5f) nlive++;

    // persistent pre-split Q fragments
    uint32_t qh[8][4], ql[8][4];
    {
        const float* Pf = (const float*)Psb;
        #pragma unroll
        for (int ds = 0; ds < 8; ds++) {
            float v[4];
            v[0] = Pf[(16 * w + lr    ) * KSTR + ds * 8 + lc    ];
            v[1] = Pf[(16 * w + lr + 8) * KSTR + ds * 8 + lc    ];
            v[2] = Pf[(16 * w + lr    ) * KSTR + ds * 8 + lc + 4];
            v[3] = Pf[(16 * w + lr + 8) * KSTR + ds * 8 + lc + 4];
            #pragma unroll
            for (int r = 0; r < 4; r++) {
                qh[ds][r] = f32_to_tf32(v[r]);
                ql[ds][r] = f32_to_tf32(v[r] - __uint_as_float(qh[ds][r]));
            }
        }
    }

    auto stage_kv = [&](int stg, int kc0) {
        const uint32_t kb = sb + (uint32_t)(stg * KV_STG_W) * 4;
        const uint32_t vb = kb + KS_W * 4;
        #pragma unroll
        for (int j = 0; j < 8; j++) {
            const int i   = tid + j * 128;
            const int row = i >> 4;
            const int c4  = (i & 15) * 4;
            CP_ASYNC16(kb + (uint32_t)(row * KSTR + c4) * 4,
                       &g_k[base + (size_t)(kc0 + row) * 64 + c4]);
            CP_ASYNC16(vb + (uint32_t)(row * VSTR + c4) * 4,
                       &g_v[base + (size_t)(kc0 + row) * 64 + c4]);
        }
    };

    float m0 = -1e30f, m1 = -1e30f, l0 = 0.0f, l1 = 0.0f;
    float ctx[8][4];
    #pragma unroll
    for (int nt = 0; nt < 8; nt++)
        #pragma unroll
        for (int r = 0; r < 4; r++) ctx[nt][r] = 0.0f;

    stage_kv(0, 0);
    CP_COMMIT();
    if (nlive > 1) stage_kv(1, 64);
    CP_COMMIT();

    for (int kt = 0; kt < nlive; kt++) {
        const int kc0 = kt * 64;
        CP_WAIT1();
        __syncthreads();    // stage data visible CTA-wide

        const uint32_t* Ksb = sm + (kt & 1) * KV_STG_W;
        const uint32_t* Vsb = Ksb + KS_W;

        // ---- S = Q K^T (2-term) ----
        float sa[8][4];
        #pragma unroll
        for (int nt = 0; nt < 8; nt++)
            #pragma unroll
            for (int r = 0; r < 4; r++) sa[nt][r] = 0.0f;

        #pragma unroll
        for (int ds = 0; ds < 8; ds++) {
            #pragma unroll
            for (int nt = 0; nt < 8; nt++) {
                const uint32_t bh0 = Ksb[(nt * 8 + lr) * KSTR + ds * 8 + lc    ];
                const uint32_t bh1 = Ksb[(nt * 8 + lr) * KSTR + ds * 8 + lc + 4];
                mma_tf32_16x8x8(sa[nt][0], sa[nt][1], sa[nt][2], sa[nt][3],
                                qh[ds][0], qh[ds][1], qh[ds][2], qh[ds][3], bh0, bh1);
                mma_tf32_16x8x8(sa[nt][0], sa[nt][1], sa[nt][2], sa[nt][3],
                                ql[ds][0], ql[ds][1], ql[ds][2], ql[ds][3], bh0, bh1);
            }
        }

        // ---- scale + mask + online softmax ----
        float mx0 = -1e30f, mx1 = -1e30f;
        #pragma unroll
        for (int nt = 0; nt < 8; nt++) {
            const float mk0 = Msk[kc0 + nt * 8 + 2 * lc    ];
            const float mk1 = Msk[kc0 + nt * 8 + 2 * lc + 1];
            sa[nt][0] = fmaf(sa[nt][0], 0.125f, mk0);
            sa[nt][1] = fmaf(sa[nt][1], 0.125f, mk1);
            sa[nt][2] = fmaf(sa[nt][2], 0.125f, mk0);
            sa[nt][3] = fmaf(sa[nt][3], 0.125f, mk1);
            mx0 = fmaxf(mx0, fmaxf(sa[nt][0], sa[nt][1]));
            mx1 = fmaxf(mx1, fmaxf(sa[nt][2], sa[nt][3]));
        }
        mx0 = fmaxf(mx0, __shfl_xor_sync(0xffffffffu, mx0, 1));
        mx0 = fmaxf(mx0, __shfl_xor_sync(0xffffffffu, mx0, 2));
        mx1 = fmaxf(mx1, __shfl_xor_sync(0xffffffffu, mx1, 1));
        mx1 = fmaxf(mx1, __shfl_xor_sync(0xffffffffu, mx1, 2));

        const float mn0 = fmaxf(m0, mx0);
        const float mn1 = fmaxf(m1, mx1);
        const float cr0 = __expf(m0 - mn0);
        const float cr1 = __expf(m1 - mn1);
        l0 *= cr0; l1 *= cr1;
        m0 = mn0; m1 = mn1;

        float ps0 = 0.0f, ps1 = 0.0f;
        #pragma unroll
        for (int nt = 0; nt < 8; nt++) {
            ctx[nt][0] *= cr0; ctx[nt][1] *= cr0;
            ctx[nt][2] *= cr1; ctx[nt][3] *= cr1;
            sa[nt][0] = __expf(sa[nt][0] - mn0);
            sa[nt][1] = __expf(sa[nt][1] - mn0);
            sa[nt][2] = __expf(sa[nt][2] - mn1);
            sa[nt][3] = __expf(sa[nt][3] - mn1);
            ps0 += sa[nt][0] + sa[nt][1];
            ps1 += sa[nt][2] + sa[nt][3];
        }
        ps0 += __shfl_xor_sync(0xffffffffu, ps0, 1);
        ps0 += __shfl_xor_sync(0xffffffffu, ps0, 2);
        ps1 += __shfl_xor_sync(0xffffffffu, ps1, 1);
        ps1 += __shfl_xor_sync(0xffffffffu, ps1, 2);
        l0 += ps0; l1 += ps1;

        // store P as tf32 bits (warp-private rows)
        #pragma unroll
        for (int nt = 0; nt < 8; nt++) {
            uint2 u0, u1;
            u0.x = f32_to_tf32(sa[nt][0]); u0.y = f32_to_tf32(sa[nt][1]);
            u1.x = f32_to_tf32(sa[nt][2]); u1.y = f32_to_tf32(sa[nt][3]);
            *(uint2*)&Psb[(16 * w + lr    ) * KSTR + nt * 8 + 2 * lc] = u0;
            *(uint2*)&Psb[(16 * w + lr + 8) * KSTR + nt * 8 + 2 * lc] = u1;
        }
        __syncwarp();

        // ---- ctx += P V (1-term) ----
        #pragma unroll
        for (int kk = 0; kk < 8; kk++) {
            uint32_t ah[4];
            ah[0] = Psb[(16 * w + lr    ) * KSTR + kk * 8 + lc    ];
            ah[1] = Psb[(16 * w + lr + 8) * KSTR + kk * 8 + lc    ];
            ah[2] = Psb[(16 * w + lr    ) * KSTR + kk * 8 + lc + 4];
            ah[3] = Psb[(16 * w + lr + 8) * KSTR + kk * 8 + lc + 4];
            #pragma unroll
            for (int nt = 0; nt < 8; nt++) {
                const uint32_t bh0 = Vsb[(kk * 8 + lc    ) * VSTR + nt * 8 + lr];
                const uint32_t bh1 = Vsb[(kk * 8 + lc + 4) * VSTR + nt * 8 + lr];
                mma_tf32_16x8x8(ctx[nt][0], ctx[nt][1], ctx[nt][2], ctx[nt][3],
                                ah[0], ah[1], ah[2], ah[3], bh0, bh1);
            }
        }

        __syncthreads();    // all warps done with this stage before refill
        if (kt + 2 < nlive)
            stage_kv(kt & 1, (kt + 2) * 64);
        CP_COMMIT();        // unconditional: uniform group accounting
    }

    const float inv0 = 1.0f / l0;
    const float inv1 = 1.0f / l1;
    const int row0 = q0 + 16 * w + lr;
    const int row1 = row0 + 8;
    #pragma unroll
    for (int nt = 0; nt < 8; nt++) {
        const int d = nt * 8 + 2 * lc;
        *(float2*)&out[(size_t)(b * SEQ + row0) * (NH * DH) + h * 64 + d] =
            make_float2(ctx[nt][0] * inv0, ctx[nt][1] * inv0);
        *(float2*)&out[(size_t)(b * SEQ + row1) * (NH * DH) + h * 64 + d] =
            make_float2(ctx[nt][2] * inv1, ctx[nt][3] * inv1);
    }
}

// ---------------------------------------------------------------------------
extern "C" void kernel_launch(void* const* d_in, const int* in_sizes, int n_in,
                              void* d_out, int out_size)
{
    const float* X     = (const float*)d_in[0];
    const float* mask  = (const float*)d_in[1];
    const float* freqs = (const float*)d_in[2];
    const float* Wq    = (const float*)d_in[3];
    const float* bq    = (const float*)d_in[4];
    const float* Wk    = (const float*)d_in[5];
    const float* bk    = (const float*)d_in[6];
    const float* Wv    = (const float*)d_in[7];
    const float* bv    = (const float*)d_in[8];
    float* out = (float*)d_out;

    cudaFuncSetAttribute(qkv_mma,  cudaFuncAttributeMaxDynamicSharedMemorySize, QKV_SMEM);
    cudaFuncSetAttribute(attn_mma, cudaFuncAttributeMaxDynamicSharedMemorySize, ATTN_SMEM);

    const int NX = BATCH * SEQ * HID / 4;
    const int NW = HID * HID / 4;
    precvt<<<(NX + 3 * NW) / 256, 256>>>(X, Wq, Wk, Wv);

    dim3 gG(HID / 128, (BATCH * SEQ) / 128, 3);
    qkv_mma<<<gG, 256, QKV_SMEM>>>(bq, bk, bv);

    dim3 gR((BATCH * NH * SEQ * 32) / 256, 2);
    rope_kernel<<<gR, 256>>>(freqs);

    dim3 gA(SEQ / 64, NH, BATCH);
    attn_mma<<<gA, 128, ATTN_SMEM>>>(mask, out);
}

// round 9
// speedup vs baseline: 3.4147x; 1.0055x over previous
#include <cuda_runtime.h>
#include <cuda_bf16.h>
#include <cstdint>

// Problem: B=4, S=1024, HID=1024, H=16, DH=64
// inputs: 0 hidden [4096,1024] f32, 1 mask [4,1024] f32, 2 freqs [1024,64] f32,
//         3 Wq, 4 bq, 5 Wk, 6 bk, 7 Wv, 8 bv
// output: ctx [4,1024,1024] f32

#define BATCH 4
#define SEQ   1024
#define HID   1024
#define NH    16
#define DH    64

// scratch. g_q stays f32 (hi/lo split in attn).
// g_k: f32 after qkv, overwritten with tf32 bits by rope.
// g_v: tf32 bits from qkv epilogue.
__device__ float    g_q[BATCH*NH*SEQ*DH];
__device__ uint32_t g_k[BATCH*NH*SEQ*DH];
__device__ uint32_t g_v[BATCH*NH*SEQ*DH];
__device__ uint32_t g_xt[BATCH*SEQ*HID];
__device__ uint32_t g_wc[3*HID*HID];

__device__ __forceinline__ uint32_t f32_to_tf32(float x) {
    uint32_t u;
    asm("cvt.rna.tf32.f32 %0, %1;" : "=r"(u) : "f"(x));
    return u;
}

__device__ __forceinline__ void mma_tf32_16x8x8(
    float& c0, float& c1, float& c2, float& c3,
    uint32_t a0, uint32_t a1, uint32_t a2, uint32_t a3,
    uint32_t b0, uint32_t b1)
{
    asm volatile(
        "mma.sync.aligned.m16n8k8.row.col.f32.tf32.tf32.f32 "
        "{%0,%1,%2,%3}, {%4,%5,%6,%7}, {%8,%9}, {%0,%1,%2,%3};"
        : "+f"(c0), "+f"(c1), "+f"(c2), "+f"(c3)
        : "r"(a0), "r"(a1), "r"(a2), "r"(a3), "r"(b0), "r"(b1));
}

__device__ __forceinline__ uint32_t smem_u32(const void* p) {
    uint32_t a;
    asm("{ .reg .u64 t; cvta.to.shared.u64 t, %1; cvt.u32.u64 %0, t; }" : "=r"(a) : "l"(p));
    return a;
}

#define CP_ASYNC16(dst, src) \
    asm volatile("cp.async.cg.shared.global [%0], [%1], 16;" :: "r"(dst), "l"(src) : "memory")
#define CP_COMMIT() asm volatile("cp.async.commit_group;" ::: "memory")
#define CP_WAIT1()  asm volatile("cp.async.wait_group 1;" ::: "memory")
#define CP_WAIT2()  asm volatile("cp.async.wait_group 2;" ::: "memory")

// ---------------------------------------------------------------------------
// Pre-convert X and W to tf32 bit patterns.
// ---------------------------------------------------------------------------
__global__ __launch_bounds__(256) void precvt(
    const float* __restrict__ X,
    const float* __restrict__ Wq, const float* __restrict__ Wk, const float* __restrict__ Wv)
{
    size_t g = (size_t)blockIdx.x * 256 + threadIdx.x;
    const size_t NX = (size_t)BATCH * SEQ * HID / 4;
    const size_t NW = (size_t)HID * HID / 4;
    const float* src;
    uint32_t* dst;
    if (g < NX)               { src = X;  dst = g_xt; }
    else if (g < NX + NW)     { src = Wq; dst = g_wc;               g -= NX; }
    else if (g < NX + 2 * NW) { src = Wk; dst = g_wc + HID * HID;   g -= NX + NW; }
    else                      { src = Wv; dst = g_wc + 2*HID*HID;   g -= NX + 2*NW; }
    const float4 v = ((const float4*)src)[g];
    uint4 t;
    t.x = f32_to_tf32(v.x); t.y = f32_to_tf32(v.y);
    t.z = f32_to_tf32(v.z); t.w = f32_to_tf32(v.w);
    ((uint4*)dst)[g] = t;
}

// ---------------------------------------------------------------------------
// QKV projection via tf32 mma.sync + cp.async 3-stage pipeline (unchanged R8).
// ---------------------------------------------------------------------------
#define BKC 16
#define NCH (HID / BKC)
#define NSTAGE 3
#define ASTR 20
#define BSTR 136
#define A_WORDS (128 * ASTR)
#define B_WORDS (16 * BSTR)
#define STG_WORDS (A_WORDS + B_WORDS)
#define QKV_SMEM (NSTAGE * STG_WORDS * 4)

__global__ __launch_bounds__(256, 2) void qkv_mma(
    const float* __restrict__ bq, const float* __restrict__ bk, const float* __restrict__ bv)
{
    extern __shared__ uint32_t smw[];
    const uint32_t sb = smem_u32(smw);

    const int which = blockIdx.z;
    const uint32_t* __restrict__ W = g_wc + (size_t)which * HID * HID;
    const float* __restrict__ bias = (which == 0) ? bq : (which == 1) ? bk : bv;

    const int m0 = blockIdx.y * 128;
    const int n0 = blockIdx.x * 128;

    const int tid  = threadIdx.x;
    const int wid  = tid >> 5;
    const int lane = tid & 31;
    const int wm = (wid & 1) * 64;
    const int wn = (wid >> 1) * 32;
    const int lr = lane >> 2;
    const int lc = lane & 3;

    const int arow  = tid >> 2;
    const int akc   = (tid & 3) * 4;
    const int bkrow = tid >> 5;
    const int bnc   = (tid & 31) * 4;

    auto issue_stage = [&](int stg, int k0) {
        const uint32_t ab = sb + (uint32_t)(stg * STG_WORDS) * 4;
        const uint32_t bb = ab + A_WORDS * 4;
        #pragma unroll
        for (int i = 0; i < 2; i++) {
            const int row = arow + i * 64;
            CP_ASYNC16(ab + (uint32_t)(row * ASTR + akc) * 4,
                       &g_xt[(size_t)(m0 + row) * HID + k0 + akc]);
        }
        #pragma unroll
        for (int i = 0; i < 2; i++) {
            const int kr = bkrow + i * 8;
            CP_ASYNC16(bb + (uint32_t)(kr * BSTR + bnc) * 4,
                       &W[(size_t)(k0 + kr) * HID + n0 + bnc]);
        }
    };

    float acc[4][4][4];
    #pragma unroll
    for (int mt = 0; mt < 4; mt++)
        #pragma unroll
        for (int nt = 0; nt < 4; nt++)
            #pragma unroll
            for (int r = 0; r < 4; r++) acc[mt][nt][r] = 0.0f;

    issue_stage(0, 0);        CP_COMMIT();
    issue_stage(1, BKC);      CP_COMMIT();

    int stg = 0;
    for (int c = 0; c < NCH; c++) {
        CP_WAIT1();
        __syncthreads();

        if (c + 2 < NCH)
            issue_stage((stg + 2) % NSTAGE, (c + 2) * BKC);
        CP_COMMIT();

        const uint32_t* As = smw + stg * STG_WORDS;
        const uint32_t* Bs = As + A_WORDS;

        #pragma unroll
        for (int kk = 0; kk < 16; kk += 8) {
            uint32_t bf[4][2];
            #pragma unroll
            for (int nt = 0; nt < 4; nt++) {
                bf[nt][0] = Bs[(kk + lc    ) * BSTR + wn + nt * 8 + lr];
                bf[nt][1] = Bs[(kk + lc + 4) * BSTR + wn + nt * 8 + lr];
            }
            #pragma unroll
            for (int mt = 0; mt < 4; mt++) {
                uint32_t a0 = As[(wm + mt * 16 + lr    ) * ASTR + kk + lc    ];
                uint32_t a1 = As[(wm + mt * 16 + 8 + lr) * ASTR + kk + lc    ];
                uint32_t a2 = As[(wm + mt * 16 + lr    ) * ASTR + kk + lc + 4];
                uint32_t a3 = As[(wm + mt * 16 + 8 + lr) * ASTR + kk + lc + 4];
                #pragma unroll
                for (int nt = 0; nt < 4; nt++)
                    mma_tf32_16x8x8(acc[mt][nt][0], acc[mt][nt][1],
                                    acc[mt][nt][2], acc[mt][nt][3],
                                    a0, a1, a2, a3, bf[nt][0], bf[nt][1]);
            }
        }
        stg = (stg + 1) % NSTAGE;
    }

    #pragma unroll
    for (int mt = 0; mt < 4; mt++) {
        #pragma unroll
        for (int nt = 0; nt < 4; nt++) {
            const int dd = wn + nt * 8 + 2 * lc;
            const int h  = (n0 + dd) >> 6;
            const int d  = dd & 63;
            const float bx = bias[n0 + dd];
            const float by = bias[n0 + dd + 1];
            #pragma unroll
            for (int half = 0; half < 2; half++) {
                const int m  = m0 + wm + mt * 16 + half * 8 + lr;
                const int b_ = m >> 10;
                const int s  = m & 1023;
                const float ox = acc[mt][nt][2 * half + 0] + bx;
                const float oy = acc[mt][nt][2 * half + 1] + by;
                const size_t idx = (((size_t)(b_ * NH + h) * SEQ + s) << 6) + d;
                if (which == 0) {
                    *(float2*)&g_q[idx] = make_float2(ox, oy);
                } else if (which == 1) {
                    *(float2*)&g_k[idx] = make_float2(ox, oy);
                } else {
                    uint2 u;
                    u.x = f32_to_tf32(ox);
                    u.y = f32_to_tf32(oy);
                    *(uint2*)&g_v[idx] = u;
                }
            }
        }
    }
}

// ---------------------------------------------------------------------------
// RoPE. Q: f32 in/out. K: f32 in, tf32 bits out.
// ---------------------------------------------------------------------------
__global__ __launch_bounds__(256) void rope_kernel(const float* __restrict__ freqs)
{
    const int p  = blockIdx.x * 256 + threadIdx.x;
    const int d  = p & 31;
    const int s  = (p >> 5) & 1023;
    const int bh = p >> 15;
    const float f = freqs[s * 64 + d];
    const float sn = sinf(f), c = cosf(f);
    const size_t base = (((size_t)bh << 10) + s) * 64 + d;
    if (blockIdx.y == 0) {
        const float x1 = g_q[base];
        const float x2 = g_q[base + 32];
        g_q[base]      = x1 * c - x2 * sn;
        g_q[base + 32] = x2 * c + x1 * sn;
    } else {
        float* kf = (float*)g_k;
        const float x1 = kf[base];
        const float x2 = kf[base + 32];
        g_k[base]      = f32_to_tf32(x1 * c - x2 * sn);
        g_k[base + 32] = f32_to_tf32(x2 * c + x1 * sn);
    }
}

// ---------------------------------------------------------------------------
// Flash attention on tensor cores — occupancy build (3 CTAs/SM).
// K double-buffered, V single-buffered (prefetch overlaps QK+softmax).
// cp.async group order per tile: [V(kt)] [K(kt+1)]; wait2 -> K(kt) ready,
// wait1 -> V(kt) ready (next K still in flight).
// Q kept f32 in regs, hi/lo split per ds (saves 64 regs vs persistent split).
// ---------------------------------------------------------------------------
#define KSTR 68
#define VSTR 72
#define KS_W (64 * KSTR)              // 4352 words
#define VS_W (64 * VSTR)              // 4608 words
#define K0_OFF 0
#define K1_OFF KS_W
#define V_OFF  (2 * KS_W)             // 8704
#define PS_OFF (V_OFF + VS_W)         // 13312
#define MSK_OFF (PS_OFF + KS_W)       // 17664
#define ATTN_SMEM ((MSK_OFF + SEQ) * 4)   // 74752 bytes -> 3 CTAs/SM

__global__ __launch_bounds__(128, 3) void attn_mma(
    const float* __restrict__ mask, float* __restrict__ out)
{
    extern __shared__ uint32_t sm[];
    const uint32_t sb = smem_u32(sm);
    float*    Msk = (float*)(sm + MSK_OFF);
    uint32_t* Psb = sm + PS_OFF;

    const int q0 = blockIdx.x * 64;
    const int h  = blockIdx.y;
    const int b  = blockIdx.z;
    const int tid  = threadIdx.x;
    const int w    = tid >> 5;
    const int lane = tid & 31;
    const int lr = lane >> 2;
    const int lc = lane & 3;
    const size_t base = ((size_t)(b * NH + h)) * SEQ * DH;

    for (int i = tid; i < SEQ; i += 128) Msk[i] = mask[b * SEQ + i];

    // stage Q (f32) into Ps region
    {
        float* Pf = (float*)Psb;
        #pragma unroll
        for (int j = 0; j < 8; j++) {
            const int i   = tid + j * 128;
            const int row = i >> 4;
            const int c4  = (i & 15) * 4;
            *(float4*)&Pf[row * KSTR + c4] =
                *(const float4*)&g_q[base + (size_t)(q0 + row) * 64 + c4];
        }
    }
    __syncthreads();

    int nlive = 0;
    while (nlive < 16 && Msk[nlive * 64] >= -1e5f) nlive++;

    // Q fragments kept f32 (split per ds in the loop)
    float qf[8][4];
    {
        const float* Pf = (const float*)Psb;
        #pragma unroll
        for (int ds = 0; ds < 8; ds++) {
            qf[ds][0] = Pf[(16 * w + lr    ) * KSTR + ds * 8 + lc    ];
            qf[ds][1] = Pf[(16 * w + lr + 8) * KSTR + ds * 8 + lc    ];
            qf[ds][2] = Pf[(16 * w + lr    ) * KSTR + ds * 8 + lc + 4];
            qf[ds][3] = Pf[(16 * w + lr + 8) * KSTR + ds * 8 + lc + 4];
        }
    }
    __syncthreads();

    auto stage_k = [&](int stg, int kc0) {
        const uint32_t kb = sb + (uint32_t)(stg ? K1_OFF : K0_OFF) * 4;
        #pragma unroll
        for (int j = 0; j < 8; j++) {
            const int i   = tid + j * 128;
            const int row = i >> 4;
            const int c4  = (i & 15) * 4;
            CP_ASYNC16(kb + (uint32_t)(row * KSTR + c4) * 4,
                       &g_k[base + (size_t)(kc0 + row) * 64 + c4]);
        }
    };
    auto stage_v = [&](int kc0) {
        const uint32_t vb = sb + (uint32_t)V_OFF * 4;
        #pragma unroll
        for (int j = 0; j < 8; j++) {
            const int i   = tid + j * 128;
            const int row = i >> 4;
            const int c4  = (i & 15) * 4;
            CP_ASYNC16(vb + (uint32_t)(row * VSTR + c4) * 4,
                       &g_v[base + (size_t)(kc0 + row) * 64 + c4]);
        }
    };

    float m0 = -1e30f, m1 = -1e30f, l0 = 0.0f, l1 = 0.0f;
    float ctx[8][4];
    #pragma unroll
    for (int nt = 0; nt < 8; nt++)
        #pragma unroll
        for (int r = 0; r < 4; r++) ctx[nt][r] = 0.0f;

    stage_k(0, 0);
    CP_COMMIT();                         // pending: [K0]

    for (int kt = 0; kt < nlive; kt++) {
        const int kc0 = kt * 64;

        stage_v(kc0);
        CP_COMMIT();                     // +[V(kt)]
        if (kt + 1 < nlive)
            stage_k((kt + 1) & 1, kc0 + 64);
        CP_COMMIT();                     // +[K(kt+1)] (possibly empty)

        CP_WAIT2();                      // K(kt) complete
        __syncthreads();

        const uint32_t* Ksb = sm + ((kt & 1) ? K1_OFF : K0_OFF);

        // ---- S = Q K^T (2-term, split per ds) ----
        float sa[8][4];
        #pragma unroll
        for (int nt = 0; nt < 8; nt++)
            #pragma unroll
            for (int r = 0; r < 4; r++) sa[nt][r] = 0.0f;

        #pragma unroll
        for (int ds = 0; ds < 8; ds++) {
            uint32_t ah[4], al[4];
            #pragma unroll
            for (int r = 0; r < 4; r++) {
                ah[r] = f32_to_tf32(qf[ds][r]);
                al[r] = f32_to_tf32(qf[ds][r] - __uint_as_float(ah[r]));
            }
            #pragma unroll
            for (int nt = 0; nt < 8; nt++) {
                const uint32_t bh0 = Ksb[(nt * 8 + lr) * KSTR + ds * 8 + lc    ];
                const uint32_t bh1 = Ksb[(nt * 8 + lr) * KSTR + ds * 8 + lc + 4];
                mma_tf32_16x8x8(sa[nt][0], sa[nt][1], sa[nt][2], sa[nt][3],
                                ah[0], ah[1], ah[2], ah[3], bh0, bh1);
                mma_tf32_16x8x8(sa[nt][0], sa[nt][1], sa[nt][2], sa[nt][3],
                                al[0], al[1], al[2], al[3], bh0, bh1);
            }
        }

        // ---- scale + mask + online softmax ----
        float mx0 = -1e30f, mx1 = -1e30f;
        #pragma unroll
        for (int nt = 0; nt < 8; nt++) {
            const float mk0 = Msk[kc0 + nt * 8 + 2 * lc    ];
            const float mk1 = Msk[kc0 + nt * 8 + 2 * lc + 1];
            sa[nt][0] = fmaf(sa[nt][0], 0.125f, mk0);
            sa[nt][1] = fmaf(sa[nt][1], 0.125f, mk1);
            sa[nt][2] = fmaf(sa[nt][2], 0.125f, mk0);
            sa[nt][3] = fmaf(sa[nt][3], 0.125f, mk1);
            mx0 = fmaxf(mx0, fmaxf(sa[nt][0], sa[nt][1]));
            mx1 = fmaxf(mx1, fmaxf(sa[nt][2], sa[nt][3]));
        }
        mx0 = fmaxf(mx0, __shfl_xor_sync(0xffffffffu, mx0, 1));
        mx0 = fmaxf(mx0, __shfl_xor_sync(0xffffffffu, mx0, 2));
        mx1 = fmaxf(mx1, __shfl_xor_sync(0xffffffffu, mx1, 1));
        mx1 = fmaxf(mx1, __shfl_xor_sync(0xffffffffu, mx1, 2));

        const float mn0 = fmaxf(m0, mx0);
        const float mn1 = fmaxf(m1, mx1);
        const float cr0 = __expf(m0 - mn0);
        const float cr1 = __expf(m1 - mn1);
        l0 *= cr0; l1 *= cr1;
        m0 = mn0; m1 = mn1;

        float ps0 = 0.0f, ps1 = 0.0f;
        #pragma unroll
        for (int nt = 0; nt < 8; nt++) {
            ctx[nt][0] *= cr0; ctx[nt][1] *= cr0;
            ctx[nt][2] *= cr1; ctx[nt][3] *= cr1;
            sa[nt][0] = __expf(sa[nt][0] - mn0);
            sa[nt][1] = __expf(sa[nt][1] - mn0);
            sa[nt][2] = __expf(sa[nt][2] - mn1);
            sa[nt][3] = __expf(sa[nt][3] - mn1);
            ps0 += sa[nt][0] + sa[nt][1];
            ps1 += sa[nt][2] + sa[nt][3];
        }
        ps0 += __shfl_xor_sync(0xffffffffu, ps0, 1);
        ps0 += __shfl_xor_sync(0xffffffffu, ps0, 2);
        ps1 += __shfl_xor_sync(0xffffffffu, ps1, 1);
        ps1 += __shfl_xor_sync(0xffffffffu, ps1, 2);
        l0 += ps0; l1 += ps1;

        // store P as tf32 bits (warp-private rows)
        #pragma unroll
        for (int nt = 0; nt < 8; nt++) {
            uint2 u0, u1;
            u0.x = f32_to_tf32(sa[nt][0]); u0.y = f32_to_tf32(sa[nt][1]);
            u1.x = f32_to_tf32(sa[nt][2]); u1.y = f32_to_tf32(sa[nt][3]);
            *(uint2*)&Psb[(16 * w + lr    ) * KSTR + nt * 8 + 2 * lc] = u0;
            *(uint2*)&Psb[(16 * w + lr + 8) * KSTR + nt * 8 + 2 * lc] = u1;
        }
        __syncwarp();

        CP_WAIT1();                      // V(kt) complete (K(kt+1) may fly)
        __syncthreads();

        const uint32_t* Vsb = sm + V_OFF;

        // ---- ctx += P V (1-term) ----
        #pragma unroll
        for (int kk = 0; kk < 8; kk++) {
            uint32_t ah[4];
            ah[0] = Psb[(16 * w + lr    ) * KSTR + kk * 8 + lc    ];
            ah[1] = Psb[(16 * w + lr + 8) * KSTR + kk * 8 + lc    ];
            ah[2] = Psb[(16 * w + lr    ) * KSTR + kk * 8 + lc + 4];
            ah[3] = Psb[(16 * w + lr + 8) * KSTR + kk * 8 + lc + 4];
            #pragma unroll
            for (int nt = 0; nt < 8; nt++) {
                const uint32_t bh0 = Vsb[(kk * 8 + lc    ) * VSTR + nt * 8 + lr];
                const uint32_t bh1 = Vsb[(kk * 8 + lc + 4) * VSTR + nt * 8 + lr];
                mma_tf32_16x8x8(ctx[nt][0], ctx[nt][1], ctx[nt][2], ctx[nt][3],
                                ah[0], ah[1], ah[2], ah[3], bh0, bh1);
            }
        }

        __syncthreads();                 // all warps done with V before refill
    }

    const float inv0 = 1.0f / l0;
    const float inv1 = 1.0f / l1;
    const int row0 = q0 + 16 * w + lr;
    const int row1 = row0 + 8;
    #pragma unroll
    for (int nt = 0; nt < 8; nt++) {
        const int d = nt * 8 + 2 * lc;
        *(float2*)&out[(size_t)(b * SEQ + row0) * (NH * DH) + h * 64 + d] =
            make_float2(ctx[nt][0] * inv0, ctx[nt][1] * inv0);
        *(float2*)&out[(size_t)(b * SEQ + row1) * (NH * DH) + h * 64 + d] =
            make_float2(ctx[nt][2] * inv1, ctx[nt][3] * inv1);
    }
}

// ---------------------------------------------------------------------------
extern "C" void kernel_launch(void* const* d_in, const int* in_sizes, int n_in,
                              void* d_out, int out_size)
{
    const float* X     = (const float*)d_in[0];
    const float* mask  = (const float*)d_in[1];
    const float* freqs = (const float*)d_in[2];
    const float* Wq    = (const float*)d_in[3];
    const float* bq    = (const float*)d_in[4];
    const float* Wk    = (const float*)d_in[5];
    const float* bk    = (const float*)d_in[6];
    const float* Wv    = (const float*)d_in[7];
    const float* bv    = (const float*)d_in[8];
    float* out = (float*)d_out;

    cudaFuncSetAttribute(qkv_mma,  cudaFuncAttributeMaxDynamicSharedMemorySize, QKV_SMEM);
    cudaFuncSetAttribute(attn_mma, cudaFuncAttributeMaxDynamicSharedMemorySize, ATTN_SMEM);

    const int NX = BATCH * SEQ * HID / 4;
    const int NW = HID * HID / 4;
    precvt<<<(NX + 3 * NW) / 256, 256>>>(X, Wq, Wk, Wv);

    dim3 gG(HID / 128, (BATCH * SEQ) / 128, 3);
    qkv_mma<<<gG, 256, QKV_SMEM>>>(bq, bk, bv);

    dim3 gR((BATCH * NH * SEQ * 32) / 256, 2);
    rope_kernel<<<gR, 256>>>(freqs);

    dim3 gA(SEQ / 64, NH, BATCH);
    attn_mma<<<gA, 128, ATTN_SMEM>>>(mask, out);
}

// round 10
// speedup vs baseline: 3.9305x; 1.1511x over previous
#include <cuda_runtime.h>
#include <cuda_bf16.h>
#include <cstdint>

// Problem: B=4, S=1024, HID=1024, H=16, DH=64
// inputs: 0 hidden [4096,1024] f32, 1 mask [4,1024] f32, 2 freqs [1024,64] f32,
//         3 Wq, 4 bq, 5 Wk, 6 bk, 7 Wv, 8 bv
// output: ctx [4,1024,1024] f32

#define BATCH 4
#define SEQ   1024
#define HID   1024
#define NH    16
#define DH    64

// scratch
__device__ float    g_q [BATCH*NH*SEQ*DH];   // f32, row-major [B,H,S,DH]
__device__ float    g_k [BATCH*NH*SEQ*DH];   // f32 row-major (pre-rope)
__device__ uint32_t g_k2[BATCH*NH*SEQ*DH];   // tf32 bits, B-frag pair-major (post-rope)
__device__ uint32_t g_v [BATCH*NH*SEQ*DH];   // tf32 bits, row-major
__device__ uint32_t g_xt[BATCH*SEQ*HID];     // X tf32 bits, A-fragment-major
__device__ uint32_t g_wc[3*HID*HID];         // W tf32 bits, B-fragment pair-major

__device__ __forceinline__ uint32_t f32_to_tf32(float x) {
    uint32_t u;
    asm("cvt.rna.tf32.f32 %0, %1;" : "=r"(u) : "f"(x));
    return u;
}

__device__ __forceinline__ void mma_tf32_16x8x8(
    float& c0, float& c1, float& c2, float& c3,
    uint32_t a0, uint32_t a1, uint32_t a2, uint32_t a3,
    uint32_t b0, uint32_t b1)
{
    asm volatile(
        "mma.sync.aligned.m16n8k8.row.col.f32.tf32.tf32.f32 "
        "{%0,%1,%2,%3}, {%4,%5,%6,%7}, {%8,%9}, {%0,%1,%2,%3};"
        : "+f"(c0), "+f"(c1), "+f"(c2), "+f"(c3)
        : "r"(a0), "r"(a1), "r"(a2), "r"(a3), "r"(b0), "r"(b1));
}

__device__ __forceinline__ uint32_t smem_u32(const void* p) {
    uint32_t a;
    asm("{ .reg .u64 t; cvta.to.shared.u64 t, %1; cvt.u32.u64 %0, t; }" : "=r"(a) : "l"(p));
    return a;
}

#define CP_ASYNC16(dst, src) \
    asm volatile("cp.async.cg.shared.global [%0], [%1], 16;" :: "r"(dst), "l"(src) : "memory")
#define CP_COMMIT() asm volatile("cp.async.commit_group;" ::: "memory")
#define CP_WAIT1()  asm volatile("cp.async.wait_group 1;" ::: "memory")
#define CP_WAIT2()  asm volatile("cp.async.wait_group 2;" ::: "memory")

// ---------------------------------------------------------------------------
// precvt: X -> g_xt (A-fragment-major), W -> g_wc (B-fragment pair-major).
// A frag: fA = m16*128 + k8; lane(lr,lc) holds 16B =
//   tf32{ X[16m16+lr][8k8+lc], X[+8][..], X[..][+4], X[+8][+4] }.
// B frag: fB = n8*128 + k8; lane holds 8B =
//   tf32{ W[8k8+lc][8n8+lr], W[8k8+4+lc][8n8+lr] }.
// ---------------------------------------------------------------------------
#define NA_LANES (256*128*32)   // 1048576
#define NB_LANES (128*128*32)   // 524288

__global__ __launch_bounds__(256) void precvt(
    const float* __restrict__ X,
    const float* __restrict__ Wq, const float* __restrict__ Wk, const float* __restrict__ Wv)
{
    size_t g = (size_t)blockIdx.x * 256 + threadIdx.x;
    if (g < NA_LANES) {
        const int lane = (int)(g & 31);
        const int fA   = (int)(g >> 5);
        const int m16 = fA >> 7, k8 = fA & 127;
        const int lr = lane >> 2, lc = lane & 3;
        const int r0 = m16 * 16 + lr, c0 = k8 * 8 + lc;
        uint4 t;
        t.x = f32_to_tf32(X[(size_t)r0 * HID + c0]);
        t.y = f32_to_tf32(X[(size_t)(r0 + 8) * HID + c0]);
        t.z = f32_to_tf32(X[(size_t)r0 * HID + c0 + 4]);
        t.w = f32_to_tf32(X[(size_t)(r0 + 8) * HID + c0 + 4]);
        ((uint4*)g_xt)[g] = t;
    } else {
        g -= NA_LANES;
        const int which = (int)(g / NB_LANES);
        const size_t gg = g % NB_LANES;
        const float* __restrict__ W = (which == 0) ? Wq : (which == 1) ? Wk : Wv;
        const int lane = (int)(gg & 31);
        const int fB   = (int)(gg >> 5);
        const int n8 = fB >> 7, k8 = fB & 127;
        const int lr = lane >> 2, lc = lane & 3;
        const int kk = k8 * 8 + lc, nn = n8 * 8 + lr;
        uint2 t;
        t.x = f32_to_tf32(W[(size_t)kk * HID + nn]);
        t.y = f32_to_tf32(W[(size_t)(kk + 4) * HID + nn]);
        ((uint2*)g_wc)[(size_t)which * NB_LANES + gg] = t;
    }
}

// ---------------------------------------------------------------------------
// QKV projection: fragment-major operands, LDS.128/LDS.64 loads,
// cp.async 3-stage pipeline. CTA 128x128, BK=16, 8 warps (2m x 4n, warp 64x32).
// ---------------------------------------------------------------------------
#define NCH 64                 // 1024/16 chunks
#define A_TILE_B 8192          // 16 frags * 512B
#define B_TILE_B 8192          // 32 frags * 256B
#define STG_B (A_TILE_B + B_TILE_B)
#define QKV_SMEM (3 * STG_B)   // 49152

__global__ __launch_bounds__(256, 2) void qkv_mma(
    const float* __restrict__ bq, const float* __restrict__ bk, const float* __restrict__ bv)
{
    extern __shared__ uint32_t smw[];
    const uint32_t sb = smem_u32(smw);

    const int which = blockIdx.z;
    const float* __restrict__ bias = (which == 0) ? bq : (which == 1) ? bk : bv;
    const size_t wcoff = (size_t)which * HID * HID * 4;   // byte offset into g_wc

    const int m0 = blockIdx.y * 128;
    const int n0 = blockIdx.x * 128;
    const int m16_0 = blockIdx.y * 8;
    const int n8_0  = blockIdx.x * 16;

    const int tid  = threadIdx.x;
    const int wid  = tid >> 5;
    const int lane = tid & 31;
    const int lr = lane >> 2;
    const int lc = lane & 3;

    auto issue_stage = [&](int stg, int c) {
        const uint32_t ab = sb + (uint32_t)(stg * STG_B);
        const uint32_t bb = ab + A_TILE_B;
        const int k8_0 = c * 2;
        #pragma unroll
        for (int i = 0; i < 2; i++) {           // A: 16 frags x 512B
            const int f = (tid >> 5) + i * 8;
            const size_t src = ((size_t)((m16_0 + (f >> 1)) * 128 + k8_0 + (f & 1))) * 512
                               + (tid & 31) * 16;
            CP_ASYNC16(ab + (uint32_t)(f * 512 + (tid & 31) * 16),
                       (const char*)g_xt + src);
        }
        #pragma unroll
        for (int i = 0; i < 2; i++) {           // B: 32 frags x 256B
            const int ch = tid + i * 256;
            const int frag = ch >> 4, off = ch & 15;
            const size_t src = ((size_t)((n8_0 + (frag >> 1)) * 128 + k8_0 + (frag & 1))) * 256
                               + off * 16 + wcoff;
            CP_ASYNC16(bb + (uint32_t)(frag * 256 + off * 16),
                       (const char*)g_wc + src);
        }
    };

    float acc[4][4][4];
    #pragma unroll
    for (int mt = 0; mt < 4; mt++)
        #pragma unroll
        for (int nt = 0; nt < 4; nt++)
            #pragma unroll
            for (int r = 0; r < 4; r++) acc[mt][nt][r] = 0.0f;

    issue_stage(0, 0);   CP_COMMIT();
    issue_stage(1, 1);   CP_COMMIT();

    int stg = 0;
    for (int c = 0; c < NCH; c++) {
        CP_WAIT1();
        __syncthreads();

        if (c + 2 < NCH)
            issue_stage((stg + 2) % 3, c + 2);
        CP_COMMIT();

        const uint32_t* As = smw + stg * (STG_B / 4);
        const uint32_t* Bs = As + A_TILE_B / 4;

        #pragma unroll
        for (int kk8 = 0; kk8 < 2; kk8++) {
            uint2 bf[4];
            #pragma unroll
            for (int nt = 0; nt < 4; nt++) {
                const int slot = (((wid >> 1) * 4 + nt) * 2 + kk8);
                bf[nt] = *(const uint2*)(Bs + slot * 64 + lane * 2);
            }
            #pragma unroll
            for (int mt = 0; mt < 4; mt++) {
                const int slot = (((wid & 1) * 4 + mt) * 2 + kk8);
                const uint4 av = *(const uint4*)(As + slot * 128 + lane * 4);
                #pragma unroll
                for (int nt = 0; nt < 4; nt++)
                    mma_tf32_16x8x8(acc[mt][nt][0], acc[mt][nt][1],
                                    acc[mt][nt][2], acc[mt][nt][3],
                                    av.x, av.y, av.z, av.w, bf[nt].x, bf[nt].y);
            }
        }
        stg = (stg + 1) % 3;
    }

    // epilogue: bias + permute to [B,H,S,DH].
    // Q -> f32, K -> f32 (rope converts+relayouts), V -> tf32 bits row-major.
    const int wm = (wid & 1) * 64;
    const int wn = (wid >> 1) * 32;
    #pragma unroll
    for (int mt = 0; mt < 4; mt++) {
        #pragma unroll
        for (int nt = 0; nt < 4; nt++) {
            const int dd = wn + nt * 8 + 2 * lc;
            const int h  = (n0 + dd) >> 6;
            const int d  = dd & 63;
            const float bx = bias[n0 + dd];
            const float by = bias[n0 + dd + 1];
            #pragma unroll
            for (int half = 0; half < 2; half++) {
                const int m  = m0 + wm + mt * 16 + half * 8 + lr;
                const int b_ = m >> 10;
                const int s  = m & 1023;
                const float ox = acc[mt][nt][2 * half + 0] + bx;
                const float oy = acc[mt][nt][2 * half + 1] + by;
                const size_t idx = (((size_t)(b_ * NH + h) * SEQ + s) << 6) + d;
                if (which == 0) {
                    *(float2*)&g_q[idx] = make_float2(ox, oy);
                } else if (which == 1) {
                    *(float2*)&g_k[idx] = make_float2(ox, oy);
                } else {
                    uint2 u;
                    u.x = f32_to_tf32(ox);
                    u.y = f32_to_tf32(oy);
                    *(uint2*)&g_v[idx] = u;
                }
            }
        }
    }
}

// ---------------------------------------------------------------------------
// RoPE. Q: f32 in/out (row-major). K: f32 row-major in -> tf32 bits out in
// B-fragment pair-major layout (g_k2):
//   element (s,d): word = ((bh*128 + s/8)*8 + d/8)*64 + ((s&7)*4 + (d&3))*2 + ((d>>2)&1)
// ---------------------------------------------------------------------------
__global__ __launch_bounds__(256) void rope_kernel(const float* __restrict__ freqs)
{
    const int p  = blockIdx.x * 256 + threadIdx.x;
    const int d  = p & 31;
    const int s  = (p >> 5) & 1023;
    const int bh = p >> 15;
    const float f = freqs[s * 64 + d];
    const float sn = sinf(f), c = cosf(f);
    const size_t base = (((size_t)bh << 10) + s) * 64 + d;
    if (blockIdx.y == 0) {
        const float x1 = g_q[base];
        const float x2 = g_q[base + 32];
        g_q[base]      = x1 * c - x2 * sn;
        g_q[base + 32] = x2 * c + x1 * sn;
    } else {
        const float x1 = g_k[base];
        const float x2 = g_k[base + 32];
        const uint32_t v1 = f32_to_tf32(x1 * c - x2 * sn);   // element (s, d)
        const uint32_t v2 = f32_to_tf32(x2 * c + x1 * sn);   // element (s, d+32)
        const size_t slotbase = ((size_t)bh * 128 + (s >> 3)) * 8;
        const int lanepart = (s & 7) * 4 + (d & 3);
        const int halfw    = (d >> 2) & 1;
        g_k2[(slotbase + (d >> 3)    ) * 64 + lanepart * 2 + halfw] = v1;
        g_k2[(slotbase + (d >> 3) + 4) * 64 + lanepart * 2 + halfw] = v2;
    }
}

// ---------------------------------------------------------------------------
// Flash attention. K fragment-major (LDS.64, contiguous 16KB tiles),
// V row-major (unchanged), P via smem (unchanged).
// K double-buffered + V single-buffered cp.async (group order as R9).
// ---------------------------------------------------------------------------
#define KSTR 68
#define VSTR 72
#define KTILE_W 4096                       // 64 frags * 64 words
#define K0_OFF 0
#define K1_OFF KTILE_W
#define V_OFF  (2 * KTILE_W)               // 8192
#define PS_OFF (V_OFF + 64 * VSTR)         // 12800
#define MSK_OFF (PS_OFF + 64 * KSTR)       // 17152
#define ATTN_SMEM ((MSK_OFF + SEQ) * 4)    // 72704 bytes -> 3 CTAs/SM

__global__ __launch_bounds__(128, 3) void attn_mma(
    const float* __restrict__ mask, float* __restrict__ out)
{
    extern __shared__ uint32_t sm[];
    const uint32_t sb = smem_u32(sm);
    float*    Msk = (float*)(sm + MSK_OFF);
    uint32_t* Psb = sm + PS_OFF;

    const int q0 = blockIdx.x * 64;
    const int h  = blockIdx.y;
    const int b  = blockIdx.z;
    const int tid  = threadIdx.x;
    const int w    = tid >> 5;
    const int lane = tid & 31;
    const int lr = lane >> 2;
    const int lc = lane & 3;
    const int bh = b * NH + h;
    const size_t base = (size_t)bh * SEQ * DH;

    for (int i = tid; i < SEQ; i += 128) Msk[i] = mask[b * SEQ + i];

    // stage Q (f32) into Ps region
    {
        float* Pf = (float*)Psb;
        #pragma unroll
        for (int j = 0; j < 8; j++) {
            const int i   = tid + j * 128;
            const int row = i >> 4;
            const int c4  = (i & 15) * 4;
            *(float4*)&Pf[row * KSTR + c4] =
                *(const float4*)&g_q[base + (size_t)(q0 + row) * 64 + c4];
        }
    }
    __syncthreads();

    int nlive = 0;
    while (nlive < 16 && Msk[nlive * 64] >= -1e5f) nlive++;

    float qf[8][4];
    {
        const float* Pf = (const float*)Psb;
        #pragma unroll
        for (int ds = 0; ds < 8; ds++) {
            qf[ds][0] = Pf[(16 * w + lr    ) * KSTR + ds * 8 + lc    ];
            qf[ds][1] = Pf[(16 * w + lr + 8) * KSTR + ds * 8 + lc    ];
            qf[ds][2] = Pf[(16 * w + lr    ) * KSTR + ds * 8 + lc + 4];
            qf[ds][3] = Pf[(16 * w + lr + 8) * KSTR + ds * 8 + lc + 4];
        }
    }
    __syncthreads();

    auto stage_k = [&](int stg, int kc0) {
        const uint32_t kb = sb + (uint32_t)((stg ? K1_OFF : K0_OFF) * 4);
        const char* src = (const char*)g_k2 + (((size_t)bh * 128 + (kc0 >> 3)) * 2048);
        #pragma unroll
        for (int j = 0; j < 8; j++) {
            const int off = (tid + j * 128) * 16;
            CP_ASYNC16(kb + (uint32_t)off, src + off);
        }
    };
    auto stage_v = [&](int kc0) {
        const uint32_t vb = sb + (uint32_t)(V_OFF * 4);
        #pragma unroll
        for (int j = 0; j < 8; j++) {
            const int i   = tid + j * 128;
            const int row = i >> 4;
            const int c4  = (i & 15) * 4;
            CP_ASYNC16(vb + (uint32_t)((row * VSTR + c4) * 4),
                       &g_v[base + (size_t)(kc0 + row) * 64 + c4]);
        }
    };

    float m0 = -1e30f, m1 = -1e30f, l0 = 0.0f, l1 = 0.0f;
    float ctx[8][4];
    #pragma unroll
    for (int nt = 0; nt < 8; nt++)
        #pragma unroll
        for (int r = 0; r < 4; r++) ctx[nt][r] = 0.0f;

    stage_k(0, 0);
    CP_COMMIT();                          // pending: [K0]

    for (int kt = 0; kt < nlive; kt++) {
        const int kc0 = kt * 64;

        stage_v(kc0);
        CP_COMMIT();                      // +[V(kt)]
        if (kt + 1 < nlive)
            stage_k((kt + 1) & 1, kc0 + 64);
        CP_COMMIT();                      // +[K(kt+1)] (possibly empty)

        CP_WAIT2();                       // K(kt) complete
        __syncthreads();

        const uint32_t* Ksb = sm + ((kt & 1) ? K1_OFF : K0_OFF);

        // ---- S = Q K^T (2-term, per-ds split) ----
        float sa[8][4];
        #pragma unroll
        for (int nt = 0; nt < 8; nt++)
            #pragma unroll
            for (int r = 0; r < 4; r++) sa[nt][r] = 0.0f;

        #pragma unroll
        for (int ds = 0; ds < 8; ds++) {
            uint32_t ah[4], al[4];
            #pragma unroll
            for (int r = 0; r < 4; r++) {
                ah[r] = f32_to_tf32(qf[ds][r]);
                al[r] = f32_to_tf32(qf[ds][r] - __uint_as_float(ah[r]));
            }
            #pragma unroll
            for (int nt = 0; nt < 8; nt++) {
                const uint2 kv = *(const uint2*)(Ksb + (nt * 8 + ds) * 64 + lane * 2);
                mma_tf32_16x8x8(sa[nt][0], sa[nt][1], sa[nt][2], sa[nt][3],
                                ah[0], ah[1], ah[2], ah[3], kv.x, kv.y);
                mma_tf32_16x8x8(sa[nt][0], sa[nt][1], sa[nt][2], sa[nt][3],
                                al[0], al[1], al[2], al[3], kv.x, kv.y);
            }
        }

        // ---- scale + mask + online softmax ----
        float mx0 = -1e30f, mx1 = -1e30f;
        #pragma unroll
        for (int nt = 0; nt < 8; nt++) {
            const float mk0 = Msk[kc0 + nt * 8 + 2 * lc    ];
            const float mk1 = Msk[kc0 + nt * 8 + 2 * lc + 1];
            sa[nt][0] = fmaf(sa[nt][0], 0.125f, mk0);
            sa[nt][1] = fmaf(sa[nt][1], 0.125f, mk1);
            sa[nt][2] = fmaf(sa[nt][2], 0.125f, mk0);
            sa[nt][3] = fmaf(sa[nt][3], 0.125f, mk1);
            mx0 = fmaxf(mx0, fmaxf(sa[nt][0], sa[nt][1]));
            mx1 = fmaxf(mx1, fmaxf(sa[nt][2], sa[nt][3]));
        }
        mx0 = fmaxf(mx0, __shfl_xor_sync(0xffffffffu, mx0, 1));
        mx0 = fmaxf(mx0, __shfl_xor_sync(0xffffffffu, mx0, 2));
        mx1 = fmaxf(mx1, __shfl_xor_sync(0xffffffffu, mx1, 1));
        mx1 = fmaxf(mx1, __shfl_xor_sync(0xffffffffu, mx1, 2));

        const float mn0 = fmaxf(m0, mx0);
        const float mn1 = fmaxf(m1, mx1);
        const float cr0 = __expf(m0 - mn0);
        const float cr1 = __expf(m1 - mn1);
        l0 *= cr0; l1 *= cr1;
        m0 = mn0; m1 = mn1;

        float ps0 = 0.0f, ps1 = 0.0f;
        #pragma unroll
        for (int nt = 0; nt < 8; nt++) {
            ctx[nt][0] *= cr0; ctx[nt][1] *= cr0;
            ctx[nt][2] *= cr1; ctx[nt][3] *= cr1;
            sa[nt][0] = __expf(sa[nt][0] - mn0);
            sa[nt][1] = __expf(sa[nt][1] - mn0);
            sa[nt][2] = __expf(sa[nt][2] - mn1);
            sa[nt][3] = __expf(sa[nt][3] - mn1);
            ps0 += sa[nt][0] + sa[nt][1];
            ps1 += sa[nt][2] + sa[nt][3];
        }
        ps0 += __shfl_xor_sync(0xffffffffu, ps0, 1);
        ps0 += __shfl_xor_sync(0xffffffffu, ps0, 2);
        ps1 += __shfl_xor_sync(0xffffffffu, ps1, 1);
        ps1 += __shfl_xor_sync(0xffffffffu, ps1, 2);
        l0 += ps0; l1 += ps1;

        // store P as tf32 bits (warp-private rows)
        #pragma unroll
        for (int nt = 0; nt < 8; nt++) {
            uint2 u0, u1;
            u0.x = f32_to_tf32(sa[nt][0]); u0.y = f32_to_tf32(sa[nt][1]);
            u1.x = f32_to_tf32(sa[nt][2]); u1.y = f32_to_tf32(sa[nt][3]);
            *(uint2*)&Psb[(16 * w + lr    ) * KSTR + nt * 8 + 2 * lc] = u0;
            *(uint2*)&Psb[(16 * w + lr + 8) * KSTR + nt * 8 + 2 * lc] = u1;
        }
        __syncwarp();

        CP_WAIT1();                       // V(kt) complete
        __syncthreads();

        const uint32_t* Vsb = sm + V_OFF;

        // ---- ctx += P V (1-term) ----
        #pragma unroll
        for (int kk = 0; kk < 8; kk++) {
            uint32_t ah[4];
            ah[0] = Psb[(16 * w + lr    ) * KSTR + kk * 8 + lc    ];
            ah[1] = Psb[(16 * w + lr + 8) * KSTR + kk * 8 + lc    ];
            ah[2] = Psb[(16 * w + lr    ) * KSTR + kk * 8 + lc + 4];
            ah[3] = Psb[(16 * w + lr + 8) * KSTR + kk * 8 + lc + 4];
            #pragma unroll
            for (int nt = 0; nt < 8; nt++) {
                const uint32_t bh0 = Vsb[(kk * 8 + lc    ) * VSTR + nt * 8 + lr];
                const uint32_t bh1 = Vsb[(kk * 8 + lc + 4) * VSTR + nt * 8 + lr];
                mma_tf32_16x8x8(ctx[nt][0], ctx[nt][1], ctx[nt][2], ctx[nt][3],
                                ah[0], ah[1], ah[2], ah[3], bh0, bh1);
            }
        }

        __syncthreads();                  // all warps done with V before refill
    }

    const float inv0 = 1.0f / l0;
    const float inv1 = 1.0f / l1;
    const int row0 = q0 + 16 * w + lr;
    const int row1 = row0 + 8;
    #pragma unroll
    for (int nt = 0; nt < 8; nt++) {
        const int d = nt * 8 + 2 * lc;
        *(float2*)&out[(size_t)(b * SEQ + row0) * (NH * DH) + h * 64 + d] =
            make_float2(ctx[nt][0] * inv0, ctx[nt][1] * inv0);
        *(float2*)&out[(size_t)(b * SEQ + row1) * (NH * DH) + h * 64 + d] =
            make_float2(ctx[nt][2] * inv1, ctx[nt][3] * inv1);
    }
}

// ---------------------------------------------------------------------------
extern "C" void kernel_launch(void* const* d_in, const int* in_sizes, int n_in,
                              void* d_out, int out_size)
{
    const float* X     = (const float*)d_in[0];
    const float* mask  = (const float*)d_in[1];
    const float* freqs = (const float*)d_in[2];
    const float* Wq    = (const float*)d_in[3];
    const float* bq    = (const float*)d_in[4];
    const float* Wk    = (const float*)d_in[5];
    const float* bk    = (const float*)d_in[6];
    const float* Wv    = (const float*)d_in[7];
    const float* bv    = (const float*)d_in[8];
    float* out = (float*)d_out;

    cudaFuncSetAttribute(qkv_mma,  cudaFuncAttributeMaxDynamicSharedMemorySize, QKV_SMEM);
    cudaFuncSetAttribute(attn_mma, cudaFuncAttributeMaxDynamicSharedMemorySize, ATTN_SMEM);

    const int total = NA_LANES + 3 * NB_LANES;   // 2,621,440
    precvt<<<total / 256, 256>>>(X, Wq, Wk, Wv);

    dim3 gG(HID / 128, (BATCH * SEQ) / 128, 3);
    qkv_mma<<<gG, 256, QKV_SMEM>>>(bq, bk, bv);

    dim3 gR((BATCH * NH * SEQ * 32) / 256, 2);
    rope_kernel<<<gR, 256>>>(freqs);

    dim3 gA(SEQ / 64, NH, BATCH);
    attn_mma<<<gA, 128, ATTN_SMEM>>>(mask, out);
}

// round 11
// speedup vs baseline: 3.9912x; 1.0154x over previous
#include <cuda_runtime.h>
#include <cuda_bf16.h>
#include <cstdint>

// Problem: B=4, S=1024, HID=1024, H=16, DH=64
// inputs: 0 hidden [4096,1024] f32, 1 mask [4,1024] f32, 2 freqs [1024,64] f32,
//         3 Wq, 4 bq, 5 Wk, 6 bk, 7 Wv, 8 bv
// output: ctx [4,1024,1024] f32

#define BATCH 4
#define SEQ   1024
#define HID   1024
#define NH    16
#define DH    64

// scratch
__device__ float    g_q [BATCH*NH*SEQ*DH];   // f32, row-major [B,H,S,DH]
__device__ float    g_k [BATCH*NH*SEQ*DH];   // f32 row-major (pre-rope)
__device__ uint32_t g_k2[BATCH*NH*SEQ*DH];   // tf32 bits, B-frag pair-major (post-rope)
__device__ uint32_t g_v [BATCH*NH*SEQ*DH];   // tf32 bits, B-frag pair-major
__device__ uint32_t g_xt[BATCH*SEQ*HID];     // X tf32 bits, A-fragment-major
__device__ uint32_t g_wc[3*HID*HID];         // W tf32 bits, B-fragment pair-major

__device__ __forceinline__ uint32_t f32_to_tf32(float x) {
    uint32_t u;
    asm("cvt.rna.tf32.f32 %0, %1;" : "=r"(u) : "f"(x));
    return u;
}

__device__ __forceinline__ void mma_tf32_16x8x8(
    float& c0, float& c1, float& c2, float& c3,
    uint32_t a0, uint32_t a1, uint32_t a2, uint32_t a3,
    uint32_t b0, uint32_t b1)
{
    asm volatile(
        "mma.sync.aligned.m16n8k8.row.col.f32.tf32.tf32.f32 "
        "{%0,%1,%2,%3}, {%4,%5,%6,%7}, {%8,%9}, {%0,%1,%2,%3};"
        : "+f"(c0), "+f"(c1), "+f"(c2), "+f"(c3)
        : "r"(a0), "r"(a1), "r"(a2), "r"(a3), "r"(b0), "r"(b1));
}

__device__ __forceinline__ uint32_t smem_u32(const void* p) {
    uint32_t a;
    asm("{ .reg .u64 t; cvta.to.shared.u64 t, %1; cvt.u32.u64 %0, t; }" : "=r"(a) : "l"(p));
    return a;
}

#define CP_ASYNC16(dst, src) \
    asm volatile("cp.async.cg.shared.global [%0], [%1], 16;" :: "r"(dst), "l"(src) : "memory")
#define CP_COMMIT() asm volatile("cp.async.commit_group;" ::: "memory")
#define CP_WAIT1()  asm volatile("cp.async.wait_group 1;" ::: "memory")
#define CP_WAIT2()  asm volatile("cp.async.wait_group 2;" ::: "memory")

// ---------------------------------------------------------------------------
// precvt: X -> g_xt (A-fragment-major), W -> g_wc (B-fragment pair-major).
// ---------------------------------------------------------------------------
#define NA_LANES (256*128*32)   // 1048576
#define NB_LANES (128*128*32)   // 524288

__global__ __launch_bounds__(256) void precvt(
    const float* __restrict__ X,
    const float* __restrict__ Wq, const float* __restrict__ Wk, const float* __restrict__ Wv)
{
    size_t g = (size_t)blockIdx.x * 256 + threadIdx.x;
    if (g < NA_LANES) {
        const int lane = (int)(g & 31);
        const int fA   = (int)(g >> 5);
        const int m16 = fA >> 7, k8 = fA & 127;
        const int lr = lane >> 2, lc = lane & 3;
        const int r0 = m16 * 16 + lr, c0 = k8 * 8 + lc;
        uint4 t;
        t.x = f32_to_tf32(X[(size_t)r0 * HID + c0]);
        t.y = f32_to_tf32(X[(size_t)(r0 + 8) * HID + c0]);
        t.z = f32_to_tf32(X[(size_t)r0 * HID + c0 + 4]);
        t.w = f32_to_tf32(X[(size_t)(r0 + 8) * HID + c0 + 4]);
        ((uint4*)g_xt)[g] = t;
    } else {
        g -= NA_LANES;
        const int which = (int)(g / NB_LANES);
        const size_t gg = g % NB_LANES;
        const float* __restrict__ W = (which == 0) ? Wq : (which == 1) ? Wk : Wv;
        const int lane = (int)(gg & 31);
        const int fB   = (int)(gg >> 5);
        const int n8 = fB >> 7, k8 = fB & 127;
        const int lr = lane >> 2, lc = lane & 3;
        const int kk = k8 * 8 + lc, nn = n8 * 8 + lr;
        uint2 t;
        t.x = f32_to_tf32(W[(size_t)kk * HID + nn]);
        t.y = f32_to_tf32(W[(size_t)(kk + 4) * HID + nn]);
        ((uint2*)g_wc)[(size_t)which * NB_LANES + gg] = t;
    }
}

// ---------------------------------------------------------------------------
// QKV projection: fragment-major operands, cp.async 3-stage pipeline.
// CTA 128x128, BK=16, 8 warps (2m x 4n, warp 64x32).
// V epilogue writes B-fragment pair-major tf32 bits directly.
// ---------------------------------------------------------------------------
#define NCH 64
#define A_TILE_B 8192
#define B_TILE_B 8192
#define STG_B (A_TILE_B + B_TILE_B)
#define QKV_SMEM (3 * STG_B)

__global__ __launch_bounds__(256, 2) void qkv_mma(
    const float* __restrict__ bq, const float* __restrict__ bk, const float* __restrict__ bv)
{
    extern __shared__ uint32_t smw[];
    const uint32_t sb = smem_u32(smw);

    const int which = blockIdx.z;
    const float* __restrict__ bias = (which == 0) ? bq : (which == 1) ? bk : bv;
    const size_t wcoff = (size_t)which * HID * HID * 4;

    const int m0 = blockIdx.y * 128;
    const int n0 = blockIdx.x * 128;
    const int m16_0 = blockIdx.y * 8;
    const int n8_0  = blockIdx.x * 16;

    const int tid  = threadIdx.x;
    const int wid  = tid >> 5;
    const int lane = tid & 31;
    const int lr = lane >> 2;
    const int lc = lane & 3;

    auto issue_stage = [&](int stg, int c) {
        const uint32_t ab = sb + (uint32_t)(stg * STG_B);
        const uint32_t bb = ab + A_TILE_B;
        const int k8_0 = c * 2;
        #pragma unroll
        for (int i = 0; i < 2; i++) {
            const int f = (tid >> 5) + i * 8;
            const size_t src = ((size_t)((m16_0 + (f >> 1)) * 128 + k8_0 + (f & 1))) * 512
                               + (tid & 31) * 16;
            CP_ASYNC16(ab + (uint32_t)(f * 512 + (tid & 31) * 16),
                       (const char*)g_xt + src);
        }
        #pragma unroll
        for (int i = 0; i < 2; i++) {
            const int ch = tid + i * 256;
            const int frag = ch >> 4, off = ch & 15;
            const size_t src = ((size_t)((n8_0 + (frag >> 1)) * 128 + k8_0 + (frag & 1))) * 256
                               + off * 16 + wcoff;
            CP_ASYNC16(bb + (uint32_t)(frag * 256 + off * 16),
                       (const char*)g_wc + src);
        }
    };

    float acc[4][4][4];
    #pragma unroll
    for (int mt = 0; mt < 4; mt++)
        #pragma unroll
        for (int nt = 0; nt < 4; nt++)
            #pragma unroll
            for (int r = 0; r < 4; r++) acc[mt][nt][r] = 0.0f;

    issue_stage(0, 0);   CP_COMMIT();
    issue_stage(1, 1);   CP_COMMIT();

    int stg = 0;
    for (int c = 0; c < NCH; c++) {
        CP_WAIT1();
        __syncthreads();

        if (c + 2 < NCH)
            issue_stage((stg + 2) % 3, c + 2);
        CP_COMMIT();

        const uint32_t* As = smw + stg * (STG_B / 4);
        const uint32_t* Bs = As + A_TILE_B / 4;

        #pragma unroll
        for (int kk8 = 0; kk8 < 2; kk8++) {
            uint2 bf[4];
            #pragma unroll
            for (int nt = 0; nt < 4; nt++) {
                const int slot = (((wid >> 1) * 4 + nt) * 2 + kk8);
                bf[nt] = *(const uint2*)(Bs + slot * 64 + lane * 2);
            }
            #pragma unroll
            for (int mt = 0; mt < 4; mt++) {
                const int slot = (((wid & 1) * 4 + mt) * 2 + kk8);
                const uint4 av = *(const uint4*)(As + slot * 128 + lane * 4);
                #pragma unroll
                for (int nt = 0; nt < 4; nt++)
                    mma_tf32_16x8x8(acc[mt][nt][0], acc[mt][nt][1],
                                    acc[mt][nt][2], acc[mt][nt][3],
                                    av.x, av.y, av.z, av.w, bf[nt].x, bf[nt].y);
            }
        }
        stg = (stg + 1) % 3;
    }

    // epilogue: bias + permute. Q -> f32, K -> f32 (rope relayouts),
    // V -> tf32 bits in B-fragment pair-major layout.
    const int wm = (wid & 1) * 64;
    const int wn = (wid >> 1) * 32;
    #pragma unroll
    for (int mt = 0; mt < 4; mt++) {
        #pragma unroll
        for (int nt = 0; nt < 4; nt++) {
            const int dd = wn + nt * 8 + 2 * lc;
            const int h  = (n0 + dd) >> 6;
            const int d  = dd & 63;
            const float bx = bias[n0 + dd];
            const float by = bias[n0 + dd + 1];
            #pragma unroll
            for (int half = 0; half < 2; half++) {
                const int m  = m0 + wm + mt * 16 + half * 8 + lr;
                const int b_ = m >> 10;
                const int s  = m & 1023;
                const float ox = acc[mt][nt][2 * half + 0] + bx;
                const float oy = acc[mt][nt][2 * half + 1] + by;
                if (which == 0) {
                    const size_t idx = (((size_t)(b_ * NH + h) * SEQ + s) << 6) + d;
                    *(float2*)&g_q[idx] = make_float2(ox, oy);
                } else if (which == 1) {
                    const size_t idx = (((size_t)(b_ * NH + h) * SEQ + s) << 6) + d;
                    *(float2*)&g_k[idx] = make_float2(ox, oy);
                } else {
                    // V frag-major: element (s,d) -> frag (s>>3, d>>3),
                    // word = ((d&7)*4 + (s&3))*2 + ((s>>2)&1)
                    const size_t fragbase =
                        (((size_t)(b_ * NH + h) * 128 + (s >> 3)) * 8 + (d >> 3)) * 64;
                    const int hw = (s >> 2) & 1;
                    g_v[fragbase + (((d & 7)    ) * 4 + (s & 3)) * 2 + hw] = f32_to_tf32(ox);
                    g_v[fragbase + (((d & 7) + 1) * 4 + (s & 3)) * 2 + hw] = f32_to_tf32(oy);
                }
            }
        }
    }
}

// ---------------------------------------------------------------------------
// RoPE. Q: f32 in/out. K: f32 in -> tf32 bits out, B-frag pair-major (g_k2).
// ---------------------------------------------------------------------------
__global__ __launch_bounds__(256) void rope_kernel(const float* __restrict__ freqs)
{
    const int p  = blockIdx.x * 256 + threadIdx.x;
    const int d  = p & 31;
    const int s  = (p >> 5) & 1023;
    const int bh = p >> 15;
    const float f = freqs[s * 64 + d];
    const float sn = sinf(f), c = cosf(f);
    const size_t base = (((size_t)bh << 10) + s) * 64 + d;
    if (blockIdx.y == 0) {
        const float x1 = g_q[base];
        const float x2 = g_q[base + 32];
        g_q[base]      = x1 * c - x2 * sn;
        g_q[base + 32] = x2 * c + x1 * sn;
    } else {
        const float x1 = g_k[base];
        const float x2 = g_k[base + 32];
        const uint32_t v1 = f32_to_tf32(x1 * c - x2 * sn);
        const uint32_t v2 = f32_to_tf32(x2 * c + x1 * sn);
        const size_t slotbase = ((size_t)bh * 128 + (s >> 3)) * 8;
        const int lanepart = (s & 7) * 4 + (d & 3);
        const int halfw    = (d >> 2) & 1;
        g_k2[(slotbase + (d >> 3)    ) * 64 + lanepart * 2 + halfw] = v1;
        g_k2[(slotbase + (d >> 3) + 4) * 64 + lanepart * 2 + halfw] = v2;
    }
}

// ---------------------------------------------------------------------------
// Flash attention. K AND V fragment-major (LDS.64, contiguous 16KB tiles).
// K double-buffered + V single-buffered cp.async.
// ---------------------------------------------------------------------------
#define KSTR 68
#define KTILE_W 4096                       // 64 frags * 64 words
#define K0_OFF 0
#define K1_OFF KTILE_W
#define V_OFF  (2 * KTILE_W)               // 8192
#define PS_OFF (V_OFF + KTILE_W)           // 12288
#define MSK_OFF (PS_OFF + 64 * KSTR)       // 16640
#define ATTN_SMEM ((MSK_OFF + SEQ) * 4)    // 70656 bytes -> 3 CTAs/SM

__global__ __launch_bounds__(128, 3) void attn_mma(
    const float* __restrict__ mask, float* __restrict__ out)
{
    extern __shared__ uint32_t sm[];
    const uint32_t sb = smem_u32(sm);
    float*    Msk = (float*)(sm + MSK_OFF);
    uint32_t* Psb = sm + PS_OFF;

    const int q0 = blockIdx.x * 64;
    const int h  = blockIdx.y;
    const int b  = blockIdx.z;
    const int tid  = threadIdx.x;
    const int w    = tid >> 5;
    const int lane = tid & 31;
    const int lr = lane >> 2;
    const int lc = lane & 3;
    const int bh = b * NH + h;
    const size_t base = (size_t)bh * SEQ * DH;

    for (int i = tid; i < SEQ; i += 128) Msk[i] = mask[b * SEQ + i];

    // stage Q (f32) into Ps region
    {
        float* Pf = (float*)Psb;
        #pragma unroll
        for (int j = 0; j < 8; j++) {
            const int i   = tid + j * 128;
            const int row = i >> 4;
            const int c4  = (i & 15) * 4;
            *(float4*)&Pf[row * KSTR + c4] =
                *(const float4*)&g_q[base + (size_t)(q0 + row) * 64 + c4];
        }
    }
    __syncthreads();

    int nlive = 0;
    while (nlive < 16 && Msk[nlive * 64] >= -1e5f) nlive++;

    float qf[8][4];
    {
        const float* Pf = (const float*)Psb;
        #pragma unroll
        for (int ds = 0; ds < 8; ds++) {
            qf[ds][0] = Pf[(16 * w + lr    ) * KSTR + ds * 8 + lc    ];
            qf[ds][1] = Pf[(16 * w + lr + 8) * KSTR + ds * 8 + lc    ];
            qf[ds][2] = Pf[(16 * w + lr    ) * KSTR + ds * 8 + lc + 4];
            qf[ds][3] = Pf[(16 * w + lr + 8) * KSTR + ds * 8 + lc + 4];
        }
    }
    __syncthreads();

    auto stage_k = [&](int stg, int kc0) {
        const uint32_t kb = sb + (uint32_t)((stg ? K1_OFF : K0_OFF) * 4);
        const char* src = (const char*)g_k2 + (((size_t)bh * 128 + (kc0 >> 3)) * 2048);
        #pragma unroll
        for (int j = 0; j < 8; j++) {
            const int off = (tid + j * 128) * 16;
            CP_ASYNC16(kb + (uint32_t)off, src + off);
        }
    };
    auto stage_v = [&](int kc0) {
        const uint32_t vb = sb + (uint32_t)(V_OFF * 4);
        const char* src = (const char*)g_v + (((size_t)bh * 128 + (kc0 >> 3)) * 2048);
        #pragma unroll
        for (int j = 0; j < 8; j++) {
            const int off = (tid + j * 128) * 16;
            CP_ASYNC16(vb + (uint32_t)off, src + off);
        }
    };

    float m0 = -1e30f, m1 = -1e30f, l0 = 0.0f, l1 = 0.0f;
    float ctx[8][4];
    #pragma unroll
    for (int nt = 0; nt < 8; nt++)
        #pragma unroll
        for (int r = 0; r < 4; r++) ctx[nt][r] = 0.0f;

    stage_k(0, 0);
    CP_COMMIT();                          // pending: [K0]

    for (int kt = 0; kt < nlive; kt++) {
        const int kc0 = kt * 64;

        stage_v(kc0);
        CP_COMMIT();                      // +[V(kt)]
        if (kt + 1 < nlive)
            stage_k((kt + 1) & 1, kc0 + 64);
        CP_COMMIT();                      // +[K(kt+1)] (possibly empty)

        CP_WAIT2();                       // K(kt) complete
        __syncthreads();

        const uint32_t* Ksb = sm + ((kt & 1) ? K1_OFF : K0_OFF);

        // ---- S = Q K^T (2-term, per-ds split) ----
        float sa[8][4];
        #pragma unroll
        for (int nt = 0; nt < 8; nt++)
            #pragma unroll
            for (int r = 0; r < 4; r++) sa[nt][r] = 0.0f;

        #pragma unroll
        for (int ds = 0; ds < 8; ds++) {
            uint32_t ah[4], al[4];
            #pragma unroll
            for (int r = 0; r < 4; r++) {
                ah[r] = f32_to_tf32(qf[ds][r]);
                al[r] = f32_to_tf32(qf[ds][r] - __uint_as_float(ah[r]));
            }
            #pragma unroll
            for (int nt = 0; nt < 8; nt++) {
                const uint2 kv = *(const uint2*)(Ksb + (nt * 8 + ds) * 64 + lane * 2);
                mma_tf32_16x8x8(sa[nt][0], sa[nt][1], sa[nt][2], sa[nt][3],
                                ah[0], ah[1], ah[2], ah[3], kv.x, kv.y);
                mma_tf32_16x8x8(sa[nt][0], sa[nt][1], sa[nt][2], sa[nt][3],
                                al[0], al[1], al[2], al[3], kv.x, kv.y);
            }
        }

        // ---- scale + mask + online softmax ----
        float mx0 = -1e30f, mx1 = -1e30f;
        #pragma unroll
        for (int nt = 0; nt < 8; nt++) {
            const float mk0 = Msk[kc0 + nt * 8 + 2 * lc    ];
            const float mk1 = Msk[kc0 + nt * 8 + 2 * lc + 1];
            sa[nt][0] = fmaf(sa[nt][0], 0.125f, mk0);
            sa[nt][1] = fmaf(sa[nt][1], 0.125f, mk1);
            sa[nt][2] = fmaf(sa[nt][2], 0.125f, mk0);
            sa[nt][3] = fmaf(sa[nt][3], 0.125f, mk1);
            mx0 = fmaxf(mx0, fmaxf(sa[nt][0], sa[nt][1]));
            mx1 = fmaxf(mx1, fmaxf(sa[nt][2], sa[nt][3]));
        }
        mx0 = fmaxf(mx0, __shfl_xor_sync(0xffffffffu, mx0, 1));
        mx0 = fmaxf(mx0, __shfl_xor_sync(0xffffffffu, mx0, 2));
        mx1 = fmaxf(mx1, __shfl_xor_sync(0xffffffffu, mx1, 1));
        mx1 = fmaxf(mx1, __shfl_xor_sync(0xffffffffu, mx1, 2));

        const float mn0 = fmaxf(m0, mx0);
        const float mn1 = fmaxf(m1, mx1);
        const float cr0 = __expf(m0 - mn0);
        const float cr1 = __expf(m1 - mn1);
        l0 *= cr0; l1 *= cr1;
        m0 = mn0; m1 = mn1;

        float ps0 = 0.0f, ps1 = 0.0f;
        #pragma unroll
        for (int nt = 0; nt < 8; nt++) {
            ctx[nt][0] *= cr0; ctx[nt][1] *= cr0;
            ctx[nt][2] *= cr1; ctx[nt][3] *= cr1;
            sa[nt][0] = __expf(sa[nt][0] - mn0);
            sa[nt][1] = __expf(sa[nt][1] - mn0);
            sa[nt][2] = __expf(sa[nt][2] - mn1);
            sa[nt][3] = __expf(sa[nt][3] - mn1);
            ps0 += sa[nt][0] + sa[nt][1];
            ps1 += sa[nt][2] + sa[nt][3];
        }
        ps0 += __shfl_xor_sync(0xffffffffu, ps0, 1);
        ps0 += __shfl_xor_sync(0xffffffffu, ps0, 2);
        ps1 += __shfl_xor_sync(0xffffffffu, ps1, 1);
        ps1 += __shfl_xor_sync(0xffffffffu, ps1, 2);
        l0 += ps0; l1 += ps1;

        // store P as tf32 bits (warp-private rows)
        #pragma unroll
        for (int nt = 0; nt < 8; nt++) {
            uint2 u0, u1;
            u0.x = f32_to_tf32(sa[nt][0]); u0.y = f32_to_tf32(sa[nt][1]);
            u1.x = f32_to_tf32(sa[nt][2]); u1.y = f32_to_tf32(sa[nt][3]);
            *(uint2*)&Psb[(16 * w + lr    ) * KSTR + nt * 8 + 2 * lc] = u0;
            *(uint2*)&Psb[(16 * w + lr + 8) * KSTR + nt * 8 + 2 * lc] = u1;
        }
        __syncwarp();

        CP_WAIT1();                       // V(kt) complete
        __syncthreads();

        const uint32_t* Vsb = sm + V_OFF;

        // ---- ctx += P V (1-term, V fragment-major LDS.64) ----
        #pragma unroll
        for (int kk = 0; kk < 8; kk++) {
            uint32_t ah[4];
            ah[0] = Psb[(16 * w + lr    ) * KSTR + kk * 8 + lc    ];
            ah[1] = Psb[(16 * w + lr + 8) * KSTR + kk * 8 + lc    ];
            ah[2] = Psb[(16 * w + lr    ) * KSTR + kk * 8 + lc + 4];
            ah[3] = Psb[(16 * w + lr + 8) * KSTR + kk * 8 + lc + 4];
            #pragma unroll
            for (int nt = 0; nt < 8; nt++) {
                const uint2 vv = *(const uint2*)(Vsb + (kk * 8 + nt) * 64 + lane * 2);
                mma_tf32_16x8x8(ctx[nt][0], ctx[nt][1], ctx[nt][2], ctx[nt][3],
                                ah[0], ah[1], ah[2], ah[3], vv.x, vv.y);
            }
        }

        __syncthreads();                  // all warps done with V before refill
    }

    const float inv0 = 1.0f / l0;
    const float inv1 = 1.0f / l1;
    const int row0 = q0 + 16 * w + lr;
    const int row1 = row0 + 8;
    #pragma unroll
    for (int nt = 0; nt < 8; nt++) {
        const int d = nt * 8 + 2 * lc;
        *(float2*)&out[(size_t)(b * SEQ + row0) * (NH * DH) + h * 64 + d] =
            make_float2(ctx[nt][0] * inv0, ctx[nt][1] * inv0);
        *(float2*)&out[(size_t)(b * SEQ + row1) * (NH * DH) + h * 64 + d] =
            make_float2(ctx[nt][2] * inv1, ctx[nt][3] * inv1);
    }
}

// ---------------------------------------------------------------------------
extern "C" void kernel_launch(void* const* d_in, const int* in_sizes, int n_in,
                              void* d_out, int out_size)
{
    const float* X     = (const float*)d_in[0];
    const float* mask  = (const float*)d_in[1];
    const float* freqs = (const float*)d_in[2];
    const float* Wq    = (const float*)d_in[3];
    const float* bq    = (const float*)d_in[4];
    const float* Wk    = (const float*)d_in[5];
    const float* bk    = (const float*)d_in[6];
    const float* Wv    = (const float*)d_in[7];
    const float* bv    = (const float*)d_in[8];
    float* out = (float*)d_out;

    cudaFuncSetAttribute(qkv_mma,  cudaFuncAttributeMaxDynamicSharedMemorySize, QKV_SMEM);
    cudaFuncSetAttribute(attn_mma, cudaFuncAttributeMaxDynamicSharedMemorySize, ATTN_SMEM);

    const int total = NA_LANES + 3 * NB_LANES;
    precvt<<<total / 256, 256>>>(X, Wq, Wk, Wv);

    dim3 gG(HID / 128, (BATCH * SEQ) / 128, 3);
    qkv_mma<<<gG, 256, QKV_SMEM>>>(bq, bk, bv);

    dim3 gR((BATCH * NH * SEQ * 32) / 256, 2);
    rope_kernel<<<gR, 256>>>(freqs);

    dim3 gA(SEQ / 64, NH, BATCH);
    attn_mma<<<gA, 128, ATTN_SMEM>>>(mask, out);
}

// round 12
// speedup vs baseline: 4.3845x; 1.0986x over previous
#include <cuda_runtime.h>
#include <cuda_bf16.h>
#include <cstdint>

// Problem: B=4, S=1024, HID=1024, H=16, DH=64
// inputs: 0 hidden [4096,1024] f32, 1 mask [4,1024] f32, 2 freqs [1024,64] f32,
//         3 Wq, 4 bq, 5 Wk, 6 bk, 7 Wv, 8 bv
// output: ctx [4,1024,1024] f32

#define BATCH 4
#define SEQ   1024
#define HID   1024
#define NH    16
#define DH    64

// scratch
__device__ float    g_q [BATCH*NH*SEQ*DH];   // f32 row-major (pre-rope)
__device__ uint32_t g_q2[BATCH*NH*SEQ*DH];   // tf32 bits, A-frag-major (post-rope)
__device__ float    g_k [BATCH*NH*SEQ*DH];   // f32 row-major (pre-rope)
__device__ uint32_t g_k2[BATCH*NH*SEQ*DH];   // tf32 bits, B-frag pair-major (post-rope)
__device__ uint32_t g_v [BATCH*NH*SEQ*DH];   // tf32 bits, B-frag pair-major
__device__ uint32_t g_xt[BATCH*SEQ*HID];     // X tf32 bits, A-fragment-major
__device__ uint32_t g_wc[3*HID*HID];         // W tf32 bits, B-fragment pair-major

__device__ __forceinline__ uint32_t f32_to_tf32(float x) {
    uint32_t u;
    asm("cvt.rna.tf32.f32 %0, %1;" : "=r"(u) : "f"(x));
    return u;
}

__device__ __forceinline__ void mma_tf32_16x8x8(
    float& c0, float& c1, float& c2, float& c3,
    uint32_t a0, uint32_t a1, uint32_t a2, uint32_t a3,
    uint32_t b0, uint32_t b1)
{
    asm volatile(
        "mma.sync.aligned.m16n8k8.row.col.f32.tf32.tf32.f32 "
        "{%0,%1,%2,%3}, {%4,%5,%6,%7}, {%8,%9}, {%0,%1,%2,%3};"
        : "+f"(c0), "+f"(c1), "+f"(c2), "+f"(c3)
        : "r"(a0), "r"(a1), "r"(a2), "r"(a3), "r"(b0), "r"(b1));
}

__device__ __forceinline__ uint32_t smem_u32(const void* p) {
    uint32_t a;
    asm("{ .reg .u64 t; cvta.to.shared.u64 t, %1; cvt.u32.u64 %0, t; }" : "=r"(a) : "l"(p));
    return a;
}

#define CP_ASYNC16(dst, src) \
    asm volatile("cp.async.cg.shared.global [%0], [%1], 16;" :: "r"(dst), "l"(src) : "memory")
#define CP_COMMIT() asm volatile("cp.async.commit_group;" ::: "memory")
#define CP_WAIT1()  asm volatile("cp.async.wait_group 1;" ::: "memory")
#define CP_WAIT2()  asm volatile("cp.async.wait_group 2;" ::: "memory")

// ---------------------------------------------------------------------------
// precvt: X -> g_xt (A-fragment-major), W -> g_wc (B-fragment pair-major).
// ---------------------------------------------------------------------------
#define NA_LANES (256*128*32)   // 1048576
#define NB_LANES (128*128*32)   // 524288

__global__ __launch_bounds__(256) void precvt(
    const float* __restrict__ X,
    const float* __restrict__ Wq, const float* __restrict__ Wk, const float* __restrict__ Wv)
{
    size_t g = (size_t)blockIdx.x * 256 + threadIdx.x;
    if (g < NA_LANES) {
        const int lane = (int)(g & 31);
        const int fA   = (int)(g >> 5);
        const int m16 = fA >> 7, k8 = fA & 127;
        const int lr = lane >> 2, lc = lane & 3;
        const int r0 = m16 * 16 + lr, c0 = k8 * 8 + lc;
        uint4 t;
        t.x = f32_to_tf32(X[(size_t)r0 * HID + c0]);
        t.y = f32_to_tf32(X[(size_t)(r0 + 8) * HID + c0]);
        t.z = f32_to_tf32(X[(size_t)r0 * HID + c0 + 4]);
        t.w = f32_to_tf32(X[(size_t)(r0 + 8) * HID + c0 + 4]);
        ((uint4*)g_xt)[g] = t;
    } else {
        g -= NA_LANES;
        const int which = (int)(g / NB_LANES);
        const size_t gg = g % NB_LANES;
        const float* __restrict__ W = (which == 0) ? Wq : (which == 1) ? Wk : Wv;
        const int lane = (int)(gg & 31);
        const int fB   = (int)(gg >> 5);
        const int n8 = fB >> 7, k8 = fB & 127;
        const int lr = lane >> 2, lc = lane & 3;
        const int kk = k8 * 8 + lc, nn = n8 * 8 + lr;
        uint2 t;
        t.x = f32_to_tf32(W[(size_t)kk * HID + nn]);
        t.y = f32_to_tf32(W[(size_t)(kk + 4) * HID + nn]);
        ((uint2*)g_wc)[(size_t)which * NB_LANES + gg] = t;
    }
}

// ---------------------------------------------------------------------------
// QKV projection: fragment-major operands, cp.async 3-stage pipeline.
// CTA 128x128, BK=32 (halved sync count), 8 warps (2m x 4n, warp 64x32).
// ---------------------------------------------------------------------------
#define NCH 32                  // 1024/32 chunks
#define A_TILE_B 16384          // 32 frags * 512B
#define B_TILE_B 16384          // 64 frags * 256B
#define STG_B (A_TILE_B + B_TILE_B)
#define QKV_SMEM (3 * STG_B)    // 98304

__global__ __launch_bounds__(256, 2) void qkv_mma(
    const float* __restrict__ bq, const float* __restrict__ bk, const float* __restrict__ bv)
{
    extern __shared__ uint32_t smw[];
    const uint32_t sb = smem_u32(smw);

    const int which = blockIdx.z;
    const float* __restrict__ bias = (which == 0) ? bq : (which == 1) ? bk : bv;
    const size_t wcoff = (size_t)which * HID * HID * 4;

    const int m0 = blockIdx.y * 128;
    const int n0 = blockIdx.x * 128;
    const int m16_0 = blockIdx.y * 8;
    const int n8_0  = blockIdx.x * 16;

    const int tid  = threadIdx.x;
    const int wid  = tid >> 5;
    const int lane = tid & 31;
    const int lr = lane >> 2;
    const int lc = lane & 3;

    auto issue_stage = [&](int stg, int c) {
        const uint32_t ab = sb + (uint32_t)(stg * STG_B);
        const uint32_t bb = ab + A_TILE_B;
        const int k8_0 = c * 4;
        #pragma unroll
        for (int i = 0; i < 4; i++) {         // A: 32 frags x 512B
            const int f = (tid >> 5) + i * 8;
            const size_t src = ((size_t)((m16_0 + (f >> 2)) * 128 + k8_0 + (f & 3))) * 512
                               + (tid & 31) * 16;
            CP_ASYNC16(ab + (uint32_t)(f * 512 + (tid & 31) * 16),
                       (const char*)g_xt + src);
        }
        #pragma unroll
        for (int i = 0; i < 4; i++) {         // B: 64 frags x 256B
            const int ch = tid + i * 256;
            const int frag = ch >> 4, off = ch & 15;
            const size_t src = ((size_t)((n8_0 + (frag >> 2)) * 128 + k8_0 + (frag & 3))) * 256
                               + off * 16 + wcoff;
            CP_ASYNC16(bb + (uint32_t)(frag * 256 + off * 16),
                       (const char*)g_wc + src);
        }
    };

    float acc[4][4][4];
    #pragma unroll
    for (int mt = 0; mt < 4; mt++)
        #pragma unroll
        for (int nt = 0; nt < 4; nt++)
            #pragma unroll
            for (int r = 0; r < 4; r++) acc[mt][nt][r] = 0.0f;

    issue_stage(0, 0);   CP_COMMIT();
    issue_stage(1, 1);   CP_COMMIT();

    int stg = 0;
    for (int c = 0; c < NCH; c++) {
        CP_WAIT1();
        __syncthreads();

        if (c + 2 < NCH)
            issue_stage((stg + 2) % 3, c + 2);
        CP_COMMIT();

        const uint32_t* As = smw + stg * (STG_B / 4);
        const uint32_t* Bs = As + A_TILE_B / 4;

        #pragma unroll
        for (int kk8 = 0; kk8 < 4; kk8++) {
            uint2 bf[4];
            #pragma unroll
            for (int nt = 0; nt < 4; nt++) {
                const int slot = (((wid >> 1) * 4 + nt) * 4 + kk8);
                bf[nt] = *(const uint2*)(Bs + slot * 64 + lane * 2);
            }
            #pragma unroll
            for (int mt = 0; mt < 4; mt++) {
                const int slot = (((wid & 1) * 4 + mt) * 4 + kk8);
                const uint4 av = *(const uint4*)(As + slot * 128 + lane * 4);
                #pragma unroll
                for (int nt = 0; nt < 4; nt++)
                    mma_tf32_16x8x8(acc[mt][nt][0], acc[mt][nt][1],
                                    acc[mt][nt][2], acc[mt][nt][3],
                                    av.x, av.y, av.z, av.w, bf[nt].x, bf[nt].y);
            }
        }
        stg = (stg + 1) % 3;
    }

    // epilogue: bias + permute. Q,K -> f32 row-major (rope relayouts),
    // V -> tf32 bits in B-fragment pair-major layout.
    const int wm = (wid & 1) * 64;
    const int wn = (wid >> 1) * 32;
    #pragma unroll
    for (int mt = 0; mt < 4; mt++) {
        #pragma unroll
        for (int nt = 0; nt < 4; nt++) {
            const int dd = wn + nt * 8 + 2 * lc;
            const int h  = (n0 + dd) >> 6;
            const int d  = dd & 63;
            const float bx = bias[n0 + dd];
            const float by = bias[n0 + dd + 1];
            #pragma unroll
            for (int half = 0; half < 2; half++) {
                const int m  = m0 + wm + mt * 16 + half * 8 + lr;
                const int b_ = m >> 10;
                const int s  = m & 1023;
                const float ox = acc[mt][nt][2 * half + 0] + bx;
                const float oy = acc[mt][nt][2 * half + 1] + by;
                if (which == 0) {
                    const size_t idx = (((size_t)(b_ * NH + h) * SEQ + s) << 6) + d;
                    *(float2*)&g_q[idx] = make_float2(ox, oy);
                } else if (which == 1) {
                    const size_t idx = (((size_t)(b_ * NH + h) * SEQ + s) << 6) + d;
                    *(float2*)&g_k[idx] = make_float2(ox, oy);
                } else {
                    // V frag-major: element (s,d) -> frag (s>>3, d>>3),
                    // word = ((d&7)*4 + (s&3))*2 + ((s>>2)&1)
                    const size_t fragbase =
                        (((size_t)(b_ * NH + h) * 128 + (s >> 3)) * 8 + (d >> 3)) * 64;
                    const int hw = (s >> 2) & 1;
                    g_v[fragbase + (((d & 7)    ) * 4 + (s & 3)) * 2 + hw] = f32_to_tf32(ox);
                    g_v[fragbase + (((d & 7) + 1) * 4 + (s & 3)) * 2 + hw] = f32_to_tf32(oy);
                }
            }
        }
    }
}

// ---------------------------------------------------------------------------
// RoPE. Q: f32 in -> tf32 bits out, A-frag-major (g_q2):
//   element (s,d): frag = (bh*64 + s/16)*8 + d/8,
//   word = frag*128 + ((s&7)*4 + (d&3))*4 + ((s>>3)&1) + 2*((d>>2)&1)
// K: f32 in -> tf32 bits out, B-frag pair-major (g_k2).
// ---------------------------------------------------------------------------
__global__ __launch_bounds__(256) void rope_kernel(const float* __restrict__ freqs)
{
    const int p  = blockIdx.x * 256 + threadIdx.x;
    const int d  = p & 31;
    const int s  = (p >> 5) & 1023;
    const int bh = p >> 15;
    const float f = freqs[s * 64 + d];
    const float sn = sinf(f), c = cosf(f);
    const size_t base = (((size_t)bh << 10) + s) * 64 + d;
    if (blockIdx.y == 0) {
        const float x1 = g_q[base];
        const float x2 = g_q[base + 32];
        const uint32_t v1 = f32_to_tf32(x1 * c - x2 * sn);   // (s, d)
        const uint32_t v2 = f32_to_tf32(x2 * c + x1 * sn);   // (s, d+32)
        const size_t fb = ((size_t)bh * 64 + (s >> 4)) * 8;
        const int lanew = ((s & 7) * 4 + (d & 3)) * 4 + ((s >> 3) & 1) + 2 * ((d >> 2) & 1);
        g_q2[(fb + (d >> 3)    ) * 128 + lanew] = v1;
        g_q2[(fb + (d >> 3) + 4) * 128 + lanew] = v2;
    } else {
        const float x1 = g_k[base];
        const float x2 = g_k[base + 32];
        const uint32_t v1 = f32_to_tf32(x1 * c - x2 * sn);
        const uint32_t v2 = f32_to_tf32(x2 * c + x1 * sn);
        const size_t slotbase = ((size_t)bh * 128 + (s >> 3)) * 8;
        const int lanepart = (s & 7) * 4 + (d & 3);
        const int halfw    = (d >> 2) & 1;
        g_k2[(slotbase + (d >> 3)    ) * 64 + lanepart * 2 + halfw] = v1;
        g_k2[(slotbase + (d >> 3) + 4) * 64 + lanepart * 2 + halfw] = v2;
    }
}

// ---------------------------------------------------------------------------
// Flash attention, all 1-term tf32. Q fragments loaded once via LDG.128
// (A-frag-major g_q2). K/V fragment-major smem tiles (LDS.64).
// K double-buffered + V single-buffered cp.async.
// ---------------------------------------------------------------------------
#define KSTR 68
#define KTILE_W 4096                       // 64 frags * 64 words
#define K0_OFF 0
#define K1_OFF KTILE_W
#define V_OFF  (2 * KTILE_W)               // 8192
#define PS_OFF (V_OFF + KTILE_W)           // 12288
#define MSK_OFF (PS_OFF + 64 * KSTR)       // 16640
#define ATTN_SMEM ((MSK_OFF + SEQ) * 4)    // 70656 bytes -> 3 CTAs/SM

__global__ __launch_bounds__(128, 3) void attn_mma(
    const float* __restrict__ mask, float* __restrict__ out)
{
    extern __shared__ uint32_t sm[];
    const uint32_t sb = smem_u32(sm);
    float*    Msk = (float*)(sm + MSK_OFF);
    uint32_t* Psb = sm + PS_OFF;

    const int q0 = blockIdx.x * 64;
    const int h  = blockIdx.y;
    const int b  = blockIdx.z;
    const int tid  = threadIdx.x;
    const int w    = tid >> 5;
    const int lane = tid & 31;
    const int lr = lane >> 2;
    const int lc = lane & 3;
    const int bh = b * NH + h;

    for (int i = tid; i < SEQ; i += 128) Msk[i] = mask[b * SEQ + i];

    // Q fragments: one LDG.128 per ds, loaded once (A-frag-major)
    uint32_t qh[8][4];
    {
        const uint32_t* qsrc = g_q2 + ((size_t)bh * 64 + (q0 >> 4) + w) * 1024;
        #pragma unroll
        for (int ds = 0; ds < 8; ds++) {
            const uint4 v = *(const uint4*)(qsrc + ds * 128 + lane * 4);
            qh[ds][0] = v.x; qh[ds][1] = v.y; qh[ds][2] = v.z; qh[ds][3] = v.w;
        }
    }
    __syncthreads();

    int nlive = 0;
    while (nlive < 16 && Msk[nlive * 64] >= -1e5f) nlive++;

    auto stage_k = [&](int stg, int kc0) {
        const uint32_t kb = sb + (uint32_t)((stg ? K1_OFF : K0_OFF) * 4);
        const char* src = (const char*)g_k2 + (((size_t)bh * 128 + (kc0 >> 3)) * 2048);
        #pragma unroll
        for (int j = 0; j < 8; j++) {
            const int off = (tid + j * 128) * 16;
            CP_ASYNC16(kb + (uint32_t)off, src + off);
        }
    };
    auto stage_v = [&](int kc0) {
        const uint32_t vb = sb + (uint32_t)(V_OFF * 4);
        const char* src = (const char*)g_v + (((size_t)bh * 128 + (kc0 >> 3)) * 2048);
        #pragma unroll
        for (int j = 0; j < 8; j++) {
            const int off = (tid + j * 128) * 16;
            CP_ASYNC16(vb + (uint32_t)off, src + off);
        }
    };

    float m0 = -1e30f, m1 = -1e30f, l0 = 0.0f, l1 = 0.0f;
    float ctx[8][4];
    #pragma unroll
    for (int nt = 0; nt < 8; nt++)
        #pragma unroll
        for (int r = 0; r < 4; r++) ctx[nt][r] = 0.0f;

    stage_k(0, 0);
    CP_COMMIT();                          // pending: [K0]

    for (int kt = 0; kt < nlive; kt++) {
        const int kc0 = kt * 64;

        stage_v(kc0);
        CP_COMMIT();                      // +[V(kt)]
        if (kt + 1 < nlive)
            stage_k((kt + 1) & 1, kc0 + 64);
        CP_COMMIT();                      // +[K(kt+1)] (possibly empty)

        CP_WAIT2();                       // K(kt) complete
        __syncthreads();

        const uint32_t* Ksb = sm + ((kt & 1) ? K1_OFF : K0_OFF);

        // ---- S = Q K^T (1-term) ----
        float sa[8][4];
        #pragma unroll
        for (int nt = 0; nt < 8; nt++)
            #pragma unroll
            for (int r = 0; r < 4; r++) sa[nt][r] = 0.0f;

        #pragma unroll
        for (int ds = 0; ds < 8; ds++) {
            #pragma unroll
            for (int nt = 0; nt < 8; nt++) {
                const uint2 kv = *(const uint2*)(Ksb + (nt * 8 + ds) * 64 + lane * 2);
                mma_tf32_16x8x8(sa[nt][0], sa[nt][1], sa[nt][2], sa[nt][3],
                                qh[ds][0], qh[ds][1], qh[ds][2], qh[ds][3], kv.x, kv.y);
            }
        }

        // ---- scale + mask + online softmax ----
        float mx0 = -1e30f, mx1 = -1e30f;
        #pragma unroll
        for (int nt = 0; nt < 8; nt++) {
            const float mk0 = Msk[kc0 + nt * 8 + 2 * lc    ];
            const float mk1 = Msk[kc0 + nt * 8 + 2 * lc + 1];
            sa[nt][0] = fmaf(sa[nt][0], 0.125f, mk0);
            sa[nt][1] = fmaf(sa[nt][1], 0.125f, mk1);
            sa[nt][2] = fmaf(sa[nt][2], 0.125f, mk0);
            sa[nt][3] = fmaf(sa[nt][3], 0.125f, mk1);
            mx0 = fmaxf(mx0, fmaxf(sa[nt][0], sa[nt][1]));
            mx1 = fmaxf(mx1, fmaxf(sa[nt][2], sa[nt][3]));
        }
        mx0 = fmaxf(mx0, __shfl_xor_sync(0xffffffffu, mx0, 1));
        mx0 = fmaxf(mx0, __shfl_xor_sync(0xffffffffu, mx0, 2));
        mx1 = fmaxf(mx1, __shfl_xor_sync(0xffffffffu, mx1, 1));
        mx1 = fmaxf(mx1, __shfl_xor_sync(0xffffffffu, mx1, 2));

        const float mn0 = fmaxf(m0, mx0);
        const float mn1 = fmaxf(m1, mx1);
        const float cr0 = __expf(m0 - mn0);
        const float cr1 = __expf(m1 - mn1);
        l0 *= cr0; l1 *= cr1;
        m0 = mn0; m1 = mn1;

        float ps0 = 0.0f, ps1 = 0.0f;
        #pragma unroll
        for (int nt = 0; nt < 8; nt++) {
            ctx[nt][0] *= cr0; ctx[nt][1] *= cr0;
            ctx[nt][2] *= cr1; ctx[nt][3] *= cr1;
            sa[nt][0] = __expf(sa[nt][0] - mn0);
            sa[nt][1] = __expf(sa[nt][1] - mn0);
            sa[nt][2] = __expf(sa[nt][2] - mn1);
            sa[nt][3] = __expf(sa[nt][3] - mn1);
            ps0 += sa[nt][0] + sa[nt][1];
            ps1 += sa[nt][2] + sa[nt][3];
        }
        ps0 += __shfl_xor_sync(0xffffffffu, ps0, 1);
        ps0 += __shfl_xor_sync(0xffffffffu, ps0, 2);
        ps1 += __shfl_xor_sync(0xffffffffu, ps1, 1);
        ps1 += __shfl_xor_sync(0xffffffffu, ps1, 2);
        l0 += ps0; l1 += ps1;

        // store P as tf32 bits (warp-private rows)
        #pragma unroll
        for (int nt = 0; nt < 8; nt++) {
            uint2 u0, u1;
            u0.x = f32_to_tf32(sa[nt][0]); u0.y = f32_to_tf32(sa[nt][1]);
            u1.x = f32_to_tf32(sa[nt][2]); u1.y = f32_to_tf32(sa[nt][3]);
            *(uint2*)&Psb[(16 * w + lr    ) * KSTR + nt * 8 + 2 * lc] = u0;
            *(uint2*)&Psb[(16 * w + lr + 8) * KSTR + nt * 8 + 2 * lc] = u1;
        }
        __syncwarp();

        CP_WAIT1();                       // V(kt) complete
        __syncthreads();

        const uint32_t* Vsb = sm + V_OFF;

        // ---- ctx += P V (1-term, V fragment-major LDS.64) ----
        #pragma unroll
        for (int kk = 0; kk < 8; kk++) {
            uint32_t ah[4];
            ah[0] = Psb[(16 * w + lr    ) * KSTR + kk * 8 + lc    ];
            ah[1] = Psb[(16 * w + lr + 8) * KSTR + kk * 8 + lc    ];
            ah[2] = Psb[(16 * w + lr    ) * KSTR + kk * 8 + lc + 4];
            ah[3] = Psb[(16 * w + lr + 8) * KSTR + kk * 8 + lc + 4];
            #pragma unroll
            for (int nt = 0; nt < 8; nt++) {
                const uint2 vv = *(const uint2*)(Vsb + (kk * 8 + nt) * 64 + lane * 2);
                mma_tf32_16x8x8(ctx[nt][0], ctx[nt][1], ctx[nt][2], ctx[nt][3],
                                ah[0], ah[1], ah[2], ah[3], vv.x, vv.y);
            }
        }

        __syncthreads();                  // all warps done with V before refill
    }

    const float inv0 = 1.0f / l0;
    const float inv1 = 1.0f / l1;
    const int row0 = q0 + 16 * w + lr;
    const int row1 = row0 + 8;
    #pragma unroll
    for (int nt = 0; nt < 8; nt++) {
        const int d = nt * 8 + 2 * lc;
        *(float2*)&out[(size_t)(b * SEQ + row0) * (NH * DH) + h * 64 + d] =
            make_float2(ctx[nt][0] * inv0, ctx[nt][1] * inv0);
        *(float2*)&out[(size_t)(b * SEQ + row1) * (NH * DH) + h * 64 + d] =
            make_float2(ctx[nt][2] * inv1, ctx[nt][3] * inv1);
    }
}

// ---------------------------------------------------------------------------
extern "C" void kernel_launch(void* const* d_in, const int* in_sizes, int n_in,
                              void* d_out, int out_size)
{
    const float* X     = (const float*)d_in[0];
    const float* mask  = (const float*)d_in[1];
    const float* freqs = (const float*)d_in[2];
    const float* Wq    = (const float*)d_in[3];
    const float* bq    = (const float*)d_in[4];
    const float* Wk    = (const float*)d_in[5];
    const float* bk    = (const float*)d_in[6];
    const float* Wv    = (const float*)d_in[7];
    const float* bv    = (const float*)d_in[8];
    float* out = (float*)d_out;

    cudaFuncSetAttribute(qkv_mma,  cudaFuncAttributeMaxDynamicSharedMemorySize, QKV_SMEM);
    cudaFuncSetAttribute(attn_mma, cudaFuncAttributeMaxDynamicSharedMemorySize, ATTN_SMEM);

    const int total = NA_LANES + 3 * NB_LANES;
    precvt<<<total / 256, 256>>>(X, Wq, Wk, Wv);

    dim3 gG(HID / 128, (BATCH * SEQ) / 128, 3);
    qkv_mma<<<gG, 256, QKV_SMEM>>>(bq, bk, bv);

    dim3 gR((BATCH * NH * SEQ * 32) / 256, 2);
    rope_kernel<<<gR, 256>>>(freqs);

    dim3 gA(SEQ / 64, NH, BATCH);
    attn_mma<<<gA, 128, ATTN_SMEM>>>(mask, out);
}